// round 1
// baseline (speedup 1.0000x reference)
#include <cuda_runtime.h>
#include <cstdint>

// ---------------- scratch (device globals; no allocation APIs) ----------------
__device__ float g_z   [32u*1024u*512u];   // spikes, 64MB
__device__ float g_h   [32768u*256u];      // hidden, 32MB
__device__ float g_qkv [32768u*768u];      // qkv, 96MB
__device__ float g_attn[32768u*256u];      // attn out, 32MB
__device__ float g_tmp [32768u*256u];      // proj/ff2 out, 32MB
__device__ float g_ff  [32768u*1024u];     // ff hidden, 128MB
__device__ float g_colsum[512];

// ---------------- column sums of Wres (for complement-sparsity) ----------------
__global__ void colsum_kernel(const float* __restrict__ Wres) {
    int r = threadIdx.x;
    float s0 = 0.f, s1 = 0.f, s2 = 0.f, s3 = 0.f;
    #pragma unroll 4
    for (int rr = 0; rr < 512; rr += 4) {
        s0 += Wres[(rr + 0) * 512 + r];
        s1 += Wres[(rr + 1) * 512 + r];
        s2 += Wres[(rr + 2) * 512 + r];
        s3 += Wres[(rr + 3) * 512 + r];
    }
    g_colsum[r] = (s0 + s1) + (s2 + s3);
}

// ---------------- LIF reservoir: one CTA per batch, 512 thr = 1/neuron ----------
__global__ void __launch_bounds__(512) lif_kernel(
    const float* __restrict__ x,     // [32][1024][8]
    const float* __restrict__ Win,   // [8][512]
    const float* __restrict__ Wres,  // [512][512]
    float* __restrict__ zout)        // [32][1024][512]
{
    const int b = blockIdx.x;
    const int r = threadIdx.x;
    const int warp = r >> 5, lane = r & 31;

    __shared__ float sWin[8][512];
    __shared__ float sx[8];
    __shared__ int   s_act[512];
    __shared__ int   s_in[512];
    __shared__ int   s_wcnt[16];

    #pragma unroll
    for (int i = 0; i < 8; i++) sWin[i][r] = Win[i * 512 + r];

    const float colsum = g_colsum[r];
    const float* xb = x + (size_t)b * 1024 * 8;
    float* zb = zout + (size_t)b * 1024 * 512;

    float v = 0.f, isyn = 0.f;
    int zprev = 0;

    for (int t = 0; t < 1024; t++) {
        unsigned bal = __ballot_sync(0xffffffffu, zprev);
        __syncthreads();                       // A: prior iter's shared reads done
        if (lane == 0) s_wcnt[warp] = __popc(bal);
        if (r < 8) sx[r] = xb[t * 8 + r];
        __syncthreads();                       // B: counts visible

        int na = 0, base_a = 0;
        #pragma unroll
        for (int w = 0; w < 16; w++) {
            int c = s_wcnt[w];
            na += c;
            if (w < warp) base_a += c;
        }
        int rank = __popc(bal & ((1u << lane) - 1u));
        if (zprev) {
            s_act[base_a + rank] = r;
        } else {
            int base_i = warp * 32 - base_a;
            s_in[base_i + (lane - rank)] = r;
        }
        __syncthreads();                       // C: lists ready

        // input current
        float cur = 0.f;
        #pragma unroll
        for (int i = 0; i < 8; i++) cur += sx[i] * sWin[i][r];

        // recurrent current: direct (sparse) or complement (dense)
        float rec;
        if (na <= 256) {
            rec = 0.f;
            for (int j = 0; j < na; j++)
                rec += Wres[s_act[j] * 512 + r];
        } else {
            const int ni = 512 - na;
            float a0 = 0.f, a1 = 0.f, a2 = 0.f, a3 = 0.f;
            int j = 0;
            for (; j + 4 <= ni; j += 4) {
                a0 += Wres[s_in[j + 0] * 512 + r];
                a1 += Wres[s_in[j + 1] * 512 + r];
                a2 += Wres[s_in[j + 2] * 512 + r];
                a3 += Wres[s_in[j + 3] * 512 + r];
            }
            for (; j < ni; j++) a0 += Wres[s_in[j] * 512 + r];
            rec = colsum - ((a0 + a1) + (a2 + a3));
        }

        float total = cur + rec;
        float vdec = v + 0.004f * (isyn - v);   // v + dt/tau_mem*(-v+i)
        float idec = isyn * 0.8f;               // i*(1 - dt*tau_syn_inv)
        float z = (vdec - 0.1f) > 0.f ? 1.f : 0.f;
        v = (1.f - z) * vdec;
        isyn = idec + total;
        zb[(size_t)t * 512 + r] = z;
        zprev = (z > 0.f);
    }
}

// ---------------- SGEMM: C[m][n] = sum_k A[m][k]*B[n][k] + bias[n]  (NT) -------
__global__ void __launch_bounds__(256) sgemm_nt(
    const float* __restrict__ A, const float* __restrict__ B,
    const float* __restrict__ bias, float* __restrict__ C,
    int M, int N, int K, int relu)
{
    __shared__ float As[8][128];
    __shared__ float Bs[8][128];

    const int tid  = threadIdx.x;
    const int bm   = blockIdx.y << 7;
    const int bn   = blockIdx.x << 7;
    const int lrow = tid >> 1;
    const int lcol = (tid & 1) << 2;
    const int tx   = tid & 15;
    const int ty   = tid >> 4;

    const float* Ag = A + (size_t)(bm + lrow) * K + lcol;
    const float* Bg = B + (size_t)(bn + lrow) * K + lcol;

    float acc[8][8];
    #pragma unroll
    for (int i = 0; i < 8; i++)
        #pragma unroll
        for (int j = 0; j < 8; j++) acc[i][j] = 0.f;

    for (int k0 = 0; k0 < K; k0 += 8) {
        float4 av = *(const float4*)(Ag + k0);
        float4 bv = *(const float4*)(Bg + k0);
        __syncthreads();
        As[lcol + 0][lrow] = av.x; As[lcol + 1][lrow] = av.y;
        As[lcol + 2][lrow] = av.z; As[lcol + 3][lrow] = av.w;
        Bs[lcol + 0][lrow] = bv.x; Bs[lcol + 1][lrow] = bv.y;
        Bs[lcol + 2][lrow] = bv.z; Bs[lcol + 3][lrow] = bv.w;
        __syncthreads();
        #pragma unroll
        for (int kk = 0; kk < 8; kk++) {
            float a[8], b[8];
            *(float4*)&a[0] = *(const float4*)&As[kk][(ty << 3) + 0];
            *(float4*)&a[4] = *(const float4*)&As[kk][(ty << 3) + 4];
            *(float4*)&b[0] = *(const float4*)&Bs[kk][(tx << 3) + 0];
            *(float4*)&b[4] = *(const float4*)&Bs[kk][(tx << 3) + 4];
            #pragma unroll
            for (int i = 0; i < 8; i++)
                #pragma unroll
                for (int j = 0; j < 8; j++) acc[i][j] += a[i] * b[j];
        }
    }

    float bv[8];
    #pragma unroll
    for (int j = 0; j < 8; j++) bv[j] = bias[bn + (tx << 3) + j];

    #pragma unroll
    for (int i = 0; i < 8; i++) {
        size_t row = (size_t)bm + (ty << 3) + i;
        float* Cp = C + row * N + bn + (tx << 3);
        float o[8];
        #pragma unroll
        for (int j = 0; j < 8; j++) {
            float t = acc[i][j] + bv[j];
            o[j] = relu ? fmaxf(t, 0.f) : t;
        }
        *(float4*)&Cp[0] = make_float4(o[0], o[1], o[2], o[3]);
        *(float4*)&Cp[4] = make_float4(o[4], o[5], o[6], o[7]);
    }
}

// ---------------- flash attention: fp32, 1 thread per query row ----------------
__global__ void __launch_bounds__(128) flash_kernel(
    const float* __restrict__ qkv, float* __restrict__ out)
{
    __shared__ float smem[128 * 68];   // Q staging, then reused as K|V tiles

    const int tid = threadIdx.x;
    const int qb  = blockIdx.x;        // 0..7 (128 rows each)
    const int bh  = blockIdx.y;        // 0..127
    const int b   = bh >> 2, h = bh & 3;
    const float* base = qkv + (size_t)b * 1024 * 768;

    // stage Q tile [128][64] (pitch 68), coalesced
    {
        const float* qg = base + h * 64;
        #pragma unroll
        for (int i = 0; i < 16; i++) {
            int idx = i * 128 + tid;
            int row = idx >> 4, c4 = (idx & 15) << 2;
            *(float4*)&smem[row * 68 + c4] =
                *(const float4*)&qg[(size_t)(qb * 128 + row) * 768 + c4];
        }
    }
    __syncthreads();
    float q[64];
    #pragma unroll
    for (int d4 = 0; d4 < 64; d4 += 4)
        *(float4*)&q[d4] = *(const float4*)&smem[tid * 68 + d4];
    __syncthreads();

    float* ks = smem;
    float* vs = smem + 64 * 64;

    float o[64];
    #pragma unroll
    for (int d = 0; d < 64; d++) o[d] = 0.f;
    float m = -1e30f, l = 0.f;

    #pragma unroll 1
    for (int kb = 0; kb < 16; kb++) {
        __syncthreads();
        const float* kg = base + 256 + h * 64;
        const float* vg = base + 512 + h * 64;
        #pragma unroll
        for (int i = 0; i < 8; i++) {
            int idx = i * 128 + tid;
            int row = idx >> 4, c4 = (idx & 15) << 2;
            *(float4*)&ks[row * 64 + c4] =
                *(const float4*)&kg[(size_t)(kb * 64 + row) * 768 + c4];
            *(float4*)&vs[row * 64 + c4] =
                *(const float4*)&vg[(size_t)(kb * 64 + row) * 768 + c4];
        }
        __syncthreads();

        float p[64];
        float mb = -1e30f;
        #pragma unroll
        for (int j = 0; j < 64; j++) {
            float s = 0.f;
            #pragma unroll
            for (int d = 0; d < 64; d++) s += q[d] * ks[j * 64 + d];
            s *= 0.125f;
            p[j] = s;
            mb = fmaxf(mb, s);
        }
        float mn = fmaxf(m, mb);
        float corr = __expf(m - mn);
        l *= corr;
        #pragma unroll
        for (int d = 0; d < 64; d++) o[d] *= corr;
        #pragma unroll
        for (int j = 0; j < 64; j++) {
            float e = __expf(p[j] - mn);
            l += e;
            #pragma unroll
            for (int d = 0; d < 64; d++) o[d] += e * vs[j * 64 + d];
        }
        m = mn;
    }

    float inv = 1.f / l;
    float* op = out + ((size_t)(b * 1024 + qb * 128 + tid)) * 256 + h * 64;
    #pragma unroll
    for (int d4 = 0; d4 < 64; d4 += 4) {
        float4 w;
        w.x = o[d4 + 0] * inv; w.y = o[d4 + 1] * inv;
        w.z = o[d4 + 2] * inv; w.w = o[d4 + 3] * inv;
        *(float4*)&op[d4] = w;
    }
}

// ---------------- layernorm(xa + xb) * g + b  (one warp per 256-row) -----------
__global__ void __launch_bounds__(256) ln_kernel(
    const float* __restrict__ xa, const float* __restrict__ xb,
    const float* __restrict__ g, const float* __restrict__ bt,
    float* __restrict__ out)
{
    const int warp = threadIdx.x >> 5, lane = threadIdx.x & 31;
    const size_t row = (size_t)blockIdx.x * 8 + warp;
    const float* pa = xa + row * 256;
    const float* pb = xb + row * 256;

    float v[8];
    float s = 0.f;
    #pragma unroll
    for (int i = 0; i < 8; i++) {
        v[i] = pa[lane + 32 * i] + pb[lane + 32 * i];
        s += v[i];
    }
    #pragma unroll
    for (int off = 16; off > 0; off >>= 1) s += __shfl_xor_sync(0xffffffffu, s, off);
    float mean = s * (1.f / 256.f);

    float vs = 0.f;
    #pragma unroll
    for (int i = 0; i < 8; i++) {
        float d = v[i] - mean;
        vs += d * d;
    }
    #pragma unroll
    for (int off = 16; off > 0; off >>= 1) vs += __shfl_xor_sync(0xffffffffu, vs, off);
    float var = vs * (1.f / 256.f);
    float inv = 1.f / sqrtf(var + 1e-5f);

    #pragma unroll
    for (int i = 0; i < 8; i++) {
        int c = lane + 32 * i;
        out[row * 256 + c] = (v[i] - mean) * inv * g[c] + bt[c];
    }
}

// -------------------------------- launch ---------------------------------------
extern "C" void kernel_launch(void* const* d_in, const int* in_sizes, int n_in,
                              void* d_out, int out_size)
{
    const float* x     = (const float*)d_in[0];
    const float* Win   = (const float*)d_in[1];
    const float* Wres  = (const float*)d_in[2];
    const float* Wread = (const float*)d_in[3];
    const float* bread = (const float*)d_in[4];
    const float* Wqkv  = (const float*)d_in[5];
    const float* bqkv  = (const float*)d_in[6];
    const float* Wo    = (const float*)d_in[7];
    const float* bo    = (const float*)d_in[8];
    const float* g1    = (const float*)d_in[9];
    const float* b1    = (const float*)d_in[10];
    const float* g2    = (const float*)d_in[11];
    const float* b2    = (const float*)d_in[12];
    const float* W1    = (const float*)d_in[13];
    const float* c1    = (const float*)d_in[14];
    const float* W2    = (const float*)d_in[15];
    const float* c2    = (const float*)d_in[16];
    float* out = (float*)d_out;

    float *z, *h, *qkv, *attn, *tmp, *ff;
    cudaGetSymbolAddress((void**)&z,    g_z);
    cudaGetSymbolAddress((void**)&h,    g_h);
    cudaGetSymbolAddress((void**)&qkv,  g_qkv);
    cudaGetSymbolAddress((void**)&attn, g_attn);
    cudaGetSymbolAddress((void**)&tmp,  g_tmp);
    cudaGetSymbolAddress((void**)&ff,   g_ff);

    const int M = 32768;

    colsum_kernel<<<1, 512>>>(Wres);
    lif_kernel<<<32, 512>>>(x, Win, Wres, z);

    // h = z @ Wread^T + bread
    sgemm_nt<<<dim3(2, 256), 256>>>(z, Wread, bread, h, M, 256, 512, 0);

    for (int l = 0; l < 2; l++) {
        // qkv = h @ Wqkv^T + bqkv
        sgemm_nt<<<dim3(6, 256), 256>>>(h, Wqkv + (size_t)l * 768 * 256,
                                        bqkv + l * 768, qkv, M, 768, 256, 0);
        // attention
        flash_kernel<<<dim3(8, 128), 128>>>(qkv, attn);
        // tmp = attn @ Wo^T + bo
        sgemm_nt<<<dim3(2, 256), 256>>>(attn, Wo + (size_t)l * 256 * 256,
                                        bo + l * 256, tmp, M, 256, 256, 0);
        // h = LN(h + tmp)
        ln_kernel<<<4096, 256>>>(h, tmp, g1 + l * 256, b1 + l * 256, h);
        // ff = relu(h @ W1^T + c1)
        sgemm_nt<<<dim3(8, 256), 256>>>(h, W1 + (size_t)l * 1024 * 256,
                                        c1 + l * 1024, ff, M, 1024, 256, 1);
        // tmp = ff @ W2^T + c2
        sgemm_nt<<<dim3(2, 256), 256>>>(ff, W2 + (size_t)l * 256 * 1024,
                                        c2 + l * 256, tmp, M, 256, 1024, 0);
        // out/h = LN(h + tmp)
        ln_kernel<<<4096, 256>>>(h, tmp, g2 + l * 256, b2 + l * 256,
                                 (l == 1) ? out : h);
    }
}

// round 2
// speedup vs baseline: 1.1380x; 1.1380x over previous
#include <cuda_runtime.h>
#include <cstdint>

// ---------------- scratch (device globals; no allocation APIs) ----------------
__device__ float g_z   [32u*1024u*512u];   // spikes, 64MB
__device__ float g_h   [32768u*256u];      // hidden, 32MB
__device__ float g_qkv [32768u*768u];      // qkv, 96MB
__device__ float g_attn[32768u*256u];      // attn out, 32MB
__device__ float g_tmp [32768u*256u];      // proj/ff2 out, 32MB
__device__ float g_ff  [32768u*1024u];     // ff hidden, 128MB
__device__ float g_colsum[512];

// ---------------- column sums of Wres (for complement-sparsity) ----------------
__global__ void colsum_kernel(const float* __restrict__ Wres) {
    int r = threadIdx.x;
    float s0 = 0.f, s1 = 0.f, s2 = 0.f, s3 = 0.f;
    #pragma unroll 4
    for (int rr = 0; rr < 512; rr += 4) {
        s0 += Wres[(rr + 0) * 512 + r];
        s1 += Wres[(rr + 1) * 512 + r];
        s2 += Wres[(rr + 2) * 512 + r];
        s3 += Wres[(rr + 3) * 512 + r];
    }
    g_colsum[r] = (s0 + s1) + (s2 + s3);
}

// ---------------- LIF reservoir: one CTA per batch, 512 thr = 1/neuron ----------
__global__ void __launch_bounds__(512) lif_kernel(
    const float* __restrict__ x,     // [32][1024][8]
    const float* __restrict__ Win,   // [8][512]
    const float* __restrict__ Wres,  // [512][512]
    float* __restrict__ zout)        // [32][1024][512]
{
    const int b = blockIdx.x;
    const int r = threadIdx.x;
    const int warp = r >> 5, lane = r & 31;

    __shared__ float sWin[8][512];
    __shared__ float sx[8];
    __shared__ int   s_act[512];
    __shared__ int   s_in[512];
    __shared__ int   s_wcnt[16];

    #pragma unroll
    for (int i = 0; i < 8; i++) sWin[i][r] = Win[i * 512 + r];

    const float colsum = g_colsum[r];
    const float* xb = x + (size_t)b * 1024 * 8;
    float* zb = zout + (size_t)b * 1024 * 512;

    float v = 0.f, isyn = 0.f;
    int zprev = 0;

    for (int t = 0; t < 1024; t++) {
        unsigned bal = __ballot_sync(0xffffffffu, zprev);
        __syncthreads();                       // A: prior iter's shared reads done
        if (lane == 0) s_wcnt[warp] = __popc(bal);
        if (r < 8) sx[r] = xb[t * 8 + r];
        __syncthreads();                       // B: counts visible

        int na = 0, base_a = 0;
        #pragma unroll
        for (int w = 0; w < 16; w++) {
            int c = s_wcnt[w];
            na += c;
            if (w < warp) base_a += c;
        }
        int rank = __popc(bal & ((1u << lane) - 1u));
        if (zprev) {
            s_act[base_a + rank] = r;
        } else {
            int base_i = warp * 32 - base_a;
            s_in[base_i + (lane - rank)] = r;
        }
        __syncthreads();                       // C: lists ready

        // input current
        float cur = 0.f;
        #pragma unroll
        for (int i = 0; i < 8; i++) cur += sx[i] * sWin[i][r];

        // recurrent current: direct (sparse) or complement (dense)
        float rec;
        if (na <= 256) {
            rec = 0.f;
            for (int j = 0; j < na; j++)
                rec += Wres[s_act[j] * 512 + r];
        } else {
            const int ni = 512 - na;
            float a0 = 0.f, a1 = 0.f, a2 = 0.f, a3 = 0.f;
            int j = 0;
            for (; j + 4 <= ni; j += 4) {
                a0 += Wres[s_in[j + 0] * 512 + r];
                a1 += Wres[s_in[j + 1] * 512 + r];
                a2 += Wres[s_in[j + 2] * 512 + r];
                a3 += Wres[s_in[j + 3] * 512 + r];
            }
            for (; j < ni; j++) a0 += Wres[s_in[j] * 512 + r];
            rec = colsum - ((a0 + a1) + (a2 + a3));
        }

        float total = cur + rec;
        float vdec = v + 0.004f * (isyn - v);   // v + dt/tau_mem*(-v+i)
        float idec = isyn * 0.8f;               // i*(1 - dt*tau_syn_inv)
        float z = (vdec - 0.1f) > 0.f ? 1.f : 0.f;
        v = (1.f - z) * vdec;
        isyn = idec + total;
        zb[(size_t)t * 512 + r] = z;
        zprev = (z > 0.f);
    }
}

// ---------------- TF32x3 tensor-core GEMM ----------------
// C[m][n] = sum_k A[m][k]*B[n][k] + bias[n], optional relu.
// Exact split: hi = a & 0xffffe000 (tf32-exact), lo = a - hi (exact).
// a*b = hi*hi' + hi*lo' + lo*hi' + O(2^-26) -> near-fp32 accuracy on tensor pipe.
// Block tile 128x128, K-tile 32, 256 threads = 8 warps in 4x2; warp tile 32x64.
// Requires M%128==0, N%128==0, K%32==0 (true for all shapes here).

__device__ __forceinline__ void split_tf32(float x, uint32_t& hi, uint32_t& lo) {
    uint32_t xb = __float_as_uint(x);
    hi = xb & 0xffffe000u;
    lo = __float_as_uint(x - __uint_as_float(hi));
}

__device__ __forceinline__ void mma_tf32(float* c, const uint32_t* a, const uint32_t* b) {
    asm volatile(
        "mma.sync.aligned.m16n8k8.row.col.f32.tf32.tf32.f32 "
        "{%0,%1,%2,%3},{%4,%5,%6,%7},{%8,%9},{%0,%1,%2,%3};\n"
        : "+f"(c[0]), "+f"(c[1]), "+f"(c[2]), "+f"(c[3])
        : "r"(a[0]), "r"(a[1]), "r"(a[2]), "r"(a[3]), "r"(b[0]), "r"(b[1]));
}

__global__ void __launch_bounds__(256) gemm_tf32x3(
    const float* __restrict__ A, const float* __restrict__ B,
    const float* __restrict__ bias, float* __restrict__ C,
    int M, int N, int K, int relu)
{
    __shared__ float sA[128][36];   // pitch 36: lds bank = lane + const (conflict-free)
    __shared__ float sB[128][36];

    const int tid  = threadIdx.x;
    const int lane = tid & 31;
    const int warp = tid >> 5;
    const int bm   = blockIdx.y << 7;
    const int bn   = blockIdx.x << 7;
    const int warpM = (warp >> 1) << 5;   // 0,32,64,96
    const int warpN = (warp & 1) << 6;    // 0,64

    // global staging addressing: each thread loads 4 float4 per tile
    const int srow = tid >> 3;            // 0..31
    const int scol = (tid & 7) << 2;      // 0,4,...,28
    const float* Ag = A + (size_t)(bm + srow) * K + scol;
    const float* Bg = B + (size_t)(bn + srow) * K + scol;

    float acc[2][8][4];
    #pragma unroll
    for (int mi = 0; mi < 2; mi++)
        #pragma unroll
        for (int ni = 0; ni < 8; ni++)
            #pragma unroll
            for (int r = 0; r < 4; r++) acc[mi][ni][r] = 0.f;

    const int ntiles = K >> 5;

    float4 ra[4], rb[4];
    #pragma unroll
    for (int p = 0; p < 4; p++) {
        ra[p] = *(const float4*)(Ag + (size_t)(p * 32) * K);
        rb[p] = *(const float4*)(Bg + (size_t)(p * 32) * K);
    }
    #pragma unroll
    for (int p = 0; p < 4; p++) {
        *(float4*)&sA[p * 32 + srow][scol] = ra[p];
        *(float4*)&sB[p * 32 + srow][scol] = rb[p];
    }
    __syncthreads();

    for (int kt = 0; kt < ntiles; kt++) {
        const bool last = (kt == ntiles - 1);
        if (!last) {
            const float* Ap = Ag + (size_t)((kt + 1) << 5);
            const float* Bp = Bg + (size_t)((kt + 1) << 5);
            #pragma unroll
            for (int p = 0; p < 4; p++) {
                ra[p] = *(const float4*)(Ap + (size_t)(p * 32) * K);
                rb[p] = *(const float4*)(Bp + (size_t)(p * 32) * K);
            }
        }

        #pragma unroll
        for (int kk = 0; kk < 4; kk++) {
            const int k = (kk << 3) + (lane & 3);
            const int rq = lane >> 2;

            uint32_t ah[2][4], al[2][4];
            #pragma unroll
            for (int mi = 0; mi < 2; mi++) {
                const int r0 = warpM + (mi << 4) + rq;
                split_tf32(sA[r0][k],     ah[mi][0], al[mi][0]);
                split_tf32(sA[r0 + 8][k], ah[mi][1], al[mi][1]);
                split_tf32(sA[r0][k + 4],     ah[mi][2], al[mi][2]);
                split_tf32(sA[r0 + 8][k + 4], ah[mi][3], al[mi][3]);
            }
            uint32_t bh[8][2], bl[8][2];
            #pragma unroll
            for (int ni = 0; ni < 8; ni++) {
                const int c0 = warpN + (ni << 3) + rq;
                split_tf32(sB[c0][k],     bh[ni][0], bl[ni][0]);
                split_tf32(sB[c0][k + 4], bh[ni][1], bl[ni][1]);
            }
            #pragma unroll
            for (int mi = 0; mi < 2; mi++)
                #pragma unroll
                for (int ni = 0; ni < 8; ni++) {
                    mma_tf32(acc[mi][ni], ah[mi], bh[ni]);
                    mma_tf32(acc[mi][ni], ah[mi], bl[ni]);
                    mma_tf32(acc[mi][ni], al[mi], bh[ni]);
                }
        }

        if (last) break;
        __syncthreads();
        #pragma unroll
        for (int p = 0; p < 4; p++) {
            *(float4*)&sA[p * 32 + srow][scol] = ra[p];
            *(float4*)&sB[p * 32 + srow][scol] = rb[p];
        }
        __syncthreads();
    }

    // epilogue
    const int rq = lane >> 2;
    const int cq = (lane & 3) << 1;
    #pragma unroll
    for (int ni = 0; ni < 8; ni++) {
        const int col = bn + warpN + (ni << 3) + cq;
        const float b0 = bias[col], b1 = bias[col + 1];
        #pragma unroll
        for (int mi = 0; mi < 2; mi++) {
            const int row0 = bm + warpM + (mi << 4) + rq;
            float2 v0, v1;
            v0.x = acc[mi][ni][0] + b0; v0.y = acc[mi][ni][1] + b1;
            v1.x = acc[mi][ni][2] + b0; v1.y = acc[mi][ni][3] + b1;
            if (relu) {
                v0.x = fmaxf(v0.x, 0.f); v0.y = fmaxf(v0.y, 0.f);
                v1.x = fmaxf(v1.x, 0.f); v1.y = fmaxf(v1.y, 0.f);
            }
            *(float2*)&C[(size_t)row0 * N + col] = v0;
            *(float2*)&C[(size_t)(row0 + 8) * N + col] = v1;
        }
    }
}

// ---------------- flash attention: fp32, 1 thread per query row ----------------
__global__ void __launch_bounds__(128) flash_kernel(
    const float* __restrict__ qkv, float* __restrict__ out)
{
    __shared__ float smem[128 * 68];   // Q staging, then reused as K|V tiles

    const int tid = threadIdx.x;
    const int qb  = blockIdx.x;        // 0..7 (128 rows each)
    const int bh  = blockIdx.y;        // 0..127
    const int b   = bh >> 2, h = bh & 3;
    const float* base = qkv + (size_t)b * 1024 * 768;

    // stage Q tile [128][64] (pitch 68), coalesced
    {
        const float* qg = base + h * 64;
        #pragma unroll
        for (int i = 0; i < 16; i++) {
            int idx = i * 128 + tid;
            int row = idx >> 4, c4 = (idx & 15) << 2;
            *(float4*)&smem[row * 68 + c4] =
                *(const float4*)&qg[(size_t)(qb * 128 + row) * 768 + c4];
        }
    }
    __syncthreads();
    float q[64];
    #pragma unroll
    for (int d4 = 0; d4 < 64; d4 += 4)
        *(float4*)&q[d4] = *(const float4*)&smem[tid * 68 + d4];
    __syncthreads();

    float* ks = smem;
    float* vs = smem + 64 * 64;

    float o[64];
    #pragma unroll
    for (int d = 0; d < 64; d++) o[d] = 0.f;
    float m = -1e30f, l = 0.f;

    #pragma unroll 1
    for (int kb = 0; kb < 16; kb++) {
        __syncthreads();
        const float* kg = base + 256 + h * 64;
        const float* vg = base + 512 + h * 64;
        #pragma unroll
        for (int i = 0; i < 8; i++) {
            int idx = i * 128 + tid;
            int row = idx >> 4, c4 = (idx & 15) << 2;
            *(float4*)&ks[row * 64 + c4] =
                *(const float4*)&kg[(size_t)(kb * 64 + row) * 768 + c4];
            *(float4*)&vs[row * 64 + c4] =
                *(const float4*)&vg[(size_t)(kb * 64 + row) * 768 + c4];
        }
        __syncthreads();

        float p[64];
        float mb = -1e30f;
        #pragma unroll
        for (int j = 0; j < 64; j++) {
            float s = 0.f;
            #pragma unroll
            for (int d = 0; d < 64; d++) s += q[d] * ks[j * 64 + d];
            s *= 0.125f;
            p[j] = s;
            mb = fmaxf(mb, s);
        }
        float mn = fmaxf(m, mb);
        float corr = __expf(m - mn);
        l *= corr;
        #pragma unroll
        for (int d = 0; d < 64; d++) o[d] *= corr;
        #pragma unroll
        for (int j = 0; j < 64; j++) {
            float e = __expf(p[j] - mn);
            l += e;
            #pragma unroll
            for (int d = 0; d < 64; d++) o[d] += e * vs[j * 64 + d];
        }
        m = mn;
    }

    float inv = 1.f / l;
    float* op = out + ((size_t)(b * 1024 + qb * 128 + tid)) * 256 + h * 64;
    #pragma unroll
    for (int d4 = 0; d4 < 64; d4 += 4) {
        float4 w;
        w.x = o[d4 + 0] * inv; w.y = o[d4 + 1] * inv;
        w.z = o[d4 + 2] * inv; w.w = o[d4 + 3] * inv;
        *(float4*)&op[d4] = w;
    }
}

// ---------------- layernorm(xa + xb) * g + b  (one warp per 256-row) -----------
__global__ void __launch_bounds__(256) ln_kernel(
    const float* __restrict__ xa, const float* __restrict__ xb,
    const float* __restrict__ g, const float* __restrict__ bt,
    float* __restrict__ out)
{
    const int warp = threadIdx.x >> 5, lane = threadIdx.x & 31;
    const size_t row = (size_t)blockIdx.x * 8 + warp;
    const float* pa = xa + row * 256;
    const float* pb = xb + row * 256;

    float v[8];
    float s = 0.f;
    #pragma unroll
    for (int i = 0; i < 8; i++) {
        v[i] = pa[lane + 32 * i] + pb[lane + 32 * i];
        s += v[i];
    }
    #pragma unroll
    for (int off = 16; off > 0; off >>= 1) s += __shfl_xor_sync(0xffffffffu, s, off);
    float mean = s * (1.f / 256.f);

    float vs = 0.f;
    #pragma unroll
    for (int i = 0; i < 8; i++) {
        float d = v[i] - mean;
        vs += d * d;
    }
    #pragma unroll
    for (int off = 16; off > 0; off >>= 1) vs += __shfl_xor_sync(0xffffffffu, vs, off);
    float var = vs * (1.f / 256.f);
    float inv = 1.f / sqrtf(var + 1e-5f);

    #pragma unroll
    for (int i = 0; i < 8; i++) {
        int c = lane + 32 * i;
        out[row * 256 + c] = (v[i] - mean) * inv * g[c] + bt[c];
    }
}

// -------------------------------- launch ---------------------------------------
extern "C" void kernel_launch(void* const* d_in, const int* in_sizes, int n_in,
                              void* d_out, int out_size)
{
    const float* x     = (const float*)d_in[0];
    const float* Win   = (const float*)d_in[1];
    const float* Wres  = (const float*)d_in[2];
    const float* Wread = (const float*)d_in[3];
    const float* bread = (const float*)d_in[4];
    const float* Wqkv  = (const float*)d_in[5];
    const float* bqkv  = (const float*)d_in[6];
    const float* Wo    = (const float*)d_in[7];
    const float* bo    = (const float*)d_in[8];
    const float* g1    = (const float*)d_in[9];
    const float* b1    = (const float*)d_in[10];
    const float* g2    = (const float*)d_in[11];
    const float* b2    = (const float*)d_in[12];
    const float* W1    = (const float*)d_in[13];
    const float* c1    = (const float*)d_in[14];
    const float* W2    = (const float*)d_in[15];
    const float* c2    = (const float*)d_in[16];
    float* out = (float*)d_out;

    float *z, *h, *qkv, *attn, *tmp, *ff;
    cudaGetSymbolAddress((void**)&z,    g_z);
    cudaGetSymbolAddress((void**)&h,    g_h);
    cudaGetSymbolAddress((void**)&qkv,  g_qkv);
    cudaGetSymbolAddress((void**)&attn, g_attn);
    cudaGetSymbolAddress((void**)&tmp,  g_tmp);
    cudaGetSymbolAddress((void**)&ff,   g_ff);

    const int M = 32768;

    colsum_kernel<<<1, 512>>>(Wres);
    lif_kernel<<<32, 512>>>(x, Win, Wres, z);

    // h = z @ Wread^T + bread
    gemm_tf32x3<<<dim3(2, 256), 256>>>(z, Wread, bread, h, M, 256, 512, 0);

    for (int l = 0; l < 2; l++) {
        // qkv = h @ Wqkv^T + bqkv
        gemm_tf32x3<<<dim3(6, 256), 256>>>(h, Wqkv + (size_t)l * 768 * 256,
                                           bqkv + l * 768, qkv, M, 768, 256, 0);
        // attention
        flash_kernel<<<dim3(8, 128), 128>>>(qkv, attn);
        // tmp = attn @ Wo^T + bo
        gemm_tf32x3<<<dim3(2, 256), 256>>>(attn, Wo + (size_t)l * 256 * 256,
                                           bo + l * 256, tmp, M, 256, 256, 0);
        // h = LN(h + tmp)
        ln_kernel<<<4096, 256>>>(h, tmp, g1 + l * 256, b1 + l * 256, h);
        // ff = relu(h @ W1^T + c1)
        gemm_tf32x3<<<dim3(8, 256), 256>>>(h, W1 + (size_t)l * 1024 * 256,
                                           c1 + l * 1024, ff, M, 1024, 256, 1);
        // tmp = ff @ W2^T + c2
        gemm_tf32x3<<<dim3(2, 256), 256>>>(ff, W2 + (size_t)l * 256 * 1024,
                                           c2 + l * 256, tmp, M, 256, 1024, 0);
        // out/h = LN(h + tmp)
        ln_kernel<<<4096, 256>>>(h, tmp, g2 + l * 256, b2 + l * 256,
                                 (l == 1) ? out : h);
    }
}

// round 3
// speedup vs baseline: 2.1116x; 1.8556x over previous
#include <cuda_runtime.h>
#include <cstdint>

// ---------------- scratch (device globals; no allocation APIs) ----------------
__device__ float g_z   [32u*1024u*512u];   // spikes, 64MB
__device__ float g_h   [32768u*256u];      // hidden, 32MB
__device__ float g_qkv [32768u*768u];      // qkv, 96MB
__device__ float g_attn[32768u*256u];      // attn out, 32MB
__device__ float g_tmp [32768u*256u];      // proj/ff2 out, 32MB
__device__ float g_ff  [32768u*1024u];     // ff hidden, 128MB
__device__ float g_colsum[512];

// ---------------- column sums of Wres (for complement-sparsity) ----------------
__global__ void colsum_kernel(const float* __restrict__ Wres) {
    int r = threadIdx.x;
    float s0 = 0.f, s1 = 0.f, s2 = 0.f, s3 = 0.f;
    #pragma unroll 4
    for (int rr = 0; rr < 512; rr += 4) {
        s0 += Wres[(rr + 0) * 512 + r];
        s1 += Wres[(rr + 1) * 512 + r];
        s2 += Wres[(rr + 2) * 512 + r];
        s3 += Wres[(rr + 3) * 512 + r];
    }
    g_colsum[r] = (s0 + s1) + (s2 + s3);
}

// ---------------- LIF reservoir: one CTA per batch, 512 thr = 1/neuron ----------
__global__ void __launch_bounds__(512) lif_kernel(
    const float* __restrict__ x,     // [32][1024][8]
    const float* __restrict__ Win,   // [8][512]
    const float* __restrict__ Wres,  // [512][512]
    float* __restrict__ zout)        // [32][1024][512]
{
    const int b = blockIdx.x;
    const int r = threadIdx.x;
    const int warp = r >> 5, lane = r & 31;

    __shared__ float sWin[8][512];
    __shared__ float sx[8];
    __shared__ int   s_act[512];
    __shared__ int   s_in[512];
    __shared__ int   s_wcnt[16];

    #pragma unroll
    for (int i = 0; i < 8; i++) sWin[i][r] = Win[i * 512 + r];

    const float colsum = g_colsum[r];
    const float* xb = x + (size_t)b * 1024 * 8;
    float* zb = zout + (size_t)b * 1024 * 512;

    float v = 0.f, isyn = 0.f;
    int zprev = 0;

    for (int t = 0; t < 1024; t++) {
        unsigned bal = __ballot_sync(0xffffffffu, zprev);
        __syncthreads();                       // A: prior iter's shared reads done
        if (lane == 0) s_wcnt[warp] = __popc(bal);
        if (r < 8) sx[r] = xb[t * 8 + r];
        __syncthreads();                       // B: counts visible

        int na = 0, base_a = 0;
        #pragma unroll
        for (int w = 0; w < 16; w++) {
            int c = s_wcnt[w];
            na += c;
            if (w < warp) base_a += c;
        }
        int rank = __popc(bal & ((1u << lane) - 1u));
        if (zprev) {
            s_act[base_a + rank] = r;
        } else {
            int base_i = warp * 32 - base_a;
            s_in[base_i + (lane - rank)] = r;
        }
        __syncthreads();                       // C: lists ready

        // input current
        float cur = 0.f;
        #pragma unroll
        for (int i = 0; i < 8; i++) cur += sx[i] * sWin[i][r];

        // recurrent current: direct (sparse) or complement (dense)
        float rec;
        if (na <= 256) {
            rec = 0.f;
            for (int j = 0; j < na; j++)
                rec += Wres[s_act[j] * 512 + r];
        } else {
            const int ni = 512 - na;
            float a0 = 0.f, a1 = 0.f, a2 = 0.f, a3 = 0.f;
            int j = 0;
            for (; j + 4 <= ni; j += 4) {
                a0 += Wres[s_in[j + 0] * 512 + r];
                a1 += Wres[s_in[j + 1] * 512 + r];
                a2 += Wres[s_in[j + 2] * 512 + r];
                a3 += Wres[s_in[j + 3] * 512 + r];
            }
            for (; j < ni; j++) a0 += Wres[s_in[j] * 512 + r];
            rec = colsum - ((a0 + a1) + (a2 + a3));
        }

        float total = cur + rec;
        float vdec = v + 0.004f * (isyn - v);   // v + dt/tau_mem*(-v+i)
        float idec = isyn * 0.8f;               // i*(1 - dt*tau_syn_inv)
        float z = (vdec - 0.1f) > 0.f ? 1.f : 0.f;
        v = (1.f - z) * vdec;
        isyn = idec + total;
        zb[(size_t)t * 512 + r] = z;
        zprev = (z > 0.f);
    }
}

// ---------------- TF32x3 helpers ----------------
__device__ __forceinline__ void split_tf32(float x, uint32_t& hi, uint32_t& lo) {
    uint32_t xb = __float_as_uint(x);
    hi = xb & 0xffffe000u;
    lo = __float_as_uint(x - __uint_as_float(hi));
}

__device__ __forceinline__ void mma_tf32(float* c, const uint32_t* a, const uint32_t* b) {
    asm volatile(
        "mma.sync.aligned.m16n8k8.row.col.f32.tf32.tf32.f32 "
        "{%0,%1,%2,%3},{%4,%5,%6,%7},{%8,%9},{%0,%1,%2,%3};\n"
        : "+f"(c[0]), "+f"(c[1]), "+f"(c[2]), "+f"(c[3])
        : "r"(a[0]), "r"(a[1]), "r"(a[2]), "r"(a[3]), "r"(b[0]), "r"(b[1]));
}

// ---------------- TF32x3 tensor-core GEMM ----------------
// C[m][n] = sum_k A[m][k]*B[n][k] + bias[n], optional relu.
__global__ void __launch_bounds__(256) gemm_tf32x3(
    const float* __restrict__ A, const float* __restrict__ B,
    const float* __restrict__ bias, float* __restrict__ C,
    int M, int N, int K, int relu)
{
    __shared__ float sA[128][36];
    __shared__ float sB[128][36];

    const int tid  = threadIdx.x;
    const int lane = tid & 31;
    const int warp = tid >> 5;
    const int bm   = blockIdx.y << 7;
    const int bn   = blockIdx.x << 7;
    const int warpM = (warp >> 1) << 5;
    const int warpN = (warp & 1) << 6;

    const int srow = tid >> 3;
    const int scol = (tid & 7) << 2;
    const float* Ag = A + (size_t)(bm + srow) * K + scol;
    const float* Bg = B + (size_t)(bn + srow) * K + scol;

    float acc[2][8][4];
    #pragma unroll
    for (int mi = 0; mi < 2; mi++)
        #pragma unroll
        for (int ni = 0; ni < 8; ni++)
            #pragma unroll
            for (int r = 0; r < 4; r++) acc[mi][ni][r] = 0.f;

    const int ntiles = K >> 5;

    float4 ra[4], rb[4];
    #pragma unroll
    for (int p = 0; p < 4; p++) {
        ra[p] = *(const float4*)(Ag + (size_t)(p * 32) * K);
        rb[p] = *(const float4*)(Bg + (size_t)(p * 32) * K);
    }
    #pragma unroll
    for (int p = 0; p < 4; p++) {
        *(float4*)&sA[p * 32 + srow][scol] = ra[p];
        *(float4*)&sB[p * 32 + srow][scol] = rb[p];
    }
    __syncthreads();

    for (int kt = 0; kt < ntiles; kt++) {
        const bool last = (kt == ntiles - 1);
        if (!last) {
            const float* Ap = Ag + (size_t)((kt + 1) << 5);
            const float* Bp = Bg + (size_t)((kt + 1) << 5);
            #pragma unroll
            for (int p = 0; p < 4; p++) {
                ra[p] = *(const float4*)(Ap + (size_t)(p * 32) * K);
                rb[p] = *(const float4*)(Bp + (size_t)(p * 32) * K);
            }
        }

        #pragma unroll
        for (int kk = 0; kk < 4; kk++) {
            const int k = (kk << 3) + (lane & 3);
            const int rq = lane >> 2;

            uint32_t ah[2][4], al[2][4];
            #pragma unroll
            for (int mi = 0; mi < 2; mi++) {
                const int r0 = warpM + (mi << 4) + rq;
                split_tf32(sA[r0][k],     ah[mi][0], al[mi][0]);
                split_tf32(sA[r0 + 8][k], ah[mi][1], al[mi][1]);
                split_tf32(sA[r0][k + 4],     ah[mi][2], al[mi][2]);
                split_tf32(sA[r0 + 8][k + 4], ah[mi][3], al[mi][3]);
            }
            uint32_t bh[8][2], bl[8][2];
            #pragma unroll
            for (int ni = 0; ni < 8; ni++) {
                const int c0 = warpN + (ni << 3) + rq;
                split_tf32(sB[c0][k],     bh[ni][0], bl[ni][0]);
                split_tf32(sB[c0][k + 4], bh[ni][1], bl[ni][1]);
            }
            #pragma unroll
            for (int mi = 0; mi < 2; mi++)
                #pragma unroll
                for (int ni = 0; ni < 8; ni++) {
                    mma_tf32(acc[mi][ni], ah[mi], bh[ni]);
                    mma_tf32(acc[mi][ni], ah[mi], bl[ni]);
                    mma_tf32(acc[mi][ni], al[mi], bh[ni]);
                }
        }

        if (last) break;
        __syncthreads();
        #pragma unroll
        for (int p = 0; p < 4; p++) {
            *(float4*)&sA[p * 32 + srow][scol] = ra[p];
            *(float4*)&sB[p * 32 + srow][scol] = rb[p];
        }
        __syncthreads();
    }

    const int rq = lane >> 2;
    const int cq = (lane & 3) << 1;
    #pragma unroll
    for (int ni = 0; ni < 8; ni++) {
        const int col = bn + warpN + (ni << 3) + cq;
        const float b0 = bias[col], b1 = bias[col + 1];
        #pragma unroll
        for (int mi = 0; mi < 2; mi++) {
            const int row0 = bm + warpM + (mi << 4) + rq;
            float2 v0, v1;
            v0.x = acc[mi][ni][0] + b0; v0.y = acc[mi][ni][1] + b1;
            v1.x = acc[mi][ni][2] + b0; v1.y = acc[mi][ni][3] + b1;
            if (relu) {
                v0.x = fmaxf(v0.x, 0.f); v0.y = fmaxf(v0.y, 0.f);
                v1.x = fmaxf(v1.x, 0.f); v1.y = fmaxf(v1.y, 0.f);
            }
            *(float2*)&C[(size_t)row0 * N + col] = v0;
            *(float2*)&C[(size_t)(row0 + 8) * N + col] = v1;
        }
    }
}

// ---------------- MMA flash attention (tf32x3) ----------------
// CTA: 64 query rows for one (b,h). 4 warps x 16 rows. K-tiles of 64 keys.
// QK^T and P@V on tensor cores with exact 3-term tf32 split (~fp32 accuracy).
// SMEM: K tile (aliased as P after QK phase) + V tile = 35.8 KB static.
__global__ void __launch_bounds__(128) flash_mma_kernel(
    const float* __restrict__ qkv, float* __restrict__ out)
{
    __shared__ float Ks[64][68];   // K tile; reused as P (64q x 64k) after QK
    __shared__ float Vs[64][72];

    const int tid  = threadIdx.x;
    const int lane = tid & 31;
    const int w    = tid >> 5;        // warp 0..3
    const int g    = lane >> 2;       // 0..7
    const int t    = lane & 3;        // 0..3
    const int qb   = blockIdx.x;      // 0..15, 64 rows each
    const int bh   = blockIdx.y;      // 0..127
    const int b    = bh >> 2, h = bh & 3;

    const float* base = qkv + (size_t)b * 1024 * 768;
    const float* qg = base + h * 64;
    const float* kg = base + 256 + h * 64;
    const float* vg = base + 512 + h * 64;

    const int wr = w * 16;            // warp row base within q block
    const float SCALE = 0.125f;
    const float L2E   = 1.4426950408889634f;

    // ---- stage Q tile (64x64) into Ks, pull fragments into registers ----
    #pragma unroll
    for (int i = 0; i < 8; i++) {
        int idx = i * 128 + tid;
        int row = idx >> 4, c4 = (idx & 15) << 2;
        *(float4*)&Ks[row][c4] =
            *(const float4*)&qg[(size_t)(qb * 64 + row) * 768 + c4];
    }
    __syncthreads();

    uint32_t qh[8][4], ql[8][4];
    {
        const int r0 = wr + g;
        #pragma unroll
        for (int ks = 0; ks < 8; ks++) {
            const int k0 = ks << 3;
            split_tf32(Ks[r0][k0 + t],         qh[ks][0], ql[ks][0]);
            split_tf32(Ks[r0 + 8][k0 + t],     qh[ks][1], ql[ks][1]);
            split_tf32(Ks[r0][k0 + t + 4],     qh[ks][2], ql[ks][2]);
            split_tf32(Ks[r0 + 8][k0 + t + 4], qh[ks][3], ql[ks][3]);
        }
    }
    __syncthreads();   // Q staging consumed before K tile overwrites

    float oacc[8][4];
    #pragma unroll
    for (int nt = 0; nt < 8; nt++)
        #pragma unroll
        for (int r = 0; r < 4; r++) oacc[nt][r] = 0.f;
    float m0 = -1e30f, m1 = -1e30f, l0 = 0.f, l1 = 0.f;

    for (int kb = 0; kb < 16; kb++) {
        // load K,V tiles (64 keys x 64 dims)
        #pragma unroll
        for (int i = 0; i < 8; i++) {
            int idx = i * 128 + tid;
            int row = idx >> 4, c4 = (idx & 15) << 2;
            size_t goff = (size_t)(kb * 64 + row) * 768 + c4;
            *(float4*)&Ks[row][c4] = *(const float4*)&kg[goff];
            *(float4*)&Vs[row][c4] = *(const float4*)&vg[goff];
        }
        __syncthreads();

        // ---- QK^T: scores 16x64 per warp ----
        float sc[8][4];
        #pragma unroll
        for (int nt = 0; nt < 8; nt++)
            #pragma unroll
            for (int r = 0; r < 4; r++) sc[nt][r] = 0.f;

        #pragma unroll
        for (int ks = 0; ks < 8; ks++) {
            const int k0 = ks << 3;
            #pragma unroll
            for (int nt = 0; nt < 8; nt++) {
                uint32_t kh2[2], kl2[2];
                split_tf32(Ks[(nt << 3) + g][k0 + t],     kh2[0], kl2[0]);
                split_tf32(Ks[(nt << 3) + g][k0 + t + 4], kh2[1], kl2[1]);
                mma_tf32(sc[nt], qh[ks], kh2);
                mma_tf32(sc[nt], qh[ks], kl2);
                mma_tf32(sc[nt], ql[ks], kh2);
            }
        }

        // ---- online softmax (register, 4-lane row groups) ----
        float mb0 = -1e30f, mb1 = -1e30f;
        #pragma unroll
        for (int nt = 0; nt < 8; nt++) {
            sc[nt][0] *= SCALE; sc[nt][1] *= SCALE;
            sc[nt][2] *= SCALE; sc[nt][3] *= SCALE;
            mb0 = fmaxf(mb0, fmaxf(sc[nt][0], sc[nt][1]));
            mb1 = fmaxf(mb1, fmaxf(sc[nt][2], sc[nt][3]));
        }
        #pragma unroll
        for (int off = 1; off <= 2; off <<= 1) {
            mb0 = fmaxf(mb0, __shfl_xor_sync(0xffffffffu, mb0, off));
            mb1 = fmaxf(mb1, __shfl_xor_sync(0xffffffffu, mb1, off));
        }
        const float mn0 = fmaxf(m0, mb0);
        const float mn1 = fmaxf(m1, mb1);
        const float c0 = exp2f((m0 - mn0) * L2E);
        const float c1 = exp2f((m1 - mn1) * L2E);
        l0 *= c0; l1 *= c1;
        #pragma unroll
        for (int nt = 0; nt < 8; nt++) {
            oacc[nt][0] *= c0; oacc[nt][1] *= c0;
            oacc[nt][2] *= c1; oacc[nt][3] *= c1;
        }
        #pragma unroll
        for (int nt = 0; nt < 8; nt++) {
            sc[nt][0] = exp2f((sc[nt][0] - mn0) * L2E);
            sc[nt][1] = exp2f((sc[nt][1] - mn0) * L2E);
            sc[nt][2] = exp2f((sc[nt][2] - mn1) * L2E);
            sc[nt][3] = exp2f((sc[nt][3] - mn1) * L2E);
            l0 += sc[nt][0] + sc[nt][1];
            l1 += sc[nt][2] + sc[nt][3];
        }
        m0 = mn0; m1 = mn1;

        // ---- P -> smem (aliases Ks; wait for all warps' K reads) ----
        __syncthreads();
        #pragma unroll
        for (int nt = 0; nt < 8; nt++) {
            const int col = (nt << 3) + (t << 1);
            *(float2*)&Ks[wr + g][col]     = make_float2(sc[nt][0], sc[nt][1]);
            *(float2*)&Ks[wr + g + 8][col] = make_float2(sc[nt][2], sc[nt][3]);
        }
        __syncwarp();

        // ---- P @ V ----
        #pragma unroll
        for (int ks = 0; ks < 8; ks++) {
            const int k0 = ks << 3;
            uint32_t ah2[4], al2[4];
            split_tf32(Ks[wr + g][k0 + t],         ah2[0], al2[0]);
            split_tf32(Ks[wr + g + 8][k0 + t],     ah2[1], al2[1]);
            split_tf32(Ks[wr + g][k0 + t + 4],     ah2[2], al2[2]);
            split_tf32(Ks[wr + g + 8][k0 + t + 4], ah2[3], al2[3]);
            #pragma unroll
            for (int nt = 0; nt < 8; nt++) {
                uint32_t vh2[2], vl2[2];
                split_tf32(Vs[k0 + t][(nt << 3) + g],     vh2[0], vl2[0]);
                split_tf32(Vs[k0 + t + 4][(nt << 3) + g], vh2[1], vl2[1]);
                mma_tf32(oacc[nt], ah2, vh2);
                mma_tf32(oacc[nt], ah2, vl2);
                mma_tf32(oacc[nt], al2, vh2);
            }
        }
        __syncthreads();  // AV reads done before next tile load
    }

    // final row-sum reduction of l across the 4-lane group
    #pragma unroll
    for (int off = 1; off <= 2; off <<= 1) {
        l0 += __shfl_xor_sync(0xffffffffu, l0, off);
        l1 += __shfl_xor_sync(0xffffffffu, l1, off);
    }
    const float inv0 = 1.f / l0;
    const float inv1 = 1.f / l1;

    const int row0 = qb * 64 + wr + g;
    float* op0 = out + ((size_t)(b * 1024 + row0)) * 256 + h * 64;
    float* op1 = op0 + (size_t)8 * 256;
    #pragma unroll
    for (int nt = 0; nt < 8; nt++) {
        const int col = (nt << 3) + (t << 1);
        *(float2*)&op0[col] = make_float2(oacc[nt][0] * inv0, oacc[nt][1] * inv0);
        *(float2*)&op1[col] = make_float2(oacc[nt][2] * inv1, oacc[nt][3] * inv1);
    }
}

// ---------------- layernorm(xa + xb) * g + b  (one warp per 256-row) -----------
__global__ void __launch_bounds__(256) ln_kernel(
    const float* __restrict__ xa, const float* __restrict__ xb,
    const float* __restrict__ g, const float* __restrict__ bt,
    float* __restrict__ out)
{
    const int warp = threadIdx.x >> 5, lane = threadIdx.x & 31;
    const size_t row = (size_t)blockIdx.x * 8 + warp;
    const float* pa = xa + row * 256;
    const float* pb = xb + row * 256;

    float v[8];
    float s = 0.f;
    #pragma unroll
    for (int i = 0; i < 8; i++) {
        v[i] = pa[lane + 32 * i] + pb[lane + 32 * i];
        s += v[i];
    }
    #pragma unroll
    for (int off = 16; off > 0; off >>= 1) s += __shfl_xor_sync(0xffffffffu, s, off);
    float mean = s * (1.f / 256.f);

    float vs = 0.f;
    #pragma unroll
    for (int i = 0; i < 8; i++) {
        float d = v[i] - mean;
        vs += d * d;
    }
    #pragma unroll
    for (int off = 16; off > 0; off >>= 1) vs += __shfl_xor_sync(0xffffffffu, vs, off);
    float var = vs * (1.f / 256.f);
    float inv = 1.f / sqrtf(var + 1e-5f);

    #pragma unroll
    for (int i = 0; i < 8; i++) {
        int c = lane + 32 * i;
        out[row * 256 + c] = (v[i] - mean) * inv * g[c] + bt[c];
    }
}

// -------------------------------- launch ---------------------------------------
extern "C" void kernel_launch(void* const* d_in, const int* in_sizes, int n_in,
                              void* d_out, int out_size)
{
    const float* x     = (const float*)d_in[0];
    const float* Win   = (const float*)d_in[1];
    const float* Wres  = (const float*)d_in[2];
    const float* Wread = (const float*)d_in[3];
    const float* bread = (const float*)d_in[4];
    const float* Wqkv  = (const float*)d_in[5];
    const float* bqkv  = (const float*)d_in[6];
    const float* Wo    = (const float*)d_in[7];
    const float* bo    = (const float*)d_in[8];
    const float* g1    = (const float*)d_in[9];
    const float* b1    = (const float*)d_in[10];
    const float* g2    = (const float*)d_in[11];
    const float* b2    = (const float*)d_in[12];
    const float* W1    = (const float*)d_in[13];
    const float* c1    = (const float*)d_in[14];
    const float* W2    = (const float*)d_in[15];
    const float* c2    = (const float*)d_in[16];
    float* out = (float*)d_out;

    float *z, *h, *qkv, *attn, *tmp, *ff;
    cudaGetSymbolAddress((void**)&z,    g_z);
    cudaGetSymbolAddress((void**)&h,    g_h);
    cudaGetSymbolAddress((void**)&qkv,  g_qkv);
    cudaGetSymbolAddress((void**)&attn, g_attn);
    cudaGetSymbolAddress((void**)&tmp,  g_tmp);
    cudaGetSymbolAddress((void**)&ff,   g_ff);

    const int M = 32768;

    colsum_kernel<<<1, 512>>>(Wres);
    lif_kernel<<<32, 512>>>(x, Win, Wres, z);

    // h = z @ Wread^T + bread
    gemm_tf32x3<<<dim3(2, 256), 256>>>(z, Wread, bread, h, M, 256, 512, 0);

    for (int l = 0; l < 2; l++) {
        // qkv = h @ Wqkv^T + bqkv
        gemm_tf32x3<<<dim3(6, 256), 256>>>(h, Wqkv + (size_t)l * 768 * 256,
                                           bqkv + l * 768, qkv, M, 768, 256, 0);
        // attention (tensor-core flash)
        flash_mma_kernel<<<dim3(16, 128), 128>>>(qkv, attn);
        // tmp = attn @ Wo^T + bo
        gemm_tf32x3<<<dim3(2, 256), 256>>>(attn, Wo + (size_t)l * 256 * 256,
                                           bo + l * 256, tmp, M, 256, 256, 0);
        // h = LN(h + tmp)
        ln_kernel<<<4096, 256>>>(h, tmp, g1 + l * 256, b1 + l * 256, h);
        // ff = relu(h @ W1^T + c1)
        gemm_tf32x3<<<dim3(8, 256), 256>>>(h, W1 + (size_t)l * 1024 * 256,
                                           c1 + l * 1024, ff, M, 1024, 256, 1);
        // tmp = ff @ W2^T + c2
        gemm_tf32x3<<<dim3(2, 256), 256>>>(ff, W2 + (size_t)l * 256 * 1024,
                                           c2 + l * 256, tmp, M, 256, 1024, 0);
        // out/h = LN(h + tmp)
        ln_kernel<<<4096, 256>>>(h, tmp, g2 + l * 256, b2 + l * 256,
                                 (l == 1) ? out : h);
    }
}

// round 4
// speedup vs baseline: 2.2483x; 1.0647x over previous
#include <cuda_runtime.h>
#include <cstdint>

// ---------------- scratch (device globals; no allocation APIs) ----------------
__device__ float g_z   [32u*1024u*512u];   // spikes, 64MB
__device__ float g_h   [32768u*256u];      // hidden, 32MB
__device__ float g_qkv [32768u*768u];      // qkv, 96MB
__device__ float g_attn[32768u*256u];      // attn out, 32MB
__device__ float g_tmp [32768u*256u];      // proj/ff2 out, 32MB
__device__ float g_ff  [32768u*1024u];     // ff hidden, 128MB
__device__ float g_colsum[512];

// ---------------- column sums of Wres (for complement-sparsity) ----------------
__global__ void colsum_kernel(const float* __restrict__ Wres) {
    int r = threadIdx.x;
    float s0 = 0.f, s1 = 0.f, s2 = 0.f, s3 = 0.f;
    #pragma unroll 4
    for (int rr = 0; rr < 512; rr += 4) {
        s0 += Wres[(rr + 0) * 512 + r];
        s1 += Wres[(rr + 1) * 512 + r];
        s2 += Wres[(rr + 2) * 512 + r];
        s3 += Wres[(rr + 3) * 512 + r];
    }
    g_colsum[r] = (s0 + s1) + (s2 + s3);
}

// ---------------- LIF reservoir: one CTA per batch, 512 thr = 1/neuron ----------
__global__ void __launch_bounds__(512) lif_kernel(
    const float* __restrict__ x,     // [32][1024][8]
    const float* __restrict__ Win,   // [8][512]
    const float* __restrict__ Wres,  // [512][512]
    float* __restrict__ zout)        // [32][1024][512]
{
    const int b = blockIdx.x;
    const int r = threadIdx.x;
    const int warp = r >> 5, lane = r & 31;

    __shared__ float sWin[8][512];
    __shared__ float sx[8];
    __shared__ int   s_act[512];
    __shared__ int   s_in[512];
    __shared__ int   s_wcnt[16];

    #pragma unroll
    for (int i = 0; i < 8; i++) sWin[i][r] = Win[i * 512 + r];

    const float colsum = g_colsum[r];
    const float* xb = x + (size_t)b * 1024 * 8;
    float* zb = zout + (size_t)b * 1024 * 512;

    float v = 0.f, isyn = 0.f;
    int zprev = 0;

    for (int t = 0; t < 1024; t++) {
        unsigned bal = __ballot_sync(0xffffffffu, zprev);
        __syncthreads();
        if (lane == 0) s_wcnt[warp] = __popc(bal);
        if (r < 8) sx[r] = xb[t * 8 + r];
        __syncthreads();

        int na = 0, base_a = 0;
        #pragma unroll
        for (int w = 0; w < 16; w++) {
            int c = s_wcnt[w];
            na += c;
            if (w < warp) base_a += c;
        }
        int rank = __popc(bal & ((1u << lane) - 1u));
        if (zprev) {
            s_act[base_a + rank] = r;
        } else {
            int base_i = warp * 32 - base_a;
            s_in[base_i + (lane - rank)] = r;
        }
        __syncthreads();

        float cur = 0.f;
        #pragma unroll
        for (int i = 0; i < 8; i++) cur += sx[i] * sWin[i][r];

        float rec;
        if (na <= 256) {
            rec = 0.f;
            for (int j = 0; j < na; j++)
                rec += Wres[s_act[j] * 512 + r];
        } else {
            const int ni = 512 - na;
            float a0 = 0.f, a1 = 0.f, a2 = 0.f, a3 = 0.f;
            int j = 0;
            for (; j + 4 <= ni; j += 4) {
                a0 += Wres[s_in[j + 0] * 512 + r];
                a1 += Wres[s_in[j + 1] * 512 + r];
                a2 += Wres[s_in[j + 2] * 512 + r];
                a3 += Wres[s_in[j + 3] * 512 + r];
            }
            for (; j < ni; j++) a0 += Wres[s_in[j] * 512 + r];
            rec = colsum - ((a0 + a1) + (a2 + a3));
        }

        float total = cur + rec;
        float vdec = v + 0.004f * (isyn - v);
        float idec = isyn * 0.8f;
        float z = (vdec - 0.1f) > 0.f ? 1.f : 0.f;
        v = (1.f - z) * vdec;
        isyn = idec + total;
        zb[(size_t)t * 512 + r] = z;
        zprev = (z > 0.f);
    }
}

// ---------------- TF32x3 helpers ----------------
__device__ __forceinline__ void split_tf32(float x, uint32_t& hi, uint32_t& lo) {
    uint32_t xb = __float_as_uint(x);
    hi = xb & 0xffffe000u;
    lo = __float_as_uint(x - __uint_as_float(hi));
}

__device__ __forceinline__ void mma_tf32(float* c, const uint32_t* a, const uint32_t* b) {
    asm volatile(
        "mma.sync.aligned.m16n8k8.row.col.f32.tf32.tf32.f32 "
        "{%0,%1,%2,%3},{%4,%5,%6,%7},{%8,%9},{%0,%1,%2,%3};\n"
        : "+f"(c[0]), "+f"(c[1]), "+f"(c[2]), "+f"(c[3])
        : "r"(a[0]), "r"(a[1]), "r"(a[2]), "r"(a[3]), "r"(b[0]), "r"(b[1]));
}

__device__ __forceinline__ void cp_async16(uint32_t saddr, const void* gptr) {
    asm volatile("cp.async.ca.shared.global [%0], [%1], 16;\n"
                 :: "r"(saddr), "l"(gptr));
}

// ---------------- TF32x3 tensor-core GEMM, cp.async double-buffered -----------
// C[m][n] = sum_k A[m][k]*B[n][k] + bias[n], optional relu.
// Block tile 128x128, K-tile 32, 256 thr (8 warps, 4x2), 2 CTAs/SM.
// Dynamic SMEM: 2 stages x (A 128x36 + B 128x36) floats = 73728 B.
#define GEMM_PITCH 36
#define GEMM_TILE  (128 * GEMM_PITCH)
#define GEMM_SMEM_BYTES (2 * 2 * GEMM_TILE * 4)

__global__ void __launch_bounds__(256, 2) gemm_tf32x3(
    const float* __restrict__ A, const float* __restrict__ B,
    const float* __restrict__ bias, float* __restrict__ C,
    int M, int N, int K, int relu)
{
    extern __shared__ float smem[];

    const int tid  = threadIdx.x;
    const int lane = tid & 31;
    const int warp = tid >> 5;
    const int bm   = blockIdx.y << 7;
    const int bn   = blockIdx.x << 7;
    const int warpM = (warp >> 1) << 5;
    const int warpN = (warp & 1) << 6;
    const int rq = lane >> 2;
    const int t  = lane & 3;

    const int srow = tid >> 3;            // 0..31
    const int scol = (tid & 7) << 2;      // 0..28
    const float* Ag = A + (size_t)(bm + srow) * K + scol;
    const float* Bg = B + (size_t)(bn + srow) * K + scol;

    // SMEM stage bases (u32 shared addresses for cp.async)
    const uint32_t smem_u32 = (uint32_t)__cvta_generic_to_shared(smem);
    const uint32_t stA[2] = { smem_u32, smem_u32 + 2u * GEMM_TILE * 4u };
    const uint32_t stB[2] = { smem_u32 + GEMM_TILE * 4u,
                              smem_u32 + 3u * GEMM_TILE * 4u };
    const uint32_t soff = ((uint32_t)srow * GEMM_PITCH + scol) * 4u;

    float acc[2][8][4];
    #pragma unroll
    for (int mi = 0; mi < 2; mi++)
        #pragma unroll
        for (int ni = 0; ni < 8; ni++)
            #pragma unroll
            for (int r = 0; r < 4; r++) acc[mi][ni][r] = 0.f;

    const int ntiles = K >> 5;

    // issue tile kt into stage s
    auto issue = [&](int kt, int s) {
        const float* Ap = Ag + (kt << 5);
        const float* Bp = Bg + (kt << 5);
        #pragma unroll
        for (int p = 0; p < 4; p++) {
            cp_async16(stA[s] + soff + p * 32u * GEMM_PITCH * 4u,
                       Ap + (size_t)(p * 32) * K);
            cp_async16(stB[s] + soff + p * 32u * GEMM_PITCH * 4u,
                       Bp + (size_t)(p * 32) * K);
        }
        asm volatile("cp.async.commit_group;\n");
    };

    issue(0, 0);
    issue(1, 1);

    for (int kt = 0; kt < ntiles; kt++) {
        const int s = kt & 1;
        if (kt + 2 < ntiles)
            asm volatile("cp.async.wait_group 1;\n" ::: "memory");
        else
            asm volatile("cp.async.wait_group 0;\n" ::: "memory");
        __syncthreads();

        const float* cA = smem + (size_t)s * 2 * GEMM_TILE;
        const float* cB = cA + GEMM_TILE;

        #pragma unroll
        for (int kk = 0; kk < 4; kk++) {
            const int k = (kk << 3) + t;

            uint32_t ah[2][4], al[2][4];
            #pragma unroll
            for (int mi = 0; mi < 2; mi++) {
                const int r0 = warpM + (mi << 4) + rq;
                split_tf32(cA[r0 * GEMM_PITCH + k],           ah[mi][0], al[mi][0]);
                split_tf32(cA[(r0 + 8) * GEMM_PITCH + k],     ah[mi][1], al[mi][1]);
                split_tf32(cA[r0 * GEMM_PITCH + k + 4],       ah[mi][2], al[mi][2]);
                split_tf32(cA[(r0 + 8) * GEMM_PITCH + k + 4], ah[mi][3], al[mi][3]);
            }
            #pragma unroll
            for (int ni = 0; ni < 8; ni++) {
                const int c0 = warpN + (ni << 3) + rq;
                uint32_t bh[2], bl[2];
                split_tf32(cB[c0 * GEMM_PITCH + k],     bh[0], bl[0]);
                split_tf32(cB[c0 * GEMM_PITCH + k + 4], bh[1], bl[1]);
                mma_tf32(acc[0][ni], ah[0], bh);
                mma_tf32(acc[0][ni], ah[0], bl);
                mma_tf32(acc[0][ni], al[0], bh);
                mma_tf32(acc[1][ni], ah[1], bh);
                mma_tf32(acc[1][ni], ah[1], bl);
                mma_tf32(acc[1][ni], al[1], bh);
            }
        }

        __syncthreads();
        if (kt + 2 < ntiles) issue(kt + 2, s);
    }

    // epilogue
    const int cq = t << 1;
    #pragma unroll
    for (int ni = 0; ni < 8; ni++) {
        const int col = bn + warpN + (ni << 3) + cq;
        const float b0 = bias[col], b1 = bias[col + 1];
        #pragma unroll
        for (int mi = 0; mi < 2; mi++) {
            const int row0 = bm + warpM + (mi << 4) + rq;
            float2 v0, v1;
            v0.x = acc[mi][ni][0] + b0; v0.y = acc[mi][ni][1] + b1;
            v1.x = acc[mi][ni][2] + b0; v1.y = acc[mi][ni][3] + b1;
            if (relu) {
                v0.x = fmaxf(v0.x, 0.f); v0.y = fmaxf(v0.y, 0.f);
                v1.x = fmaxf(v1.x, 0.f); v1.y = fmaxf(v1.y, 0.f);
            }
            *(float2*)&C[(size_t)row0 * N + col] = v0;
            *(float2*)&C[(size_t)(row0 + 8) * N + col] = v1;
        }
    }
}

// ---------------- MMA flash attention (tf32x3) ----------------
__global__ void __launch_bounds__(128) flash_mma_kernel(
    const float* __restrict__ qkv, float* __restrict__ out)
{
    __shared__ float Ks[64][68];   // K tile; reused as P after QK
    __shared__ float Vs[64][72];

    const int tid  = threadIdx.x;
    const int lane = tid & 31;
    const int w    = tid >> 5;
    const int g    = lane >> 2;
    const int t    = lane & 3;
    const int qb   = blockIdx.x;
    const int bh   = blockIdx.y;
    const int b    = bh >> 2, h = bh & 3;

    const float* base = qkv + (size_t)b * 1024 * 768;
    const float* qg = base + h * 64;
    const float* kg = base + 256 + h * 64;
    const float* vg = base + 512 + h * 64;

    const int wr = w * 16;
    const float SCALE = 0.125f;
    const float L2E   = 1.4426950408889634f;

    #pragma unroll
    for (int i = 0; i < 8; i++) {
        int idx = i * 128 + tid;
        int row = idx >> 4, c4 = (idx & 15) << 2;
        *(float4*)&Ks[row][c4] =
            *(const float4*)&qg[(size_t)(qb * 64 + row) * 768 + c4];
    }
    __syncthreads();

    uint32_t qh[8][4], ql[8][4];
    {
        const int r0 = wr + g;
        #pragma unroll
        for (int ks = 0; ks < 8; ks++) {
            const int k0 = ks << 3;
            split_tf32(Ks[r0][k0 + t],         qh[ks][0], ql[ks][0]);
            split_tf32(Ks[r0 + 8][k0 + t],     qh[ks][1], ql[ks][1]);
            split_tf32(Ks[r0][k0 + t + 4],     qh[ks][2], ql[ks][2]);
            split_tf32(Ks[r0 + 8][k0 + t + 4], qh[ks][3], ql[ks][3]);
        }
    }
    __syncthreads();

    float oacc[8][4];
    #pragma unroll
    for (int nt = 0; nt < 8; nt++)
        #pragma unroll
        for (int r = 0; r < 4; r++) oacc[nt][r] = 0.f;
    float m0 = -1e30f, m1 = -1e30f, l0 = 0.f, l1 = 0.f;

    for (int kb = 0; kb < 16; kb++) {
        #pragma unroll
        for (int i = 0; i < 8; i++) {
            int idx = i * 128 + tid;
            int row = idx >> 4, c4 = (idx & 15) << 2;
            size_t goff = (size_t)(kb * 64 + row) * 768 + c4;
            *(float4*)&Ks[row][c4] = *(const float4*)&kg[goff];
            *(float4*)&Vs[row][c4] = *(const float4*)&vg[goff];
        }
        __syncthreads();

        float sc[8][4];
        #pragma unroll
        for (int nt = 0; nt < 8; nt++)
            #pragma unroll
            for (int r = 0; r < 4; r++) sc[nt][r] = 0.f;

        #pragma unroll
        for (int ks = 0; ks < 8; ks++) {
            const int k0 = ks << 3;
            #pragma unroll
            for (int nt = 0; nt < 8; nt++) {
                uint32_t kh2[2], kl2[2];
                split_tf32(Ks[(nt << 3) + g][k0 + t],     kh2[0], kl2[0]);
                split_tf32(Ks[(nt << 3) + g][k0 + t + 4], kh2[1], kl2[1]);
                mma_tf32(sc[nt], qh[ks], kh2);
                mma_tf32(sc[nt], qh[ks], kl2);
                mma_tf32(sc[nt], ql[ks], kh2);
            }
        }

        float mb0 = -1e30f, mb1 = -1e30f;
        #pragma unroll
        for (int nt = 0; nt < 8; nt++) {
            sc[nt][0] *= SCALE; sc[nt][1] *= SCALE;
            sc[nt][2] *= SCALE; sc[nt][3] *= SCALE;
            mb0 = fmaxf(mb0, fmaxf(sc[nt][0], sc[nt][1]));
            mb1 = fmaxf(mb1, fmaxf(sc[nt][2], sc[nt][3]));
        }
        #pragma unroll
        for (int off = 1; off <= 2; off <<= 1) {
            mb0 = fmaxf(mb0, __shfl_xor_sync(0xffffffffu, mb0, off));
            mb1 = fmaxf(mb1, __shfl_xor_sync(0xffffffffu, mb1, off));
        }
        const float mn0 = fmaxf(m0, mb0);
        const float mn1 = fmaxf(m1, mb1);
        const float c0 = exp2f((m0 - mn0) * L2E);
        const float c1 = exp2f((m1 - mn1) * L2E);
        l0 *= c0; l1 *= c1;
        #pragma unroll
        for (int nt = 0; nt < 8; nt++) {
            oacc[nt][0] *= c0; oacc[nt][1] *= c0;
            oacc[nt][2] *= c1; oacc[nt][3] *= c1;
        }
        #pragma unroll
        for (int nt = 0; nt < 8; nt++) {
            sc[nt][0] = exp2f((sc[nt][0] - mn0) * L2E);
            sc[nt][1] = exp2f((sc[nt][1] - mn0) * L2E);
            sc[nt][2] = exp2f((sc[nt][2] - mn1) * L2E);
            sc[nt][3] = exp2f((sc[nt][3] - mn1) * L2E);
            l0 += sc[nt][0] + sc[nt][1];
            l1 += sc[nt][2] + sc[nt][3];
        }
        m0 = mn0; m1 = mn1;

        __syncthreads();
        #pragma unroll
        for (int nt = 0; nt < 8; nt++) {
            const int col = (nt << 3) + (t << 1);
            *(float2*)&Ks[wr + g][col]     = make_float2(sc[nt][0], sc[nt][1]);
            *(float2*)&Ks[wr + g + 8][col] = make_float2(sc[nt][2], sc[nt][3]);
        }
        __syncwarp();

        #pragma unroll
        for (int ks = 0; ks < 8; ks++) {
            const int k0 = ks << 3;
            uint32_t ah2[4], al2[4];
            split_tf32(Ks[wr + g][k0 + t],         ah2[0], al2[0]);
            split_tf32(Ks[wr + g + 8][k0 + t],     ah2[1], al2[1]);
            split_tf32(Ks[wr + g][k0 + t + 4],     ah2[2], al2[2]);
            split_tf32(Ks[wr + g + 8][k0 + t + 4], ah2[3], al2[3]);
            #pragma unroll
            for (int nt = 0; nt < 8; nt++) {
                uint32_t vh2[2], vl2[2];
                split_tf32(Vs[k0 + t][(nt << 3) + g],     vh2[0], vl2[0]);
                split_tf32(Vs[k0 + t + 4][(nt << 3) + g], vh2[1], vl2[1]);
                mma_tf32(oacc[nt], ah2, vh2);
                mma_tf32(oacc[nt], ah2, vl2);
                mma_tf32(oacc[nt], al2, vh2);
            }
        }
        __syncthreads();
    }

    #pragma unroll
    for (int off = 1; off <= 2; off <<= 1) {
        l0 += __shfl_xor_sync(0xffffffffu, l0, off);
        l1 += __shfl_xor_sync(0xffffffffu, l1, off);
    }
    const float inv0 = 1.f / l0;
    const float inv1 = 1.f / l1;

    const int row0 = qb * 64 + wr + g;
    float* op0 = out + ((size_t)(b * 1024 + row0)) * 256 + h * 64;
    float* op1 = op0 + (size_t)8 * 256;
    #pragma unroll
    for (int nt = 0; nt < 8; nt++) {
        const int col = (nt << 3) + (t << 1);
        *(float2*)&op0[col] = make_float2(oacc[nt][0] * inv0, oacc[nt][1] * inv0);
        *(float2*)&op1[col] = make_float2(oacc[nt][2] * inv1, oacc[nt][3] * inv1);
    }
}

// ---------------- layernorm(xa + xb) * g + b  (one warp per 256-row) -----------
__global__ void __launch_bounds__(256) ln_kernel(
    const float* __restrict__ xa, const float* __restrict__ xb,
    const float* __restrict__ g, const float* __restrict__ bt,
    float* __restrict__ out)
{
    const int warp = threadIdx.x >> 5, lane = threadIdx.x & 31;
    const size_t row = (size_t)blockIdx.x * 8 + warp;
    const float* pa = xa + row * 256;
    const float* pb = xb + row * 256;

    float v[8];
    float s = 0.f;
    #pragma unroll
    for (int i = 0; i < 8; i++) {
        v[i] = pa[lane + 32 * i] + pb[lane + 32 * i];
        s += v[i];
    }
    #pragma unroll
    for (int off = 16; off > 0; off >>= 1) s += __shfl_xor_sync(0xffffffffu, s, off);
    float mean = s * (1.f / 256.f);

    float vs = 0.f;
    #pragma unroll
    for (int i = 0; i < 8; i++) {
        float d = v[i] - mean;
        vs += d * d;
    }
    #pragma unroll
    for (int off = 16; off > 0; off >>= 1) vs += __shfl_xor_sync(0xffffffffu, vs, off);
    float var = vs * (1.f / 256.f);
    float inv = 1.f / sqrtf(var + 1e-5f);

    #pragma unroll
    for (int i = 0; i < 8; i++) {
        int c = lane + 32 * i;
        out[row * 256 + c] = (v[i] - mean) * inv * g[c] + bt[c];
    }
}

// -------------------------------- launch ---------------------------------------
extern "C" void kernel_launch(void* const* d_in, const int* in_sizes, int n_in,
                              void* d_out, int out_size)
{
    const float* x     = (const float*)d_in[0];
    const float* Win   = (const float*)d_in[1];
    const float* Wres  = (const float*)d_in[2];
    const float* Wread = (const float*)d_in[3];
    const float* bread = (const float*)d_in[4];
    const float* Wqkv  = (const float*)d_in[5];
    const float* bqkv  = (const float*)d_in[6];
    const float* Wo    = (const float*)d_in[7];
    const float* bo    = (const float*)d_in[8];
    const float* g1    = (const float*)d_in[9];
    const float* b1    = (const float*)d_in[10];
    const float* g2    = (const float*)d_in[11];
    const float* b2    = (const float*)d_in[12];
    const float* W1    = (const float*)d_in[13];
    const float* c1    = (const float*)d_in[14];
    const float* W2    = (const float*)d_in[15];
    const float* c2    = (const float*)d_in[16];
    float* out = (float*)d_out;

    float *z, *h, *qkv, *attn, *tmp, *ff;
    cudaGetSymbolAddress((void**)&z,    g_z);
    cudaGetSymbolAddress((void**)&h,    g_h);
    cudaGetSymbolAddress((void**)&qkv,  g_qkv);
    cudaGetSymbolAddress((void**)&attn, g_attn);
    cudaGetSymbolAddress((void**)&tmp,  g_tmp);
    cudaGetSymbolAddress((void**)&ff,   g_ff);

    cudaFuncSetAttribute(gemm_tf32x3,
                         cudaFuncAttributeMaxDynamicSharedMemorySize,
                         GEMM_SMEM_BYTES);

    const int M = 32768;
    const int SB = GEMM_SMEM_BYTES;

    colsum_kernel<<<1, 512>>>(Wres);
    lif_kernel<<<32, 512>>>(x, Win, Wres, z);

    // h = z @ Wread^T + bread
    gemm_tf32x3<<<dim3(2, 256), 256, SB>>>(z, Wread, bread, h, M, 256, 512, 0);

    for (int l = 0; l < 2; l++) {
        // qkv = h @ Wqkv^T + bqkv
        gemm_tf32x3<<<dim3(6, 256), 256, SB>>>(h, Wqkv + (size_t)l * 768 * 256,
                                               bqkv + l * 768, qkv, M, 768, 256, 0);
        // attention (tensor-core flash)
        flash_mma_kernel<<<dim3(16, 128), 128>>>(qkv, attn);
        // tmp = attn @ Wo^T + bo
        gemm_tf32x3<<<dim3(2, 256), 256, SB>>>(attn, Wo + (size_t)l * 256 * 256,
                                               bo + l * 256, tmp, M, 256, 256, 0);
        // h = LN(h + tmp)
        ln_kernel<<<4096, 256>>>(h, tmp, g1 + l * 256, b1 + l * 256, h);
        // ff = relu(h @ W1^T + c1)
        gemm_tf32x3<<<dim3(8, 256), 256, SB>>>(h, W1 + (size_t)l * 1024 * 256,
                                               c1 + l * 1024, ff, M, 1024, 256, 1);
        // tmp = ff @ W2^T + c2
        gemm_tf32x3<<<dim3(2, 256), 256, SB>>>(ff, W2 + (size_t)l * 256 * 1024,
                                               c2 + l * 256, tmp, M, 256, 1024, 0);
        // out/h = LN(h + tmp)
        ln_kernel<<<4096, 256>>>(h, tmp, g2 + l * 256, b2 + l * 256,
                                 (l == 1) ? out : h);
    }
}

// round 5
// speedup vs baseline: 2.5044x; 1.1139x over previous
#include <cuda_runtime.h>
#include <cstdint>

// ---------------- scratch (device globals; no allocation APIs) ----------------
__device__ float    g_qkv [32768u*768u];     // fp32 qkv (flash input), 96MB
__device__ float    g_h   [32768u*256u];     // fp32 hidden (residual), 32MB
__device__ float    g_tmp [32768u*256u];     // fp32 proj/ff2 out, 32MB
__device__ float    g_colsum[512];

// bf16x2 packed (hi,lo) operand arrays; u32 = {odd<<16 | even}
__device__ uint32_t g_zh   [32u*1024u*256u]; // spikes bf16 (exact), 32MB
__device__ uint32_t g_hh   [32768u*128u], g_hl   [32768u*128u];
__device__ uint32_t g_attnh[32768u*128u], g_attnl[32768u*128u];
__device__ uint32_t g_ffh  [32768u*512u], g_ffl  [32768u*512u];
__device__ uint32_t g_wrh  [256u*256u],   g_wrl  [256u*256u];
__device__ uint32_t g_wqh  [2u*768u*128u],g_wql  [2u*768u*128u];
__device__ uint32_t g_woh  [2u*256u*128u],g_wol  [2u*256u*128u];
__device__ uint32_t g_w1h  [2u*1024u*128u],g_w1l [2u*1024u*128u];
__device__ uint32_t g_w2h  [2u*256u*512u],g_w2l  [2u*256u*512u];

// ---------------- bf16 split helpers ----------------
// pack two floats (e=even/low, o=odd/high) into bf16x2 hi word + residual lo word
__device__ __forceinline__ void split2(float e, float o, uint32_t& hi, uint32_t& lo) {
    asm("cvt.rn.bf16x2.f32 %0, %1, %2;" : "=r"(hi) : "f"(o), "f"(e));
    float he = __uint_as_float(hi << 16);
    float ho = __uint_as_float(hi & 0xffff0000u);
    asm("cvt.rn.bf16x2.f32 %0, %1, %2;" : "=r"(lo) : "f"(o - ho), "f"(e - he));
}

__global__ void wsplit_kernel(const float* __restrict__ src,
                              uint32_t* __restrict__ h, uint32_t* __restrict__ l,
                              int npairs) {
    int i = blockIdx.x * 256 + threadIdx.x;
    if (i < npairs) {
        float2 v = *(const float2*)(src + 2 * i);
        split2(v.x, v.y, h[i], l[i]);
    }
}

// ---------------- column sums of Wres ----------------
__global__ void colsum_kernel(const float* __restrict__ Wres) {
    int r = threadIdx.x;
    float s0 = 0.f, s1 = 0.f, s2 = 0.f, s3 = 0.f;
    #pragma unroll 4
    for (int rr = 0; rr < 512; rr += 4) {
        s0 += Wres[(rr + 0) * 512 + r];
        s1 += Wres[(rr + 1) * 512 + r];
        s2 += Wres[(rr + 2) * 512 + r];
        s3 += Wres[(rr + 3) * 512 + r];
    }
    g_colsum[r] = (s0 + s1) + (s2 + s3);
}

// ---------------- LIF reservoir (writes bf16 spike pairs) ----------------
__global__ void __launch_bounds__(512) lif_kernel(
    const float* __restrict__ x, const float* __restrict__ Win,
    const float* __restrict__ Wres, uint32_t* __restrict__ zh)
{
    const int b = blockIdx.x;
    const int r = threadIdx.x;
    const int warp = r >> 5, lane = r & 31;

    __shared__ float sWin[8][512];
    __shared__ float sx[8];
    __shared__ int   s_act[512];
    __shared__ int   s_in[512];
    __shared__ int   s_wcnt[16];

    #pragma unroll
    for (int i = 0; i < 8; i++) sWin[i][r] = Win[i * 512 + r];

    const float colsum = g_colsum[r];
    const float* xb = x + (size_t)b * 1024 * 8;
    uint32_t* zb = zh + (size_t)b * 1024 * 256;

    float v = 0.f, isyn = 0.f;
    int zprev = 0;

    for (int t = 0; t < 1024; t++) {
        unsigned bal = __ballot_sync(0xffffffffu, zprev);
        __syncthreads();
        if (lane == 0) s_wcnt[warp] = __popc(bal);
        if (r < 8) sx[r] = xb[t * 8 + r];
        __syncthreads();

        int na = 0, base_a = 0;
        #pragma unroll
        for (int w = 0; w < 16; w++) {
            int c = s_wcnt[w];
            na += c;
            if (w < warp) base_a += c;
        }
        int rank = __popc(bal & ((1u << lane) - 1u));
        if (zprev) s_act[base_a + rank] = r;
        else       s_in[warp * 32 - base_a + (lane - rank)] = r;
        __syncthreads();

        float cur = 0.f;
        #pragma unroll
        for (int i = 0; i < 8; i++) cur += sx[i] * sWin[i][r];

        float rec;
        if (na <= 256) {
            rec = 0.f;
            for (int j = 0; j < na; j++) rec += Wres[s_act[j] * 512 + r];
        } else {
            const int ni = 512 - na;
            float a0 = 0.f, a1 = 0.f, a2 = 0.f, a3 = 0.f;
            int j = 0;
            for (; j + 4 <= ni; j += 4) {
                a0 += Wres[s_in[j + 0] * 512 + r];
                a1 += Wres[s_in[j + 1] * 512 + r];
                a2 += Wres[s_in[j + 2] * 512 + r];
                a3 += Wres[s_in[j + 3] * 512 + r];
            }
            for (; j < ni; j++) a0 += Wres[s_in[j] * 512 + r];
            rec = colsum - ((a0 + a1) + (a2 + a3));
        }

        float total = cur + rec;
        float vdec = v + 0.004f * (isyn - v);
        float idec = isyn * 0.8f;
        int z = (vdec - 0.1f) > 0.f ? 1 : 0;
        v = z ? 0.f : vdec;
        isyn = idec + total;

        // pack pair (r even, r+1) as bf16x2 {1.0 or 0.0}
        int zn = __shfl_down_sync(0xffffffffu, z, 1);
        if (!(r & 1))
            zb[t * 256 + (r >> 1)] = (z ? 0x3f80u : 0u) | (zn ? 0x3f800000u : 0u);
        zprev = z;
    }
}

// ---------------- tf32 helpers (flash only) ----------------
__device__ __forceinline__ void split_tf32(float x, uint32_t& hi, uint32_t& lo) {
    uint32_t xb = __float_as_uint(x);
    hi = xb & 0xffffe000u;
    lo = __float_as_uint(x - __uint_as_float(hi));
}

__device__ __forceinline__ void mma_tf32(float* c, const uint32_t* a, const uint32_t* b) {
    asm volatile(
        "mma.sync.aligned.m16n8k8.row.col.f32.tf32.tf32.f32 "
        "{%0,%1,%2,%3},{%4,%5,%6,%7},{%8,%9},{%0,%1,%2,%3};\n"
        : "+f"(c[0]), "+f"(c[1]), "+f"(c[2]), "+f"(c[3])
        : "r"(a[0]), "r"(a[1]), "r"(a[2]), "r"(a[3]), "r"(b[0]), "r"(b[1]));
}

__device__ __forceinline__ void mma_bf16(float* c, const uint32_t* a, const uint32_t* b) {
    asm volatile(
        "mma.sync.aligned.m16n8k16.row.col.f32.bf16.bf16.f32 "
        "{%0,%1,%2,%3},{%4,%5,%6,%7},{%8,%9},{%0,%1,%2,%3};\n"
        : "+f"(c[0]), "+f"(c[1]), "+f"(c[2]), "+f"(c[3])
        : "r"(a[0]), "r"(a[1]), "r"(a[2]), "r"(a[3]), "r"(b[0]), "r"(b[1]));
}

__device__ __forceinline__ void cp_async16(uint32_t saddr, const void* gptr) {
    asm volatile("cp.async.ca.shared.global [%0], [%1], 16;\n" :: "r"(saddr), "l"(gptr));
}

// ---------------- bf16x3 tensor-core GEMM (pre-split operands) ----------------
// C[m][n] = sum_k A[m][k]*B[n][k] + bias[n]
// A,B given as packed bf16x2 (hi,lo) u32 arrays, pitch K/2. Al may be null (2-term).
// Outputs: fp32 C (nullable) and/or bf16 pair Ch/Cl (nullable), optional relu.
// Block tile 128x128, K-tile 32 elems (16 u32), 256 thr (8 warps 4x2), 2 CTAs/SM.
#define PA 20
#define MAT_U32 (128 * PA)            // 2560
#define STAGE_U32 (4 * MAT_U32)       // 10240
#define GEMM_SMEM_BYTES (2 * STAGE_U32 * 4)   // 81920

__global__ void __launch_bounds__(256, 2) gemm_bf16x3(
    const uint32_t* __restrict__ Ah, const uint32_t* __restrict__ Al,
    const uint32_t* __restrict__ Bh, const uint32_t* __restrict__ Bl,
    const float* __restrict__ bias,
    float* __restrict__ C, uint32_t* __restrict__ Ch, uint32_t* __restrict__ Cl,
    int M, int N, int K, int relu)
{
    extern __shared__ uint32_t smem_u[];
    const int KP   = K >> 1;
    const int tid  = threadIdx.x;
    const int lane = tid & 31;
    const int warp = tid >> 5;
    const int bm   = blockIdx.y << 7;
    const int bn   = blockIdx.x << 7;
    const int warpM = (warp >> 1) << 5;
    const int warpN = (warp & 1) << 6;
    const int g = lane >> 2;
    const int t = lane & 3;
    const bool hasAl = (Al != nullptr);

    const uint32_t sbase = (uint32_t)__cvta_generic_to_shared(smem_u);

    float acc[2][8][4];
    #pragma unroll
    for (int mi = 0; mi < 2; mi++)
        #pragma unroll
        for (int ni = 0; ni < 8; ni++)
            #pragma unroll
            for (int r = 0; r < 4; r++) acc[mi][ni][r] = 0.f;

    const int ntiles = K >> 5;

    auto issue = [&](int kt, int s) {
        uint32_t st = sbase + (uint32_t)(s * STAGE_U32) * 4u;
        #pragma unroll
        for (int i = 0; i < 2; i++) {
            int slot = tid + (i << 8);
            int row = slot >> 2, c4 = (slot & 3) << 2;
            size_t go = (size_t)row * KP + kt * 16 + c4;
            uint32_t so = (uint32_t)(row * PA + c4) * 4u;
            cp_async16(st + 0 * MAT_U32 * 4u + so, Ah + (size_t)bm * KP + go);
            if (hasAl)
                cp_async16(st + 1 * MAT_U32 * 4u + so, Al + (size_t)bm * KP + go);
            cp_async16(st + 2 * MAT_U32 * 4u + so, Bh + (size_t)bn * KP + go);
            cp_async16(st + 3 * MAT_U32 * 4u + so, Bl + (size_t)bn * KP + go);
        }
        asm volatile("cp.async.commit_group;\n");
    };

    issue(0, 0);
    if (ntiles > 1) issue(1, 1);

    for (int kt = 0; kt < ntiles; kt++) {
        const int s = kt & 1;
        if (kt + 2 < ntiles)
            asm volatile("cp.async.wait_group 1;\n" ::: "memory");
        else
            asm volatile("cp.async.wait_group 0;\n" ::: "memory");
        __syncthreads();

        const uint32_t* cs  = smem_u + s * STAGE_U32;
        const uint32_t* sAh = cs;
        const uint32_t* sAl = cs + 1 * MAT_U32;
        const uint32_t* sBh = cs + 2 * MAT_U32;
        const uint32_t* sBl = cs + 3 * MAT_U32;

        #pragma unroll
        for (int ch = 0; ch < 2; ch++) {
            const int c8 = (ch << 3) + t;

            uint32_t ah[2][4], alr[2][4];
            #pragma unroll
            for (int mi = 0; mi < 2; mi++) {
                const int r0 = warpM + (mi << 4);
                ah[mi][0] = sAh[(r0 + g) * PA + c8];
                ah[mi][1] = sAh[(r0 + 8 + g) * PA + c8];
                ah[mi][2] = sAh[(r0 + g) * PA + c8 + 4];
                ah[mi][3] = sAh[(r0 + 8 + g) * PA + c8 + 4];
                if (hasAl) {
                    alr[mi][0] = sAl[(r0 + g) * PA + c8];
                    alr[mi][1] = sAl[(r0 + 8 + g) * PA + c8];
                    alr[mi][2] = sAl[(r0 + g) * PA + c8 + 4];
                    alr[mi][3] = sAl[(r0 + 8 + g) * PA + c8 + 4];
                }
            }
            #pragma unroll
            for (int ni = 0; ni < 8; ni++) {
                const int c0 = warpN + (ni << 3) + g;
                uint32_t bh2[2], bl2[2];
                bh2[0] = sBh[c0 * PA + c8];
                bh2[1] = sBh[c0 * PA + c8 + 4];
                bl2[0] = sBl[c0 * PA + c8];
                bl2[1] = sBl[c0 * PA + c8 + 4];
                mma_bf16(acc[0][ni], ah[0], bh2);
                mma_bf16(acc[0][ni], ah[0], bl2);
                mma_bf16(acc[1][ni], ah[1], bh2);
                mma_bf16(acc[1][ni], ah[1], bl2);
                if (hasAl) {
                    mma_bf16(acc[0][ni], alr[0], bh2);
                    mma_bf16(acc[1][ni], alr[1], bh2);
                }
            }
        }

        __syncthreads();
        if (kt + 2 < ntiles) issue(kt + 2, s);
    }

    // epilogue
    const int cq = t << 1;
    #pragma unroll
    for (int ni = 0; ni < 8; ni++) {
        const int col = bn + warpN + (ni << 3) + cq;
        const float b0 = bias[col], b1 = bias[col + 1];
        #pragma unroll
        for (int mi = 0; mi < 2; mi++) {
            const int row0 = bm + warpM + (mi << 4) + g;
            float2 v0, v1;
            v0.x = acc[mi][ni][0] + b0; v0.y = acc[mi][ni][1] + b1;
            v1.x = acc[mi][ni][2] + b0; v1.y = acc[mi][ni][3] + b1;
            if (relu) {
                v0.x = fmaxf(v0.x, 0.f); v0.y = fmaxf(v0.y, 0.f);
                v1.x = fmaxf(v1.x, 0.f); v1.y = fmaxf(v1.y, 0.f);
            }
            if (C) {
                *(float2*)&C[(size_t)row0 * N + col] = v0;
                *(float2*)&C[(size_t)(row0 + 8) * N + col] = v1;
            }
            if (Ch) {
                const int NP = N >> 1;
                const int pc = col >> 1;
                uint32_t ph, pl;
                split2(v0.x, v0.y, ph, pl);
                Ch[(size_t)row0 * NP + pc] = ph;
                Cl[(size_t)row0 * NP + pc] = pl;
                split2(v1.x, v1.y, ph, pl);
                Ch[(size_t)(row0 + 8) * NP + pc] = ph;
                Cl[(size_t)(row0 + 8) * NP + pc] = pl;
            }
        }
    }
}

// ---------------- MMA flash attention (tf32x3; bf16 pair output) ----------------
__global__ void __launch_bounds__(128) flash_mma_kernel(
    const float* __restrict__ qkv,
    uint32_t* __restrict__ attnh, uint32_t* __restrict__ attnl)
{
    __shared__ float Ks[64][68];
    __shared__ float Vs[64][72];

    const int tid  = threadIdx.x;
    const int lane = tid & 31;
    const int w    = tid >> 5;
    const int g    = lane >> 2;
    const int t    = lane & 3;
    const int qb   = blockIdx.x;
    const int bh   = blockIdx.y;
    const int b    = bh >> 2, h = bh & 3;

    const float* base = qkv + (size_t)b * 1024 * 768;
    const float* qg = base + h * 64;
    const float* kg = base + 256 + h * 64;
    const float* vg = base + 512 + h * 64;

    const int wr = w * 16;
    const float SCALE = 0.125f;
    const float L2E   = 1.4426950408889634f;

    #pragma unroll
    for (int i = 0; i < 8; i++) {
        int idx = i * 128 + tid;
        int row = idx >> 4, c4 = (idx & 15) << 2;
        *(float4*)&Ks[row][c4] =
            *(const float4*)&qg[(size_t)(qb * 64 + row) * 768 + c4];
    }
    __syncthreads();

    uint32_t qh[8][4], ql[8][4];
    {
        const int r0 = wr + g;
        #pragma unroll
        for (int ks = 0; ks < 8; ks++) {
            const int k0 = ks << 3;
            split_tf32(Ks[r0][k0 + t],         qh[ks][0], ql[ks][0]);
            split_tf32(Ks[r0 + 8][k0 + t],     qh[ks][1], ql[ks][1]);
            split_tf32(Ks[r0][k0 + t + 4],     qh[ks][2], ql[ks][2]);
            split_tf32(Ks[r0 + 8][k0 + t + 4], qh[ks][3], ql[ks][3]);
        }
    }
    __syncthreads();

    float oacc[8][4];
    #pragma unroll
    for (int nt = 0; nt < 8; nt++)
        #pragma unroll
        for (int r = 0; r < 4; r++) oacc[nt][r] = 0.f;
    float m0 = -1e30f, m1 = -1e30f, l0 = 0.f, l1 = 0.f;

    for (int kb = 0; kb < 16; kb++) {
        #pragma unroll
        for (int i = 0; i < 8; i++) {
            int idx = i * 128 + tid;
            int row = idx >> 4, c4 = (idx & 15) << 2;
            size_t goff = (size_t)(kb * 64 + row) * 768 + c4;
            *(float4*)&Ks[row][c4] = *(const float4*)&kg[goff];
            *(float4*)&Vs[row][c4] = *(const float4*)&vg[goff];
        }
        __syncthreads();

        float sc[8][4];
        #pragma unroll
        for (int nt = 0; nt < 8; nt++)
            #pragma unroll
            for (int r = 0; r < 4; r++) sc[nt][r] = 0.f;

        #pragma unroll
        for (int ks = 0; ks < 8; ks++) {
            const int k0 = ks << 3;
            #pragma unroll
            for (int nt = 0; nt < 8; nt++) {
                uint32_t kh2[2], kl2[2];
                split_tf32(Ks[(nt << 3) + g][k0 + t],     kh2[0], kl2[0]);
                split_tf32(Ks[(nt << 3) + g][k0 + t + 4], kh2[1], kl2[1]);
                mma_tf32(sc[nt], qh[ks], kh2);
                mma_tf32(sc[nt], qh[ks], kl2);
                mma_tf32(sc[nt], ql[ks], kh2);
            }
        }

        float mb0 = -1e30f, mb1 = -1e30f;
        #pragma unroll
        for (int nt = 0; nt < 8; nt++) {
            sc[nt][0] *= SCALE; sc[nt][1] *= SCALE;
            sc[nt][2] *= SCALE; sc[nt][3] *= SCALE;
            mb0 = fmaxf(mb0, fmaxf(sc[nt][0], sc[nt][1]));
            mb1 = fmaxf(mb1, fmaxf(sc[nt][2], sc[nt][3]));
        }
        #pragma unroll
        for (int off = 1; off <= 2; off <<= 1) {
            mb0 = fmaxf(mb0, __shfl_xor_sync(0xffffffffu, mb0, off));
            mb1 = fmaxf(mb1, __shfl_xor_sync(0xffffffffu, mb1, off));
        }
        const float mn0 = fmaxf(m0, mb0);
        const float mn1 = fmaxf(m1, mb1);
        const float c0 = exp2f((m0 - mn0) * L2E);
        const float c1 = exp2f((m1 - mn1) * L2E);
        l0 *= c0; l1 *= c1;
        #pragma unroll
        for (int nt = 0; nt < 8; nt++) {
            oacc[nt][0] *= c0; oacc[nt][1] *= c0;
            oacc[nt][2] *= c1; oacc[nt][3] *= c1;
        }
        #pragma unroll
        for (int nt = 0; nt < 8; nt++) {
            sc[nt][0] = exp2f((sc[nt][0] - mn0) * L2E);
            sc[nt][1] = exp2f((sc[nt][1] - mn0) * L2E);
            sc[nt][2] = exp2f((sc[nt][2] - mn1) * L2E);
            sc[nt][3] = exp2f((sc[nt][3] - mn1) * L2E);
            l0 += sc[nt][0] + sc[nt][1];
            l1 += sc[nt][2] + sc[nt][3];
        }
        m0 = mn0; m1 = mn1;

        __syncthreads();
        #pragma unroll
        for (int nt = 0; nt < 8; nt++) {
            const int col = (nt << 3) + (t << 1);
            *(float2*)&Ks[wr + g][col]     = make_float2(sc[nt][0], sc[nt][1]);
            *(float2*)&Ks[wr + g + 8][col] = make_float2(sc[nt][2], sc[nt][3]);
        }
        __syncwarp();

        #pragma unroll
        for (int ks = 0; ks < 8; ks++) {
            const int k0 = ks << 3;
            uint32_t ah2[4], al2[4];
            split_tf32(Ks[wr + g][k0 + t],         ah2[0], al2[0]);
            split_tf32(Ks[wr + g + 8][k0 + t],     ah2[1], al2[1]);
            split_tf32(Ks[wr + g][k0 + t + 4],     ah2[2], al2[2]);
            split_tf32(Ks[wr + g + 8][k0 + t + 4], ah2[3], al2[3]);
            #pragma unroll
            for (int nt = 0; nt < 8; nt++) {
                uint32_t vh2[2], vl2[2];
                split_tf32(Vs[k0 + t][(nt << 3) + g],     vh2[0], vl2[0]);
                split_tf32(Vs[k0 + t + 4][(nt << 3) + g], vh2[1], vl2[1]);
                mma_tf32(oacc[nt], ah2, vh2);
                mma_tf32(oacc[nt], ah2, vl2);
                mma_tf32(oacc[nt], al2, vh2);
            }
        }
        __syncthreads();
    }

    #pragma unroll
    for (int off = 1; off <= 2; off <<= 1) {
        l0 += __shfl_xor_sync(0xffffffffu, l0, off);
        l1 += __shfl_xor_sync(0xffffffffu, l1, off);
    }
    const float inv0 = 1.f / l0;
    const float inv1 = 1.f / l1;

    const int row0 = b * 1024 + qb * 64 + wr + g;
    #pragma unroll
    for (int nt = 0; nt < 8; nt++) {
        const int pc = h * 32 + (nt << 2) + t;   // pair col in 128-wide row
        uint32_t ph, pl;
        split2(oacc[nt][0] * inv0, oacc[nt][1] * inv0, ph, pl);
        attnh[(size_t)row0 * 128 + pc] = ph;
        attnl[(size_t)row0 * 128 + pc] = pl;
        split2(oacc[nt][2] * inv1, oacc[nt][3] * inv1, ph, pl);
        attnh[(size_t)(row0 + 8) * 128 + pc] = ph;
        attnl[(size_t)(row0 + 8) * 128 + pc] = pl;
    }
}

// ---------------- layernorm(xa+xb)*g+b, fp32 out + optional bf16 pair out ------
__global__ void __launch_bounds__(256) ln_kernel(
    const float* __restrict__ xa, const float* __restrict__ xb,
    const float* __restrict__ g, const float* __restrict__ bt,
    float* __restrict__ out, uint32_t* __restrict__ oh, uint32_t* __restrict__ ol)
{
    const int warp = threadIdx.x >> 5, lane = threadIdx.x & 31;
    const size_t row = (size_t)blockIdx.x * 8 + warp;
    const float* pa = xa + row * 256;
    const float* pb = xb + row * 256;

    float v[8];
    float s = 0.f;
    #pragma unroll
    for (int i = 0; i < 8; i++) {
        v[i] = pa[lane + 32 * i] + pb[lane + 32 * i];
        s += v[i];
    }
    #pragma unroll
    for (int off = 16; off > 0; off >>= 1) s += __shfl_xor_sync(0xffffffffu, s, off);
    float mean = s * (1.f / 256.f);

    float vs = 0.f;
    #pragma unroll
    for (int i = 0; i < 8; i++) { float d = v[i] - mean; vs += d * d; }
    #pragma unroll
    for (int off = 16; off > 0; off >>= 1) vs += __shfl_xor_sync(0xffffffffu, vs, off);
    float inv = 1.f / sqrtf(vs * (1.f / 256.f) + 1e-5f);

    #pragma unroll
    for (int i = 0; i < 8; i++) {
        int c = lane + 32 * i;
        float o = (v[i] - mean) * inv * g[c] + bt[c];
        out[row * 256 + c] = o;
        float on = __shfl_down_sync(0xffffffffu, o, 1);
        if (oh && !(lane & 1)) {
            uint32_t ph, pl;
            split2(o, on, ph, pl);
            oh[row * 128 + (c >> 1)] = ph;
            ol[row * 128 + (c >> 1)] = pl;
        }
    }
}

// -------------------------------- launch ---------------------------------------
extern "C" void kernel_launch(void* const* d_in, const int* in_sizes, int n_in,
                              void* d_out, int out_size)
{
    const float* x     = (const float*)d_in[0];
    const float* Win   = (const float*)d_in[1];
    const float* Wres  = (const float*)d_in[2];
    const float* Wread = (const float*)d_in[3];
    const float* bread = (const float*)d_in[4];
    const float* Wqkv  = (const float*)d_in[5];
    const float* bqkv  = (const float*)d_in[6];
    const float* Wo    = (const float*)d_in[7];
    const float* bo    = (const float*)d_in[8];
    const float* g1    = (const float*)d_in[9];
    const float* b1    = (const float*)d_in[10];
    const float* g2    = (const float*)d_in[11];
    const float* b2    = (const float*)d_in[12];
    const float* W1    = (const float*)d_in[13];
    const float* c1    = (const float*)d_in[14];
    const float* W2    = (const float*)d_in[15];
    const float* c2    = (const float*)d_in[16];
    float* out = (float*)d_out;

    float *qkv, *h, *tmp;
    uint32_t *zh, *hh, *hl, *ath, *atl, *ffh, *ffl;
    uint32_t *wrh, *wrl, *wqh, *wql, *woh, *wol, *w1h, *w1l, *w2h, *w2l;
    cudaGetSymbolAddress((void**)&qkv, g_qkv);
    cudaGetSymbolAddress((void**)&h,   g_h);
    cudaGetSymbolAddress((void**)&tmp, g_tmp);
    cudaGetSymbolAddress((void**)&zh,  g_zh);
    cudaGetSymbolAddress((void**)&hh,  g_hh);
    cudaGetSymbolAddress((void**)&hl,  g_hl);
    cudaGetSymbolAddress((void**)&ath, g_attnh);
    cudaGetSymbolAddress((void**)&atl, g_attnl);
    cudaGetSymbolAddress((void**)&ffh, g_ffh);
    cudaGetSymbolAddress((void**)&ffl, g_ffl);
    cudaGetSymbolAddress((void**)&wrh, g_wrh);
    cudaGetSymbolAddress((void**)&wrl, g_wrl);
    cudaGetSymbolAddress((void**)&wqh, g_wqh);
    cudaGetSymbolAddress((void**)&wql, g_wql);
    cudaGetSymbolAddress((void**)&woh, g_woh);
    cudaGetSymbolAddress((void**)&wol, g_wol);
    cudaGetSymbolAddress((void**)&w1h, g_w1h);
    cudaGetSymbolAddress((void**)&w1l, g_w1l);
    cudaGetSymbolAddress((void**)&w2h, g_w2h);
    cudaGetSymbolAddress((void**)&w2l, g_w2l);

    cudaFuncSetAttribute(gemm_bf16x3,
                         cudaFuncAttributeMaxDynamicSharedMemorySize,
                         GEMM_SMEM_BYTES);

    const int M = 32768;
    const int SB = GEMM_SMEM_BYTES;

    // weight splits
    wsplit_kernel<<<256,  256>>>(Wread, wrh, wrl, 256 * 256);
    wsplit_kernel<<<768,  256>>>(Wqkv,  wqh, wql, 2 * 768 * 128);
    wsplit_kernel<<<256,  256>>>(Wo,    woh, wol, 2 * 256 * 128);
    wsplit_kernel<<<1024, 256>>>(W1,    w1h, w1l, 2 * 1024 * 128);
    wsplit_kernel<<<1024, 256>>>(W2,    w2h, w2l, 2 * 256 * 512);

    colsum_kernel<<<1, 512>>>(Wres);
    lif_kernel<<<32, 512>>>(x, Win, Wres, zh);

    // h = z @ Wread^T + bread   (z exact in bf16 -> 2-term)
    gemm_bf16x3<<<dim3(2, 256), 256, SB>>>(zh, nullptr, wrh, wrl, bread,
                                           h, hh, hl, M, 256, 512, 0);

    for (int l = 0; l < 2; l++) {
        // qkv = h @ Wqkv^T + bqkv (fp32 out for flash)
        gemm_bf16x3<<<dim3(6, 256), 256, SB>>>(hh, hl,
            wqh + (size_t)l * 768 * 128, wql + (size_t)l * 768 * 128,
            bqkv + l * 768, qkv, nullptr, nullptr, M, 768, 256, 0);
        // attention -> bf16 pair out
        flash_mma_kernel<<<dim3(16, 128), 128>>>(qkv, ath, atl);
        // tmp = attn @ Wo^T + bo (fp32 out for LN)
        gemm_bf16x3<<<dim3(2, 256), 256, SB>>>(ath, atl,
            woh + (size_t)l * 256 * 128, wol + (size_t)l * 256 * 128,
            bo + l * 256, tmp, nullptr, nullptr, M, 256, 256, 0);
        // h = LN(h + tmp) (+ bf16 pairs)
        ln_kernel<<<4096, 256>>>(h, tmp, g1 + l * 256, b1 + l * 256, h, hh, hl);
        // ff = relu(h @ W1^T + c1) -> bf16 pair only
        gemm_bf16x3<<<dim3(8, 256), 256, SB>>>(hh, hl,
            w1h + (size_t)l * 1024 * 128, w1l + (size_t)l * 1024 * 128,
            c1 + l * 1024, nullptr, ffh, ffl, M, 1024, 256, 1);
        // tmp = ff @ W2^T + c2 (fp32)
        gemm_bf16x3<<<dim3(2, 256), 256, SB>>>(ffh, ffl,
            w2h + (size_t)l * 256 * 512, w2l + (size_t)l * 256 * 512,
            c2 + l * 256, tmp, nullptr, nullptr, M, 256, 1024, 0);
        // out/h = LN(h + tmp)
        ln_kernel<<<4096, 256>>>(h, tmp, g2 + l * 256, b2 + l * 256,
                                 (l == 1) ? out : h,
                                 (l == 1) ? nullptr : hh,
                                 (l == 1) ? nullptr : hl);
    }
}

// round 6
// speedup vs baseline: 2.7208x; 1.0864x over previous
#include <cuda_runtime.h>
#include <cstdint>

// ---------------- scratch (device globals; no allocation APIs) ----------------
__device__ float    g_qkv [32768u*768u];     // fp32 qkv (flash input), 96MB
__device__ float    g_h   [32768u*256u];     // fp32 hidden (residual), 32MB
__device__ float    g_tmp [32768u*256u];     // fp32 proj/ff2 out, 32MB
__device__ float    g_colsum[512];

// bf16x2 packed (hi,lo) operand arrays; u32 = {odd<<16 | even}
__device__ uint32_t g_zh   [32u*1024u*256u]; // spikes bf16 (exact), 32MB
__device__ uint32_t g_hh   [32768u*128u], g_hl   [32768u*128u];
__device__ uint32_t g_attnh[32768u*128u], g_attnl[32768u*128u];
__device__ uint32_t g_ffh  [32768u*512u], g_ffl  [32768u*512u];
__device__ uint32_t g_wrh  [256u*256u],   g_wrl  [256u*256u];
__device__ uint32_t g_wqh  [2u*768u*128u],g_wql  [2u*768u*128u];
__device__ uint32_t g_woh  [2u*256u*128u],g_wol  [2u*256u*128u];
__device__ uint32_t g_w1h  [2u*1024u*128u],g_w1l [2u*1024u*128u];
__device__ uint32_t g_w2h  [2u*256u*512u],g_w2l  [2u*256u*512u];

// ---------------- bf16 split helpers ----------------
__device__ __forceinline__ void split2(float e, float o, uint32_t& hi, uint32_t& lo) {
    asm("cvt.rn.bf16x2.f32 %0, %1, %2;" : "=r"(hi) : "f"(o), "f"(e));
    float he = __uint_as_float(hi << 16);
    float ho = __uint_as_float(hi & 0xffff0000u);
    asm("cvt.rn.bf16x2.f32 %0, %1, %2;" : "=r"(lo) : "f"(o - ho), "f"(e - he));
}

__global__ void wsplit_kernel(const float* __restrict__ src,
                              uint32_t* __restrict__ h, uint32_t* __restrict__ l,
                              int npairs) {
    int i = blockIdx.x * 256 + threadIdx.x;
    if (i < npairs) {
        float2 v = *(const float2*)(src + 2 * i);
        split2(v.x, v.y, h[i], l[i]);
    }
}

// ---------------- column sums of Wres ----------------
__global__ void colsum_kernel(const float* __restrict__ Wres) {
    int r = threadIdx.x;
    float s0 = 0.f, s1 = 0.f, s2 = 0.f, s3 = 0.f;
    #pragma unroll 4
    for (int rr = 0; rr < 512; rr += 4) {
        s0 += Wres[(rr + 0) * 512 + r];
        s1 += Wres[(rr + 1) * 512 + r];
        s2 += Wres[(rr + 2) * 512 + r];
        s3 += Wres[(rr + 3) * 512 + r];
    }
    g_colsum[r] = (s0 + s1) + (s2 + s3);
}

// ---------------- LIF reservoir (writes bf16 spike pairs) ----------------
__global__ void __launch_bounds__(512) lif_kernel(
    const float* __restrict__ x, const float* __restrict__ Win,
    const float* __restrict__ Wres, uint32_t* __restrict__ zh)
{
    const int b = blockIdx.x;
    const int r = threadIdx.x;
    const int warp = r >> 5, lane = r & 31;

    __shared__ float sWin[8][512];
    __shared__ float sx[8];
    __shared__ int   s_act[512];
    __shared__ int   s_in[512];
    __shared__ int   s_wcnt[16];

    #pragma unroll
    for (int i = 0; i < 8; i++) sWin[i][r] = Win[i * 512 + r];

    const float colsum = g_colsum[r];
    const float* xb = x + (size_t)b * 1024 * 8;
    uint32_t* zb = zh + (size_t)b * 1024 * 256;

    float v = 0.f, isyn = 0.f;
    int zprev = 0;

    for (int t = 0; t < 1024; t++) {
        unsigned bal = __ballot_sync(0xffffffffu, zprev);
        __syncthreads();
        if (lane == 0) s_wcnt[warp] = __popc(bal);
        if (r < 8) sx[r] = xb[t * 8 + r];
        __syncthreads();

        int na = 0, base_a = 0;
        #pragma unroll
        for (int w = 0; w < 16; w++) {
            int c = s_wcnt[w];
            na += c;
            if (w < warp) base_a += c;
        }
        int rank = __popc(bal & ((1u << lane) - 1u));
        if (zprev) s_act[base_a + rank] = r;
        else       s_in[warp * 32 - base_a + (lane - rank)] = r;
        __syncthreads();

        float cur = 0.f;
        #pragma unroll
        for (int i = 0; i < 8; i++) cur += sx[i] * sWin[i][r];

        float rec;
        if (na <= 256) {
            rec = 0.f;
            for (int j = 0; j < na; j++) rec += Wres[s_act[j] * 512 + r];
        } else {
            const int ni = 512 - na;
            float a0 = 0.f, a1 = 0.f, a2 = 0.f, a3 = 0.f;
            int j = 0;
            for (; j + 4 <= ni; j += 4) {
                a0 += Wres[s_in[j + 0] * 512 + r];
                a1 += Wres[s_in[j + 1] * 512 + r];
                a2 += Wres[s_in[j + 2] * 512 + r];
                a3 += Wres[s_in[j + 3] * 512 + r];
            }
            for (; j < ni; j++) a0 += Wres[s_in[j] * 512 + r];
            rec = colsum - ((a0 + a1) + (a2 + a3));
        }

        float total = cur + rec;
        float vdec = v + 0.004f * (isyn - v);
        float idec = isyn * 0.8f;
        int z = (vdec - 0.1f) > 0.f ? 1 : 0;
        v = z ? 0.f : vdec;
        isyn = idec + total;

        int zn = __shfl_down_sync(0xffffffffu, z, 1);
        if (!(r & 1))
            zb[t * 256 + (r >> 1)] = (z ? 0x3f80u : 0u) | (zn ? 0x3f800000u : 0u);
        zprev = z;
    }
}

// ---------------- MMA helpers ----------------
__device__ __forceinline__ void mma_bf16(float* c, const uint32_t* a, const uint32_t* b) {
    asm volatile(
        "mma.sync.aligned.m16n8k16.row.col.f32.bf16.bf16.f32 "
        "{%0,%1,%2,%3},{%4,%5,%6,%7},{%8,%9},{%0,%1,%2,%3};\n"
        : "+f"(c[0]), "+f"(c[1]), "+f"(c[2]), "+f"(c[3])
        : "r"(a[0]), "r"(a[1]), "r"(a[2]), "r"(a[3]), "r"(b[0]), "r"(b[1]));
}

__device__ __forceinline__ void cp_async16(uint32_t saddr, const void* gptr) {
    asm volatile("cp.async.ca.shared.global [%0], [%1], 16;\n" :: "r"(saddr), "l"(gptr));
}

// ---------------- bf16x3 tensor-core GEMM (pre-split operands) ----------------
#define PA 20
#define MAT_U32 (128 * PA)
#define STAGE_U32 (4 * MAT_U32)
#define GEMM_SMEM_BYTES (2 * STAGE_U32 * 4)

__global__ void __launch_bounds__(256, 2) gemm_bf16x3(
    const uint32_t* __restrict__ Ah, const uint32_t* __restrict__ Al,
    const uint32_t* __restrict__ Bh, const uint32_t* __restrict__ Bl,
    const float* __restrict__ bias,
    float* __restrict__ C, uint32_t* __restrict__ Ch, uint32_t* __restrict__ Cl,
    int M, int N, int K, int relu)
{
    extern __shared__ uint32_t smem_u[];
    const int KP   = K >> 1;
    const int tid  = threadIdx.x;
    const int lane = tid & 31;
    const int warp = tid >> 5;
    const int bm   = blockIdx.y << 7;
    const int bn   = blockIdx.x << 7;
    const int warpM = (warp >> 1) << 5;
    const int warpN = (warp & 1) << 6;
    const int g = lane >> 2;
    const int t = lane & 3;
    const bool hasAl = (Al != nullptr);

    const uint32_t sbase = (uint32_t)__cvta_generic_to_shared(smem_u);

    float acc[2][8][4];
    #pragma unroll
    for (int mi = 0; mi < 2; mi++)
        #pragma unroll
        for (int ni = 0; ni < 8; ni++)
            #pragma unroll
            for (int r = 0; r < 4; r++) acc[mi][ni][r] = 0.f;

    const int ntiles = K >> 5;

    auto issue = [&](int kt, int s) {
        uint32_t st = sbase + (uint32_t)(s * STAGE_U32) * 4u;
        #pragma unroll
        for (int i = 0; i < 2; i++) {
            int slot = tid + (i << 8);
            int row = slot >> 2, c4 = (slot & 3) << 2;
            size_t go = (size_t)row * KP + kt * 16 + c4;
            uint32_t so = (uint32_t)(row * PA + c4) * 4u;
            cp_async16(st + 0 * MAT_U32 * 4u + so, Ah + (size_t)bm * KP + go);
            if (hasAl)
                cp_async16(st + 1 * MAT_U32 * 4u + so, Al + (size_t)bm * KP + go);
            cp_async16(st + 2 * MAT_U32 * 4u + so, Bh + (size_t)bn * KP + go);
            cp_async16(st + 3 * MAT_U32 * 4u + so, Bl + (size_t)bn * KP + go);
        }
        asm volatile("cp.async.commit_group;\n");
    };

    issue(0, 0);
    if (ntiles > 1) issue(1, 1);

    for (int kt = 0; kt < ntiles; kt++) {
        const int s = kt & 1;
        if (kt + 2 < ntiles)
            asm volatile("cp.async.wait_group 1;\n" ::: "memory");
        else
            asm volatile("cp.async.wait_group 0;\n" ::: "memory");
        __syncthreads();

        const uint32_t* cs  = smem_u + s * STAGE_U32;
        const uint32_t* sAh = cs;
        const uint32_t* sAl = cs + 1 * MAT_U32;
        const uint32_t* sBh = cs + 2 * MAT_U32;
        const uint32_t* sBl = cs + 3 * MAT_U32;

        #pragma unroll
        for (int ch = 0; ch < 2; ch++) {
            const int c8 = (ch << 3) + t;

            uint32_t ah[2][4], alr[2][4];
            #pragma unroll
            for (int mi = 0; mi < 2; mi++) {
                const int r0 = warpM + (mi << 4);
                ah[mi][0] = sAh[(r0 + g) * PA + c8];
                ah[mi][1] = sAh[(r0 + 8 + g) * PA + c8];
                ah[mi][2] = sAh[(r0 + g) * PA + c8 + 4];
                ah[mi][3] = sAh[(r0 + 8 + g) * PA + c8 + 4];
                if (hasAl) {
                    alr[mi][0] = sAl[(r0 + g) * PA + c8];
                    alr[mi][1] = sAl[(r0 + 8 + g) * PA + c8];
                    alr[mi][2] = sAl[(r0 + g) * PA + c8 + 4];
                    alr[mi][3] = sAl[(r0 + 8 + g) * PA + c8 + 4];
                }
            }
            #pragma unroll
            for (int ni = 0; ni < 8; ni++) {
                const int c0 = warpN + (ni << 3) + g;
                uint32_t bh2[2], bl2[2];
                bh2[0] = sBh[c0 * PA + c8];
                bh2[1] = sBh[c0 * PA + c8 + 4];
                bl2[0] = sBl[c0 * PA + c8];
                bl2[1] = sBl[c0 * PA + c8 + 4];
                mma_bf16(acc[0][ni], ah[0], bh2);
                mma_bf16(acc[0][ni], ah[0], bl2);
                mma_bf16(acc[1][ni], ah[1], bh2);
                mma_bf16(acc[1][ni], ah[1], bl2);
                if (hasAl) {
                    mma_bf16(acc[0][ni], alr[0], bh2);
                    mma_bf16(acc[1][ni], alr[1], bh2);
                }
            }
        }

        __syncthreads();
        if (kt + 2 < ntiles) issue(kt + 2, s);
    }

    const int cq = t << 1;
    #pragma unroll
    for (int ni = 0; ni < 8; ni++) {
        const int col = bn + warpN + (ni << 3) + cq;
        const float b0 = bias[col], b1 = bias[col + 1];
        #pragma unroll
        for (int mi = 0; mi < 2; mi++) {
            const int row0 = bm + warpM + (mi << 4) + g;
            float2 v0, v1;
            v0.x = acc[mi][ni][0] + b0; v0.y = acc[mi][ni][1] + b1;
            v1.x = acc[mi][ni][2] + b0; v1.y = acc[mi][ni][3] + b1;
            if (relu) {
                v0.x = fmaxf(v0.x, 0.f); v0.y = fmaxf(v0.y, 0.f);
                v1.x = fmaxf(v1.x, 0.f); v1.y = fmaxf(v1.y, 0.f);
            }
            if (C) {
                *(float2*)&C[(size_t)row0 * N + col] = v0;
                *(float2*)&C[(size_t)(row0 + 8) * N + col] = v1;
            }
            if (Ch) {
                const int NP = N >> 1;
                const int pc = col >> 1;
                uint32_t ph, pl;
                split2(v0.x, v0.y, ph, pl);
                Ch[(size_t)row0 * NP + pc] = ph;
                Cl[(size_t)row0 * NP + pc] = pl;
                split2(v1.x, v1.y, ph, pl);
                Ch[(size_t)(row0 + 8) * NP + pc] = ph;
                Cl[(size_t)(row0 + 8) * NP + pc] = pl;
            }
        }
    }
}

// ---------------- bf16x3 MMA flash attention ----------------
// CTA: 64 q-rows x (b,h); 4 warps x 16 rows; key tiles of 64.
// K/V converted global->SMEM bf16 (hi,lo) pairs once per tile;
// P packed at softmax output. All MMAs m16n8k16 bf16, 3-term.
// SMEM: KPh/KPl [64][36] (aliased as P) + VPh/VPl [32][68] = 35840 B.
__global__ void __launch_bounds__(128) flash_mma_kernel(
    const float* __restrict__ qkv,
    uint32_t* __restrict__ attnh, uint32_t* __restrict__ attnl)
{
    __shared__ uint32_t S[8960];
    uint32_t* KPh = S;            // [64][36]  key x d-pair
    uint32_t* KPl = S + 2304;
    uint32_t* VPh = S + 4608;     // [32][68]  k-pair x d
    uint32_t* VPl = S + 6784;
    float* QsF = (float*)S;       // [64][68] fp32 Q staging (pre-loop only)

    const int tid  = threadIdx.x;
    const int lane = tid & 31;
    const int w    = tid >> 5;
    const int g    = lane >> 2;
    const int t    = lane & 3;
    const int qb   = blockIdx.x;      // 0..15
    const int bh   = blockIdx.y;      // 0..127
    const int b    = bh >> 2, h = bh & 3;

    const float* base = qkv + (size_t)b * 1024 * 768;
    const float* qg = base + h * 64;
    const float* kg = base + 256 + h * 64;
    const float* vg = base + 512 + h * 64;

    const int wr = w * 16;
    const float SCALE = 0.125f;
    const float L2E   = 1.4426950408889634f;

    // ---- stage Q fp32, split into bf16 fragment registers ----
    #pragma unroll
    for (int i = 0; i < 8; i++) {
        int idx = i * 128 + tid;
        int row = idx >> 4, c4 = (idx & 15) << 2;
        *(float4*)&QsF[row * 68 + c4] =
            *(const float4*)&qg[(size_t)(qb * 64 + row) * 768 + c4];
    }
    __syncthreads();

    uint32_t qh[4][4], ql[4][4];
    #pragma unroll
    for (int c = 0; c < 4; c++) {
        const int d0 = c * 16 + 2 * t;
        const float* r0 = &QsF[(wr + g) * 68];
        const float* r1 = &QsF[(wr + g + 8) * 68];
        split2(r0[d0],     r0[d0 + 1],     qh[c][0], ql[c][0]);
        split2(r1[d0],     r1[d0 + 1],     qh[c][1], ql[c][1]);
        split2(r0[d0 + 8], r0[d0 + 9],     qh[c][2], ql[c][2]);
        split2(r1[d0 + 8], r1[d0 + 9],     qh[c][3], ql[c][3]);
    }
    __syncthreads();   // Q staging consumed before K/V conversions overwrite S

    float oacc[8][4];
    #pragma unroll
    for (int nt = 0; nt < 8; nt++)
        #pragma unroll
        for (int r = 0; r < 4; r++) oacc[nt][r] = 0.f;
    float m0 = -1e30f, m1 = -1e30f, l0 = 0.f, l1 = 0.f;

    for (int kb = 0; kb < 16; kb++) {
        // ---- convert K tile: global fp32 -> (hi,lo) pairs along d ----
        #pragma unroll
        for (int i = 0; i < 16; i++) {
            const int row = (i << 2) + w;      // 0..63
            float2 kv = *(const float2*)&kg[(size_t)(kb * 64 + row) * 768 + 2 * lane];
            split2(kv.x, kv.y, KPh[row * 36 + lane], KPl[row * 36 + lane]);
        }
        // ---- convert V tile: pairs along key index ----
        #pragma unroll
        for (int i = 0; i < 16; i++) {
            const int idx = i * 128 + tid;
            const int d = idx & 63, k2 = idx >> 6;    // k2 0..31
            const size_t go = (size_t)(kb * 64 + 2 * k2) * 768 + d;
            split2(vg[go], vg[go + 768], VPh[k2 * 68 + d], VPl[k2 * 68 + d]);
        }
        __syncthreads();

        // ---- QK^T (bf16x3) ----
        float sc[8][4];
        #pragma unroll
        for (int nt = 0; nt < 8; nt++)
            #pragma unroll
            for (int r = 0; r < 4; r++) sc[nt][r] = 0.f;

        #pragma unroll
        for (int c = 0; c < 4; c++) {
            const int c8 = c * 8 + t;
            #pragma unroll
            for (int nt = 0; nt < 8; nt++) {
                const uint32_t* kr = &KPh[(nt * 8 + g) * 36];
                const uint32_t* kl = &KPl[(nt * 8 + g) * 36];
                uint32_t bh2[2] = { kr[c8], kr[c8 + 4] };
                uint32_t bl2[2] = { kl[c8], kl[c8 + 4] };
                mma_bf16(sc[nt], qh[c], bh2);
                mma_bf16(sc[nt], qh[c], bl2);
                mma_bf16(sc[nt], ql[c], bh2);
            }
        }

        // ---- online softmax ----
        float mb0 = -1e30f, mb1 = -1e30f;
        #pragma unroll
        for (int nt = 0; nt < 8; nt++) {
            sc[nt][0] *= SCALE; sc[nt][1] *= SCALE;
            sc[nt][2] *= SCALE; sc[nt][3] *= SCALE;
            mb0 = fmaxf(mb0, fmaxf(sc[nt][0], sc[nt][1]));
            mb1 = fmaxf(mb1, fmaxf(sc[nt][2], sc[nt][3]));
        }
        #pragma unroll
        for (int off = 1; off <= 2; off <<= 1) {
            mb0 = fmaxf(mb0, __shfl_xor_sync(0xffffffffu, mb0, off));
            mb1 = fmaxf(mb1, __shfl_xor_sync(0xffffffffu, mb1, off));
        }
        const float mn0 = fmaxf(m0, mb0);
        const float mn1 = fmaxf(m1, mb1);
        const float c0 = exp2f((m0 - mn0) * L2E);
        const float c1 = exp2f((m1 - mn1) * L2E);
        l0 *= c0; l1 *= c1;
        #pragma unroll
        for (int nt = 0; nt < 8; nt++) {
            oacc[nt][0] *= c0; oacc[nt][1] *= c0;
            oacc[nt][2] *= c1; oacc[nt][3] *= c1;
        }
        #pragma unroll
        for (int nt = 0; nt < 8; nt++) {
            sc[nt][0] = exp2f((sc[nt][0] - mn0) * L2E);
            sc[nt][1] = exp2f((sc[nt][1] - mn0) * L2E);
            sc[nt][2] = exp2f((sc[nt][2] - mn1) * L2E);
            sc[nt][3] = exp2f((sc[nt][3] - mn1) * L2E);
            l0 += sc[nt][0] + sc[nt][1];
            l1 += sc[nt][2] + sc[nt][3];
        }
        m0 = mn0; m1 = mn1;

        // ---- pack P into (hi,lo) pairs, aliasing K pair region ----
        __syncthreads();   // all QK reads of KPh/KPl complete
        uint32_t* Ph = KPh;
        uint32_t* Pl = KPl;
        #pragma unroll
        for (int nt = 0; nt < 8; nt++) {
            const int pc = nt * 4 + t;
            split2(sc[nt][0], sc[nt][1], Ph[(wr + g) * 36 + pc], Pl[(wr + g) * 36 + pc]);
            split2(sc[nt][2], sc[nt][3], Ph[(wr + g + 8) * 36 + pc], Pl[(wr + g + 8) * 36 + pc]);
        }
        __syncwarp();      // each warp reads back only its own 16 rows

        // ---- P @ V (bf16x3) ----
        #pragma unroll
        for (int c = 0; c < 4; c++) {
            const int c8 = c * 8 + t;
            uint32_t ah2[4], al2[4];
            ah2[0] = Ph[(wr + g) * 36 + c8];
            ah2[1] = Ph[(wr + g + 8) * 36 + c8];
            ah2[2] = Ph[(wr + g) * 36 + c8 + 4];
            ah2[3] = Ph[(wr + g + 8) * 36 + c8 + 4];
            al2[0] = Pl[(wr + g) * 36 + c8];
            al2[1] = Pl[(wr + g + 8) * 36 + c8];
            al2[2] = Pl[(wr + g) * 36 + c8 + 4];
            al2[3] = Pl[(wr + g + 8) * 36 + c8 + 4];
            #pragma unroll
            for (int nt = 0; nt < 8; nt++) {
                const int vc = nt * 8 + g;
                uint32_t bh2[2] = { VPh[(c8) * 68 + vc], VPh[(c8 + 4) * 68 + vc] };
                uint32_t bl2[2] = { VPl[(c8) * 68 + vc], VPl[(c8 + 4) * 68 + vc] };
                mma_bf16(oacc[nt], ah2, bh2);
                mma_bf16(oacc[nt], ah2, bl2);
                mma_bf16(oacc[nt], al2, bh2);
            }
        }
        __syncthreads();   // PV reads done before next tile's conversions
    }

    #pragma unroll
    for (int off = 1; off <= 2; off <<= 1) {
        l0 += __shfl_xor_sync(0xffffffffu, l0, off);
        l1 += __shfl_xor_sync(0xffffffffu, l1, off);
    }
    const float inv0 = 1.f / l0;
    const float inv1 = 1.f / l1;

    const int row0 = b * 1024 + qb * 64 + wr + g;
    #pragma unroll
    for (int nt = 0; nt < 8; nt++) {
        const int pc = h * 32 + (nt << 2) + t;
        uint32_t ph, pl;
        split2(oacc[nt][0] * inv0, oacc[nt][1] * inv0, ph, pl);
        attnh[(size_t)row0 * 128 + pc] = ph;
        attnl[(size_t)row0 * 128 + pc] = pl;
        split2(oacc[nt][2] * inv1, oacc[nt][3] * inv1, ph, pl);
        attnh[(size_t)(row0 + 8) * 128 + pc] = ph;
        attnl[(size_t)(row0 + 8) * 128 + pc] = pl;
    }
}

// ---------------- layernorm(xa+xb)*g+b, fp32 out + optional bf16 pair out ------
__global__ void __launch_bounds__(256) ln_kernel(
    const float* __restrict__ xa, const float* __restrict__ xb,
    const float* __restrict__ g, const float* __restrict__ bt,
    float* __restrict__ out, uint32_t* __restrict__ oh, uint32_t* __restrict__ ol)
{
    const int warp = threadIdx.x >> 5, lane = threadIdx.x & 31;
    const size_t row = (size_t)blockIdx.x * 8 + warp;
    const float* pa = xa + row * 256;
    const float* pb = xb + row * 256;

    float v[8];
    float s = 0.f;
    #pragma unroll
    for (int i = 0; i < 8; i++) {
        v[i] = pa[lane + 32 * i] + pb[lane + 32 * i];
        s += v[i];
    }
    #pragma unroll
    for (int off = 16; off > 0; off >>= 1) s += __shfl_xor_sync(0xffffffffu, s, off);
    float mean = s * (1.f / 256.f);

    float vs = 0.f;
    #pragma unroll
    for (int i = 0; i < 8; i++) { float d = v[i] - mean; vs += d * d; }
    #pragma unroll
    for (int off = 16; off > 0; off >>= 1) vs += __shfl_xor_sync(0xffffffffu, vs, off);
    float inv = 1.f / sqrtf(vs * (1.f / 256.f) + 1e-5f);

    #pragma unroll
    for (int i = 0; i < 8; i++) {
        int c = lane + 32 * i;
        float o = (v[i] - mean) * inv * g[c] + bt[c];
        out[row * 256 + c] = o;
        float on = __shfl_down_sync(0xffffffffu, o, 1);
        if (oh && !(lane & 1)) {
            uint32_t ph, pl;
            split2(o, on, ph, pl);
            oh[row * 128 + (c >> 1)] = ph;
            ol[row * 128 + (c >> 1)] = pl;
        }
    }
}

// -------------------------------- launch ---------------------------------------
extern "C" void kernel_launch(void* const* d_in, const int* in_sizes, int n_in,
                              void* d_out, int out_size)
{
    const float* x     = (const float*)d_in[0];
    const float* Win   = (const float*)d_in[1];
    const float* Wres  = (const float*)d_in[2];
    const float* Wread = (const float*)d_in[3];
    const float* bread = (const float*)d_in[4];
    const float* Wqkv  = (const float*)d_in[5];
    const float* bqkv  = (const float*)d_in[6];
    const float* Wo    = (const float*)d_in[7];
    const float* bo    = (const float*)d_in[8];
    const float* g1    = (const float*)d_in[9];
    const float* b1    = (const float*)d_in[10];
    const float* g2    = (const float*)d_in[11];
    const float* b2    = (const float*)d_in[12];
    const float* W1    = (const float*)d_in[13];
    const float* c1    = (const float*)d_in[14];
    const float* W2    = (const float*)d_in[15];
    const float* c2    = (const float*)d_in[16];
    float* out = (float*)d_out;

    float *qkv, *h, *tmp;
    uint32_t *zh, *hh, *hl, *ath, *atl, *ffh, *ffl;
    uint32_t *wrh, *wrl, *wqh, *wql, *woh, *wol, *w1h, *w1l, *w2h, *w2l;
    cudaGetSymbolAddress((void**)&qkv, g_qkv);
    cudaGetSymbolAddress((void**)&h,   g_h);
    cudaGetSymbolAddress((void**)&tmp, g_tmp);
    cudaGetSymbolAddress((void**)&zh,  g_zh);
    cudaGetSymbolAddress((void**)&hh,  g_hh);
    cudaGetSymbolAddress((void**)&hl,  g_hl);
    cudaGetSymbolAddress((void**)&ath, g_attnh);
    cudaGetSymbolAddress((void**)&atl, g_attnl);
    cudaGetSymbolAddress((void**)&ffh, g_ffh);
    cudaGetSymbolAddress((void**)&ffl, g_ffl);
    cudaGetSymbolAddress((void**)&wrh, g_wrh);
    cudaGetSymbolAddress((void**)&wrl, g_wrl);
    cudaGetSymbolAddress((void**)&wqh, g_wqh);
    cudaGetSymbolAddress((void**)&wql, g_wql);
    cudaGetSymbolAddress((void**)&woh, g_woh);
    cudaGetSymbolAddress((void**)&wol, g_wol);
    cudaGetSymbolAddress((void**)&w1h, g_w1h);
    cudaGetSymbolAddress((void**)&w1l, g_w1l);
    cudaGetSymbolAddress((void**)&w2h, g_w2h);
    cudaGetSymbolAddress((void**)&w2l, g_w2l);

    cudaFuncSetAttribute(gemm_bf16x3,
                         cudaFuncAttributeMaxDynamicSharedMemorySize,
                         GEMM_SMEM_BYTES);

    const int M = 32768;
    const int SB = GEMM_SMEM_BYTES;

    wsplit_kernel<<<256,  256>>>(Wread, wrh, wrl, 256 * 256);
    wsplit_kernel<<<768,  256>>>(Wqkv,  wqh, wql, 2 * 768 * 128);
    wsplit_kernel<<<256,  256>>>(Wo,    woh, wol, 2 * 256 * 128);
    wsplit_kernel<<<1024, 256>>>(W1,    w1h, w1l, 2 * 1024 * 128);
    wsplit_kernel<<<1024, 256>>>(W2,    w2h, w2l, 2 * 256 * 512);

    colsum_kernel<<<1, 512>>>(Wres);
    lif_kernel<<<32, 512>>>(x, Win, Wres, zh);

    gemm_bf16x3<<<dim3(2, 256), 256, SB>>>(zh, nullptr, wrh, wrl, bread,
                                           h, hh, hl, M, 256, 512, 0);

    for (int l = 0; l < 2; l++) {
        gemm_bf16x3<<<dim3(6, 256), 256, SB>>>(hh, hl,
            wqh + (size_t)l * 768 * 128, wql + (size_t)l * 768 * 128,
            bqkv + l * 768, qkv, nullptr, nullptr, M, 768, 256, 0);
        flash_mma_kernel<<<dim3(16, 128), 128>>>(qkv, ath, atl);
        gemm_bf16x3<<<dim3(2, 256), 256, SB>>>(ath, atl,
            woh + (size_t)l * 256 * 128, wol + (size_t)l * 256 * 128,
            bo + l * 256, tmp, nullptr, nullptr, M, 256, 256, 0);
        ln_kernel<<<4096, 256>>>(h, tmp, g1 + l * 256, b1 + l * 256, h, hh, hl);
        gemm_bf16x3<<<dim3(8, 256), 256, SB>>>(hh, hl,
            w1h + (size_t)l * 1024 * 128, w1l + (size_t)l * 1024 * 128,
            c1 + l * 1024, nullptr, ffh, ffl, M, 1024, 256, 1);
        gemm_bf16x3<<<dim3(2, 256), 256, SB>>>(ffh, ffl,
            w2h + (size_t)l * 256 * 512, w2l + (size_t)l * 256 * 512,
            c2 + l * 256, tmp, nullptr, nullptr, M, 256, 1024, 0);
        ln_kernel<<<4096, 256>>>(h, tmp, g2 + l * 256, b2 + l * 256,
                                 (l == 1) ? out : h,
                                 (l == 1) ? nullptr : hh,
                                 (l == 1) ? nullptr : hl);
    }
}

// round 7
// speedup vs baseline: 3.0566x; 1.1234x over previous
#include <cuda_runtime.h>
#include <cstdint>

// ---------------- scratch (device globals; no allocation APIs) ----------------
__device__ float    g_qkv [32768u*768u];     // fp32 qkv (flash input), 96MB
__device__ float    g_h   [32768u*256u];     // fp32 hidden (residual), 32MB
__device__ float    g_tmp [32768u*256u];     // fp32 proj/ff2 out, 32MB
__device__ float    g_colsum[512];

// bf16x2 packed (hi,lo) operand arrays; u32 = {odd<<16 | even}
__device__ uint32_t g_zh   [32u*1024u*256u]; // spikes bf16 (exact), 32MB
__device__ uint32_t g_hh   [32768u*128u], g_hl   [32768u*128u];
__device__ uint32_t g_attnh[32768u*128u], g_attnl[32768u*128u];
__device__ uint32_t g_ffh  [32768u*512u], g_ffl  [32768u*512u];
__device__ uint32_t g_wrh  [256u*256u],   g_wrl  [256u*256u];
__device__ uint32_t g_wqh  [2u*768u*128u],g_wql  [2u*768u*128u];
__device__ uint32_t g_woh  [2u*256u*128u],g_wol  [2u*256u*128u];
__device__ uint32_t g_w1h  [2u*1024u*128u],g_w1l [2u*1024u*128u];
__device__ uint32_t g_w2h  [2u*256u*512u],g_w2l  [2u*256u*512u];

// ---------------- bf16 split helpers ----------------
__device__ __forceinline__ void split2(float e, float o, uint32_t& hi, uint32_t& lo) {
    asm("cvt.rn.bf16x2.f32 %0, %1, %2;" : "=r"(hi) : "f"(o), "f"(e));
    float he = __uint_as_float(hi << 16);
    float ho = __uint_as_float(hi & 0xffff0000u);
    asm("cvt.rn.bf16x2.f32 %0, %1, %2;" : "=r"(lo) : "f"(o - ho), "f"(e - he));
}

__global__ void wsplit_kernel(const float* __restrict__ src,
                              uint32_t* __restrict__ h, uint32_t* __restrict__ l,
                              int npairs) {
    int i = blockIdx.x * 256 + threadIdx.x;
    if (i < npairs) {
        float2 v = *(const float2*)(src + 2 * i);
        split2(v.x, v.y, h[i], l[i]);
    }
}

// ---------------- column sums of Wres ----------------
__global__ void colsum_kernel(const float* __restrict__ Wres) {
    int r = threadIdx.x;
    float s0 = 0.f, s1 = 0.f, s2 = 0.f, s3 = 0.f;
    #pragma unroll 4
    for (int rr = 0; rr < 512; rr += 4) {
        s0 += Wres[(rr + 0) * 512 + r];
        s1 += Wres[(rr + 1) * 512 + r];
        s2 += Wres[(rr + 2) * 512 + r];
        s3 += Wres[(rr + 3) * 512 + r];
    }
    g_colsum[r] = (s0 + s1) + (s2 + s3);
}

// ---------------- LIF reservoir: saturation fast path (1 barrier/step) ---------
// Steady state has all 512 neurons spiking -> rec == colsum exactly; only the
// short transient needs the exact active/inactive list machinery.
__global__ void __launch_bounds__(512) lif_kernel(
    const float* __restrict__ x, const float* __restrict__ Win,
    const float* __restrict__ Wres, uint32_t* __restrict__ zh)
{
    const int b = blockIdx.x;
    const int r = threadIdx.x;
    const int warp = r >> 5, lane = r & 31;

    __shared__ float sWin[8][512];
    __shared__ int   s_act[512];
    __shared__ int   s_in[512];
    __shared__ int   s_wcnt[16];

    #pragma unroll
    for (int i = 0; i < 8; i++) sWin[i][r] = Win[i * 512 + r];
    // first __syncthreads_count below doubles as the staging barrier

    const float colsum = g_colsum[r];
    const float* xb = x + (size_t)b * 1024 * 8;
    uint32_t* zb = zh + (size_t)b * 1024 * 256;

    float v = 0.f, isyn = 0.f;
    int zprev = 0;

    for (int t = 0; t < 1024; t++) {
        const int na = __syncthreads_count(zprev);   // barrier + CTA popcount

        float rec;
        if (na == 512) {
            rec = colsum;                            // saturated: exact, free
        } else if (na == 0) {
            rec = 0.f;
        } else {
            // transient: exact list-based path
            unsigned bal = __ballot_sync(0xffffffffu, zprev);
            if (lane == 0) s_wcnt[warp] = __popc(bal);
            __syncthreads();
            int base_a = 0;
            #pragma unroll
            for (int w = 0; w < 16; w++) {
                int c = s_wcnt[w];
                if (w < warp) base_a += c;
            }
            int rank = __popc(bal & ((1u << lane) - 1u));
            if (zprev) s_act[base_a + rank] = r;
            else       s_in[warp * 32 - base_a + (lane - rank)] = r;
            __syncthreads();

            if (na <= 256) {
                rec = 0.f;
                for (int j = 0; j < na; j++) rec += Wres[s_act[j] * 512 + r];
            } else {
                const int ni = 512 - na;
                float a0 = 0.f, a1 = 0.f, a2 = 0.f, a3 = 0.f;
                int j = 0;
                for (; j + 4 <= ni; j += 4) {
                    a0 += Wres[s_in[j + 0] * 512 + r];
                    a1 += Wres[s_in[j + 1] * 512 + r];
                    a2 += Wres[s_in[j + 2] * 512 + r];
                    a3 += Wres[s_in[j + 3] * 512 + r];
                }
                for (; j < ni; j++) a0 += Wres[s_in[j] * 512 + r];
                rec = colsum - ((a0 + a1) + (a2 + a3));
            }
        }

        // input current: 8 uniform loads (broadcast) x per-neuron weights
        float cur = 0.f;
        #pragma unroll
        for (int i = 0; i < 8; i++) cur += xb[t * 8 + i] * sWin[i][r];

        float total = cur + rec;
        float vdec = v + 0.004f * (isyn - v);
        float idec = isyn * 0.8f;
        int z = (vdec - 0.1f) > 0.f ? 1 : 0;
        v = z ? 0.f : vdec;
        isyn = idec + total;

        int zn = __shfl_down_sync(0xffffffffu, z, 1);
        if (!(r & 1))
            zb[t * 256 + (r >> 1)] = (z ? 0x3f80u : 0u) | (zn ? 0x3f800000u : 0u);
        zprev = z;
    }
}

// ---------------- MMA helpers ----------------
__device__ __forceinline__ void mma_bf16(float* c, const uint32_t* a, const uint32_t* b) {
    asm volatile(
        "mma.sync.aligned.m16n8k16.row.col.f32.bf16.bf16.f32 "
        "{%0,%1,%2,%3},{%4,%5,%6,%7},{%8,%9},{%0,%1,%2,%3};\n"
        : "+f"(c[0]), "+f"(c[1]), "+f"(c[2]), "+f"(c[3])
        : "r"(a[0]), "r"(a[1]), "r"(a[2]), "r"(a[3]), "r"(b[0]), "r"(b[1]));
}

__device__ __forceinline__ void cp_async16(uint32_t saddr, const void* gptr) {
    asm volatile("cp.async.ca.shared.global [%0], [%1], 16;\n" :: "r"(saddr), "l"(gptr));
}

// ---------------- bf16x3 tensor-core GEMM (pre-split operands) ----------------
#define PA 20
#define MAT_U32 (128 * PA)
#define STAGE_U32 (4 * MAT_U32)
#define GEMM_SMEM_BYTES (2 * STAGE_U32 * 4)

__global__ void __launch_bounds__(256, 2) gemm_bf16x3(
    const uint32_t* __restrict__ Ah, const uint32_t* __restrict__ Al,
    const uint32_t* __restrict__ Bh, const uint32_t* __restrict__ Bl,
    const float* __restrict__ bias,
    float* __restrict__ C, uint32_t* __restrict__ Ch, uint32_t* __restrict__ Cl,
    int M, int N, int K, int relu)
{
    extern __shared__ uint32_t smem_u[];
    const int KP   = K >> 1;
    const int tid  = threadIdx.x;
    const int lane = tid & 31;
    const int warp = tid >> 5;
    const int bm   = blockIdx.y << 7;
    const int bn   = blockIdx.x << 7;
    const int warpM = (warp >> 1) << 5;
    const int warpN = (warp & 1) << 6;
    const int g = lane >> 2;
    const int t = lane & 3;
    const bool hasAl = (Al != nullptr);

    const uint32_t sbase = (uint32_t)__cvta_generic_to_shared(smem_u);

    float acc[2][8][4];
    #pragma unroll
    for (int mi = 0; mi < 2; mi++)
        #pragma unroll
        for (int ni = 0; ni < 8; ni++)
            #pragma unroll
            for (int r = 0; r < 4; r++) acc[mi][ni][r] = 0.f;

    const int ntiles = K >> 5;

    auto issue = [&](int kt, int s) {
        uint32_t st = sbase + (uint32_t)(s * STAGE_U32) * 4u;
        #pragma unroll
        for (int i = 0; i < 2; i++) {
            int slot = tid + (i << 8);
            int row = slot >> 2, c4 = (slot & 3) << 2;
            size_t go = (size_t)row * KP + kt * 16 + c4;
            uint32_t so = (uint32_t)(row * PA + c4) * 4u;
            cp_async16(st + 0 * MAT_U32 * 4u + so, Ah + (size_t)bm * KP + go);
            if (hasAl)
                cp_async16(st + 1 * MAT_U32 * 4u + so, Al + (size_t)bm * KP + go);
            cp_async16(st + 2 * MAT_U32 * 4u + so, Bh + (size_t)bn * KP + go);
            cp_async16(st + 3 * MAT_U32 * 4u + so, Bl + (size_t)bn * KP + go);
        }
        asm volatile("cp.async.commit_group;\n");
    };

    issue(0, 0);
    if (ntiles > 1) issue(1, 1);

    for (int kt = 0; kt < ntiles; kt++) {
        const int s = kt & 1;
        if (kt + 2 < ntiles)
            asm volatile("cp.async.wait_group 1;\n" ::: "memory");
        else
            asm volatile("cp.async.wait_group 0;\n" ::: "memory");
        __syncthreads();

        const uint32_t* cs  = smem_u + s * STAGE_U32;
        const uint32_t* sAh = cs;
        const uint32_t* sAl = cs + 1 * MAT_U32;
        const uint32_t* sBh = cs + 2 * MAT_U32;
        const uint32_t* sBl = cs + 3 * MAT_U32;

        #pragma unroll
        for (int ch = 0; ch < 2; ch++) {
            const int c8 = (ch << 3) + t;

            uint32_t ah[2][4], alr[2][4];
            #pragma unroll
            for (int mi = 0; mi < 2; mi++) {
                const int r0 = warpM + (mi << 4);
                ah[mi][0] = sAh[(r0 + g) * PA + c8];
                ah[mi][1] = sAh[(r0 + 8 + g) * PA + c8];
                ah[mi][2] = sAh[(r0 + g) * PA + c8 + 4];
                ah[mi][3] = sAh[(r0 + 8 + g) * PA + c8 + 4];
                if (hasAl) {
                    alr[mi][0] = sAl[(r0 + g) * PA + c8];
                    alr[mi][1] = sAl[(r0 + 8 + g) * PA + c8];
                    alr[mi][2] = sAl[(r0 + g) * PA + c8 + 4];
                    alr[mi][3] = sAl[(r0 + 8 + g) * PA + c8 + 4];
                }
            }
            #pragma unroll
            for (int ni = 0; ni < 8; ni++) {
                const int c0 = warpN + (ni << 3) + g;
                uint32_t bh2[2], bl2[2];
                bh2[0] = sBh[c0 * PA + c8];
                bh2[1] = sBh[c0 * PA + c8 + 4];
                bl2[0] = sBl[c0 * PA + c8];
                bl2[1] = sBl[c0 * PA + c8 + 4];
                mma_bf16(acc[0][ni], ah[0], bh2);
                mma_bf16(acc[0][ni], ah[0], bl2);
                mma_bf16(acc[1][ni], ah[1], bh2);
                mma_bf16(acc[1][ni], ah[1], bl2);
                if (hasAl) {
                    mma_bf16(acc[0][ni], alr[0], bh2);
                    mma_bf16(acc[1][ni], alr[1], bh2);
                }
            }
        }

        __syncthreads();
        if (kt + 2 < ntiles) issue(kt + 2, s);
    }

    const int cq = t << 1;
    #pragma unroll
    for (int ni = 0; ni < 8; ni++) {
        const int col = bn + warpN + (ni << 3) + cq;
        const float b0 = bias[col], b1 = bias[col + 1];
        #pragma unroll
        for (int mi = 0; mi < 2; mi++) {
            const int row0 = bm + warpM + (mi << 4) + g;
            float2 v0, v1;
            v0.x = acc[mi][ni][0] + b0; v0.y = acc[mi][ni][1] + b1;
            v1.x = acc[mi][ni][2] + b0; v1.y = acc[mi][ni][3] + b1;
            if (relu) {
                v0.x = fmaxf(v0.x, 0.f); v0.y = fmaxf(v0.y, 0.f);
                v1.x = fmaxf(v1.x, 0.f); v1.y = fmaxf(v1.y, 0.f);
            }
            if (C) {
                *(float2*)&C[(size_t)row0 * N + col] = v0;
                *(float2*)&C[(size_t)(row0 + 8) * N + col] = v1;
            }
            if (Ch) {
                const int NP = N >> 1;
                const int pc = col >> 1;
                uint32_t ph, pl;
                split2(v0.x, v0.y, ph, pl);
                Ch[(size_t)row0 * NP + pc] = ph;
                Cl[(size_t)row0 * NP + pc] = pl;
                split2(v1.x, v1.y, ph, pl);
                Ch[(size_t)(row0 + 8) * NP + pc] = ph;
                Cl[(size_t)(row0 + 8) * NP + pc] = pl;
            }
        }
    }
}

// ---------------- bf16x3 MMA flash attention ----------------
__global__ void __launch_bounds__(128) flash_mma_kernel(
    const float* __restrict__ qkv,
    uint32_t* __restrict__ attnh, uint32_t* __restrict__ attnl)
{
    __shared__ uint32_t S[8960];
    uint32_t* KPh = S;
    uint32_t* KPl = S + 2304;
    uint32_t* VPh = S + 4608;
    uint32_t* VPl = S + 6784;
    float* QsF = (float*)S;

    const int tid  = threadIdx.x;
    const int lane = tid & 31;
    const int w    = tid >> 5;
    const int g    = lane >> 2;
    const int t    = lane & 3;
    const int qb   = blockIdx.x;
    const int bh   = blockIdx.y;
    const int b    = bh >> 2, h = bh & 3;

    const float* base = qkv + (size_t)b * 1024 * 768;
    const float* qg = base + h * 64;
    const float* kg = base + 256 + h * 64;
    const float* vg = base + 512 + h * 64;

    const int wr = w * 16;
    const float SCALE = 0.125f;
    const float L2E   = 1.4426950408889634f;

    #pragma unroll
    for (int i = 0; i < 8; i++) {
        int idx = i * 128 + tid;
        int row = idx >> 4, c4 = (idx & 15) << 2;
        *(float4*)&QsF[row * 68 + c4] =
            *(const float4*)&qg[(size_t)(qb * 64 + row) * 768 + c4];
    }
    __syncthreads();

    uint32_t qh[4][4], ql[4][4];
    #pragma unroll
    for (int c = 0; c < 4; c++) {
        const int d0 = c * 16 + 2 * t;
        const float* r0 = &QsF[(wr + g) * 68];
        const float* r1 = &QsF[(wr + g + 8) * 68];
        split2(r0[d0],     r0[d0 + 1],     qh[c][0], ql[c][0]);
        split2(r1[d0],     r1[d0 + 1],     qh[c][1], ql[c][1]);
        split2(r0[d0 + 8], r0[d0 + 9],     qh[c][2], ql[c][2]);
        split2(r1[d0 + 8], r1[d0 + 9],     qh[c][3], ql[c][3]);
    }
    __syncthreads();

    float oacc[8][4];
    #pragma unroll
    for (int nt = 0; nt < 8; nt++)
        #pragma unroll
        for (int r = 0; r < 4; r++) oacc[nt][r] = 0.f;
    float m0 = -1e30f, m1 = -1e30f, l0 = 0.f, l1 = 0.f;

    for (int kb = 0; kb < 16; kb++) {
        #pragma unroll
        for (int i = 0; i < 16; i++) {
            const int row = (i << 2) + w;
            float2 kv = *(const float2*)&kg[(size_t)(kb * 64 + row) * 768 + 2 * lane];
            split2(kv.x, kv.y, KPh[row * 36 + lane], KPl[row * 36 + lane]);
        }
        #pragma unroll
        for (int i = 0; i < 16; i++) {
            const int idx = i * 128 + tid;
            const int d = idx & 63, k2 = idx >> 6;
            const size_t go = (size_t)(kb * 64 + 2 * k2) * 768 + d;
            split2(vg[go], vg[go + 768], VPh[k2 * 68 + d], VPl[k2 * 68 + d]);
        }
        __syncthreads();

        float sc[8][4];
        #pragma unroll
        for (int nt = 0; nt < 8; nt++)
            #pragma unroll
            for (int r = 0; r < 4; r++) sc[nt][r] = 0.f;

        #pragma unroll
        for (int c = 0; c < 4; c++) {
            const int c8 = c * 8 + t;
            #pragma unroll
            for (int nt = 0; nt < 8; nt++) {
                const uint32_t* kr = &KPh[(nt * 8 + g) * 36];
                const uint32_t* kl = &KPl[(nt * 8 + g) * 36];
                uint32_t bh2[2] = { kr[c8], kr[c8 + 4] };
                uint32_t bl2[2] = { kl[c8], kl[c8 + 4] };
                mma_bf16(sc[nt], qh[c], bh2);
                mma_bf16(sc[nt], qh[c], bl2);
                mma_bf16(sc[nt], ql[c], bh2);
            }
        }

        float mb0 = -1e30f, mb1 = -1e30f;
        #pragma unroll
        for (int nt = 0; nt < 8; nt++) {
            sc[nt][0] *= SCALE; sc[nt][1] *= SCALE;
            sc[nt][2] *= SCALE; sc[nt][3] *= SCALE;
            mb0 = fmaxf(mb0, fmaxf(sc[nt][0], sc[nt][1]));
            mb1 = fmaxf(mb1, fmaxf(sc[nt][2], sc[nt][3]));
        }
        #pragma unroll
        for (int off = 1; off <= 2; off <<= 1) {
            mb0 = fmaxf(mb0, __shfl_xor_sync(0xffffffffu, mb0, off));
            mb1 = fmaxf(mb1, __shfl_xor_sync(0xffffffffu, mb1, off));
        }
        const float mn0 = fmaxf(m0, mb0);
        const float mn1 = fmaxf(m1, mb1);
        const float c0 = exp2f((m0 - mn0) * L2E);
        const float c1 = exp2f((m1 - mn1) * L2E);
        l0 *= c0; l1 *= c1;
        #pragma unroll
        for (int nt = 0; nt < 8; nt++) {
            oacc[nt][0] *= c0; oacc[nt][1] *= c0;
            oacc[nt][2] *= c1; oacc[nt][3] *= c1;
        }
        #pragma unroll
        for (int nt = 0; nt < 8; nt++) {
            sc[nt][0] = exp2f((sc[nt][0] - mn0) * L2E);
            sc[nt][1] = exp2f((sc[nt][1] - mn0) * L2E);
            sc[nt][2] = exp2f((sc[nt][2] - mn1) * L2E);
            sc[nt][3] = exp2f((sc[nt][3] - mn1) * L2E);
            l0 += sc[nt][0] + sc[nt][1];
            l1 += sc[nt][2] + sc[nt][3];
        }
        m0 = mn0; m1 = mn1;

        __syncthreads();
        uint32_t* Ph = KPh;
        uint32_t* Pl = KPl;
        #pragma unroll
        for (int nt = 0; nt < 8; nt++) {
            const int pc = nt * 4 + t;
            split2(sc[nt][0], sc[nt][1], Ph[(wr + g) * 36 + pc], Pl[(wr + g) * 36 + pc]);
            split2(sc[nt][2], sc[nt][3], Ph[(wr + g + 8) * 36 + pc], Pl[(wr + g + 8) * 36 + pc]);
        }
        __syncwarp();

        #pragma unroll
        for (int c = 0; c < 4; c++) {
            const int c8 = c * 8 + t;
            uint32_t ah2[4], al2[4];
            ah2[0] = Ph[(wr + g) * 36 + c8];
            ah2[1] = Ph[(wr + g + 8) * 36 + c8];
            ah2[2] = Ph[(wr + g) * 36 + c8 + 4];
            ah2[3] = Ph[(wr + g + 8) * 36 + c8 + 4];
            al2[0] = Pl[(wr + g) * 36 + c8];
            al2[1] = Pl[(wr + g + 8) * 36 + c8];
            al2[2] = Pl[(wr + g) * 36 + c8 + 4];
            al2[3] = Pl[(wr + g + 8) * 36 + c8 + 4];
            #pragma unroll
            for (int nt = 0; nt < 8; nt++) {
                const int vc = nt * 8 + g;
                uint32_t bh2[2] = { VPh[(c8) * 68 + vc], VPh[(c8 + 4) * 68 + vc] };
                uint32_t bl2[2] = { VPl[(c8) * 68 + vc], VPl[(c8 + 4) * 68 + vc] };
                mma_bf16(oacc[nt], ah2, bh2);
                mma_bf16(oacc[nt], ah2, bl2);
                mma_bf16(oacc[nt], al2, bh2);
            }
        }
        __syncthreads();
    }

    #pragma unroll
    for (int off = 1; off <= 2; off <<= 1) {
        l0 += __shfl_xor_sync(0xffffffffu, l0, off);
        l1 += __shfl_xor_sync(0xffffffffu, l1, off);
    }
    const float inv0 = 1.f / l0;
    const float inv1 = 1.f / l1;

    const int row0 = b * 1024 + qb * 64 + wr + g;
    #pragma unroll
    for (int nt = 0; nt < 8; nt++) {
        const int pc = h * 32 + (nt << 2) + t;
        uint32_t ph, pl;
        split2(oacc[nt][0] * inv0, oacc[nt][1] * inv0, ph, pl);
        attnh[(size_t)row0 * 128 + pc] = ph;
        attnl[(size_t)row0 * 128 + pc] = pl;
        split2(oacc[nt][2] * inv1, oacc[nt][3] * inv1, ph, pl);
        attnh[(size_t)(row0 + 8) * 128 + pc] = ph;
        attnl[(size_t)(row0 + 8) * 128 + pc] = pl;
    }
}

// ---------------- layernorm(xa+xb)*g+b, fp32 out + optional bf16 pair out ------
__global__ void __launch_bounds__(256) ln_kernel(
    const float* __restrict__ xa, const float* __restrict__ xb,
    const float* __restrict__ g, const float* __restrict__ bt,
    float* __restrict__ out, uint32_t* __restrict__ oh, uint32_t* __restrict__ ol)
{
    const int warp = threadIdx.x >> 5, lane = threadIdx.x & 31;
    const size_t row = (size_t)blockIdx.x * 8 + warp;
    const float* pa = xa + row * 256;
    const float* pb = xb + row * 256;

    float v[8];
    float s = 0.f;
    #pragma unroll
    for (int i = 0; i < 8; i++) {
        v[i] = pa[lane + 32 * i] + pb[lane + 32 * i];
        s += v[i];
    }
    #pragma unroll
    for (int off = 16; off > 0; off >>= 1) s += __shfl_xor_sync(0xffffffffu, s, off);
    float mean = s * (1.f / 256.f);

    float vs = 0.f;
    #pragma unroll
    for (int i = 0; i < 8; i++) { float d = v[i] - mean; vs += d * d; }
    #pragma unroll
    for (int off = 16; off > 0; off >>= 1) vs += __shfl_xor_sync(0xffffffffu, vs, off);
    float inv = 1.f / sqrtf(vs * (1.f / 256.f) + 1e-5f);

    #pragma unroll
    for (int i = 0; i < 8; i++) {
        int c = lane + 32 * i;
        float o = (v[i] - mean) * inv * g[c] + bt[c];
        out[row * 256 + c] = o;
        float on = __shfl_down_sync(0xffffffffu, o, 1);
        if (oh && !(lane & 1)) {
            uint32_t ph, pl;
            split2(o, on, ph, pl);
            oh[row * 128 + (c >> 1)] = ph;
            ol[row * 128 + (c >> 1)] = pl;
        }
    }
}

// -------------------------------- launch ---------------------------------------
extern "C" void kernel_launch(void* const* d_in, const int* in_sizes, int n_in,
                              void* d_out, int out_size)
{
    const float* x     = (const float*)d_in[0];
    const float* Win   = (const float*)d_in[1];
    const float* Wres  = (const float*)d_in[2];
    const float* Wread = (const float*)d_in[3];
    const float* bread = (const float*)d_in[4];
    const float* Wqkv  = (const float*)d_in[5];
    const float* bqkv  = (const float*)d_in[6];
    const float* Wo    = (const float*)d_in[7];
    const float* bo    = (const float*)d_in[8];
    const float* g1    = (const float*)d_in[9];
    const float* b1    = (const float*)d_in[10];
    const float* g2    = (const float*)d_in[11];
    const float* b2    = (const float*)d_in[12];
    const float* W1    = (const float*)d_in[13];
    const float* c1    = (const float*)d_in[14];
    const float* W2    = (const float*)d_in[15];
    const float* c2    = (const float*)d_in[16];
    float* out = (float*)d_out;

    float *qkv, *h, *tmp;
    uint32_t *zh, *hh, *hl, *ath, *atl, *ffh, *ffl;
    uint32_t *wrh, *wrl, *wqh, *wql, *woh, *wol, *w1h, *w1l, *w2h, *w2l;
    cudaGetSymbolAddress((void**)&qkv, g_qkv);
    cudaGetSymbolAddress((void**)&h,   g_h);
    cudaGetSymbolAddress((void**)&tmp, g_tmp);
    cudaGetSymbolAddress((void**)&zh,  g_zh);
    cudaGetSymbolAddress((void**)&hh,  g_hh);
    cudaGetSymbolAddress((void**)&hl,  g_hl);
    cudaGetSymbolAddress((void**)&ath, g_attnh);
    cudaGetSymbolAddress((void**)&atl, g_attnl);
    cudaGetSymbolAddress((void**)&ffh, g_ffh);
    cudaGetSymbolAddress((void**)&ffl, g_ffl);
    cudaGetSymbolAddress((void**)&wrh, g_wrh);
    cudaGetSymbolAddress((void**)&wrl, g_wrl);
    cudaGetSymbolAddress((void**)&wqh, g_wqh);
    cudaGetSymbolAddress((void**)&wql, g_wql);
    cudaGetSymbolAddress((void**)&woh, g_woh);
    cudaGetSymbolAddress((void**)&wol, g_wol);
    cudaGetSymbolAddress((void**)&w1h, g_w1h);
    cudaGetSymbolAddress((void**)&w1l, g_w1l);
    cudaGetSymbolAddress((void**)&w2h, g_w2h);
    cudaGetSymbolAddress((void**)&w2l, g_w2l);

    cudaFuncSetAttribute(gemm_bf16x3,
                         cudaFuncAttributeMaxDynamicSharedMemorySize,
                         GEMM_SMEM_BYTES);

    const int M = 32768;
    const int SB = GEMM_SMEM_BYTES;

    wsplit_kernel<<<256,  256>>>(Wread, wrh, wrl, 256 * 256);
    wsplit_kernel<<<768,  256>>>(Wqkv,  wqh, wql, 2 * 768 * 128);
    wsplit_kernel<<<256,  256>>>(Wo,    woh, wol, 2 * 256 * 128);
    wsplit_kernel<<<1024, 256>>>(W1,    w1h, w1l, 2 * 1024 * 128);
    wsplit_kernel<<<1024, 256>>>(W2,    w2h, w2l, 2 * 256 * 512);

    colsum_kernel<<<1, 512>>>(Wres);
    lif_kernel<<<32, 512>>>(x, Win, Wres, zh);

    gemm_bf16x3<<<dim3(2, 256), 256, SB>>>(zh, nullptr, wrh, wrl, bread,
                                           h, hh, hl, M, 256, 512, 0);

    for (int l = 0; l < 2; l++) {
        gemm_bf16x3<<<dim3(6, 256), 256, SB>>>(hh, hl,
            wqh + (size_t)l * 768 * 128, wql + (size_t)l * 768 * 128,
            bqkv + l * 768, qkv, nullptr, nullptr, M, 768, 256, 0);
        flash_mma_kernel<<<dim3(16, 128), 128>>>(qkv, ath, atl);
        gemm_bf16x3<<<dim3(2, 256), 256, SB>>>(ath, atl,
            woh + (size_t)l * 256 * 128, wol + (size_t)l * 256 * 128,
            bo + l * 256, tmp, nullptr, nullptr, M, 256, 256, 0);
        ln_kernel<<<4096, 256>>>(h, tmp, g1 + l * 256, b1 + l * 256, h, hh, hl);
        gemm_bf16x3<<<dim3(8, 256), 256, SB>>>(hh, hl,
            w1h + (size_t)l * 1024 * 128, w1l + (size_t)l * 1024 * 128,
            c1 + l * 1024, nullptr, ffh, ffl, M, 1024, 256, 1);
        gemm_bf16x3<<<dim3(2, 256), 256, SB>>>(ffh, ffl,
            w2h + (size_t)l * 256 * 512, w2l + (size_t)l * 256 * 512,
            c2 + l * 256, tmp, nullptr, nullptr, M, 256, 1024, 0);
        ln_kernel<<<4096, 256>>>(h, tmp, g2 + l * 256, b2 + l * 256,
                                 (l == 1) ? out : h,
                                 (l == 1) ? nullptr : hh,
                                 (l == 1) ? nullptr : hl);
    }
}

// round 8
// speedup vs baseline: 3.1658x; 1.0357x over previous
#include <cuda_runtime.h>
#include <cstdint>

// ---------------- scratch (device globals; no allocation APIs) ----------------
__device__ float    g_qkv [32768u*768u];     // fp32 qkv (V source), 96MB
__device__ float    g_h   [32768u*256u];     // fp32 hidden (residual), 32MB
__device__ float    g_tmp [32768u*256u];     // fp32 (residual-fused) GEMM out, 32MB
__device__ float    g_colsum[512];

// bf16x2 packed (hi,lo) operand arrays; u32 = {odd<<16 | even}
__device__ uint32_t g_zh   [32u*1024u*256u];
__device__ uint32_t g_qkvh [32768u*384u], g_qkvl [32768u*384u];   // pre-split qkv
__device__ uint32_t g_hh   [32768u*128u], g_hl   [32768u*128u];
__device__ uint32_t g_attnh[32768u*128u], g_attnl[32768u*128u];
__device__ uint32_t g_ffh  [32768u*512u], g_ffl  [32768u*512u];
__device__ uint32_t g_wrh  [256u*256u],   g_wrl  [256u*256u];
__device__ uint32_t g_wqh  [2u*768u*128u],g_wql  [2u*768u*128u];
__device__ uint32_t g_woh  [2u*256u*128u],g_wol  [2u*256u*128u];
__device__ uint32_t g_w1h  [2u*1024u*128u],g_w1l [2u*1024u*128u];
__device__ uint32_t g_w2h  [2u*256u*512u],g_w2l  [2u*256u*512u];

// ---------------- bf16 split helpers ----------------
__device__ __forceinline__ void split2(float e, float o, uint32_t& hi, uint32_t& lo) {
    asm("cvt.rn.bf16x2.f32 %0, %1, %2;" : "=r"(hi) : "f"(o), "f"(e));
    float he = __uint_as_float(hi << 16);
    float ho = __uint_as_float(hi & 0xffff0000u);
    asm("cvt.rn.bf16x2.f32 %0, %1, %2;" : "=r"(lo) : "f"(o - ho), "f"(e - he));
}

__global__ void wsplit_kernel(const float* __restrict__ src,
                              uint32_t* __restrict__ h, uint32_t* __restrict__ l,
                              int npairs) {
    int i = blockIdx.x * 256 + threadIdx.x;
    if (i < npairs) {
        float2 v = *(const float2*)(src + 2 * i);
        split2(v.x, v.y, h[i], l[i]);
    }
}

// ---------------- column sums of Wres ----------------
__global__ void colsum_kernel(const float* __restrict__ Wres) {
    int r = threadIdx.x;
    float s0 = 0.f, s1 = 0.f, s2 = 0.f, s3 = 0.f;
    #pragma unroll 4
    for (int rr = 0; rr < 512; rr += 4) {
        s0 += Wres[(rr + 0) * 512 + r];
        s1 += Wres[(rr + 1) * 512 + r];
        s2 += Wres[(rr + 2) * 512 + r];
        s3 += Wres[(rr + 3) * 512 + r];
    }
    g_colsum[r] = (s0 + s1) + (s2 + s3);
}

// ---------------- LIF reservoir: saturation fast path (1 barrier/step) ---------
__global__ void __launch_bounds__(512) lif_kernel(
    const float* __restrict__ x, const float* __restrict__ Win,
    const float* __restrict__ Wres, uint32_t* __restrict__ zh)
{
    const int b = blockIdx.x;
    const int r = threadIdx.x;
    const int warp = r >> 5, lane = r & 31;

    __shared__ float sWin[8][512];
    __shared__ int   s_act[512];
    __shared__ int   s_in[512];
    __shared__ int   s_wcnt[16];

    #pragma unroll
    for (int i = 0; i < 8; i++) sWin[i][r] = Win[i * 512 + r];

    const float colsum = g_colsum[r];
    const float* xb = x + (size_t)b * 1024 * 8;
    uint32_t* zb = zh + (size_t)b * 1024 * 256;

    float v = 0.f, isyn = 0.f;
    int zprev = 0;

    for (int t = 0; t < 1024; t++) {
        const int na = __syncthreads_count(zprev);

        float rec;
        if (na == 512) {
            rec = colsum;
        } else if (na == 0) {
            rec = 0.f;
        } else {
            unsigned bal = __ballot_sync(0xffffffffu, zprev);
            if (lane == 0) s_wcnt[warp] = __popc(bal);
            __syncthreads();
            int base_a = 0;
            #pragma unroll
            for (int w = 0; w < 16; w++) {
                int c = s_wcnt[w];
                if (w < warp) base_a += c;
            }
            int rank = __popc(bal & ((1u << lane) - 1u));
            if (zprev) s_act[base_a + rank] = r;
            else       s_in[warp * 32 - base_a + (lane - rank)] = r;
            __syncthreads();

            if (na <= 256) {
                rec = 0.f;
                for (int j = 0; j < na; j++) rec += Wres[s_act[j] * 512 + r];
            } else {
                const int ni = 512 - na;
                float a0 = 0.f, a1 = 0.f, a2 = 0.f, a3 = 0.f;
                int j = 0;
                for (; j + 4 <= ni; j += 4) {
                    a0 += Wres[s_in[j + 0] * 512 + r];
                    a1 += Wres[s_in[j + 1] * 512 + r];
                    a2 += Wres[s_in[j + 2] * 512 + r];
                    a3 += Wres[s_in[j + 3] * 512 + r];
                }
                for (; j < ni; j++) a0 += Wres[s_in[j] * 512 + r];
                rec = colsum - ((a0 + a1) + (a2 + a3));
            }
        }

        float cur = 0.f;
        #pragma unroll
        for (int i = 0; i < 8; i++) cur += xb[t * 8 + i] * sWin[i][r];

        float total = cur + rec;
        float vdec = v + 0.004f * (isyn - v);
        float idec = isyn * 0.8f;
        int z = (vdec - 0.1f) > 0.f ? 1 : 0;
        v = z ? 0.f : vdec;
        isyn = idec + total;

        int zn = __shfl_down_sync(0xffffffffu, z, 1);
        if (!(r & 1))
            zb[t * 256 + (r >> 1)] = (z ? 0x3f80u : 0u) | (zn ? 0x3f800000u : 0u);
        zprev = z;
    }
}

// ---------------- MMA helpers ----------------
__device__ __forceinline__ void mma_bf16(float* c, const uint32_t* a, const uint32_t* b) {
    asm volatile(
        "mma.sync.aligned.m16n8k16.row.col.f32.bf16.bf16.f32 "
        "{%0,%1,%2,%3},{%4,%5,%6,%7},{%8,%9},{%0,%1,%2,%3};\n"
        : "+f"(c[0]), "+f"(c[1]), "+f"(c[2]), "+f"(c[3])
        : "r"(a[0]), "r"(a[1]), "r"(a[2]), "r"(a[3]), "r"(b[0]), "r"(b[1]));
}

__device__ __forceinline__ void cp_async16(uint32_t saddr, const void* gptr) {
    asm volatile("cp.async.ca.shared.global [%0], [%1], 16;\n" :: "r"(saddr), "l"(gptr));
}

// ---------------- bf16x3 tensor-core GEMM (pre-split operands) ----------------
// C[m][n] = sum_k A[m][k]*B[n][k] + bias[n] (+ Radd[m][n] residual, optional)
#define PA 20
#define MAT_U32 (128 * PA)
#define STAGE_U32 (4 * MAT_U32)
#define GEMM_SMEM_BYTES (2 * STAGE_U32 * 4)

__global__ void __launch_bounds__(256, 2) gemm_bf16x3(
    const uint32_t* __restrict__ Ah, const uint32_t* __restrict__ Al,
    const uint32_t* __restrict__ Bh, const uint32_t* __restrict__ Bl,
    const float* __restrict__ bias, const float* __restrict__ Radd,
    float* __restrict__ C, uint32_t* __restrict__ Ch, uint32_t* __restrict__ Cl,
    int M, int N, int K, int relu)
{
    extern __shared__ uint32_t smem_u[];
    const int KP   = K >> 1;
    const int tid  = threadIdx.x;
    const int lane = tid & 31;
    const int warp = tid >> 5;
    const int bm   = blockIdx.y << 7;
    const int bn   = blockIdx.x << 7;
    const int warpM = (warp >> 1) << 5;
    const int warpN = (warp & 1) << 6;
    const int g = lane >> 2;
    const int t = lane & 3;
    const bool hasAl = (Al != nullptr);

    const uint32_t sbase = (uint32_t)__cvta_generic_to_shared(smem_u);

    float acc[2][8][4];
    #pragma unroll
    for (int mi = 0; mi < 2; mi++)
        #pragma unroll
        for (int ni = 0; ni < 8; ni++)
            #pragma unroll
            for (int r = 0; r < 4; r++) acc[mi][ni][r] = 0.f;

    const int ntiles = K >> 5;

    auto issue = [&](int kt, int s) {
        uint32_t st = sbase + (uint32_t)(s * STAGE_U32) * 4u;
        #pragma unroll
        for (int i = 0; i < 2; i++) {
            int slot = tid + (i << 8);
            int row = slot >> 2, c4 = (slot & 3) << 2;
            size_t go = (size_t)row * KP + kt * 16 + c4;
            uint32_t so = (uint32_t)(row * PA + c4) * 4u;
            cp_async16(st + 0 * MAT_U32 * 4u + so, Ah + (size_t)bm * KP + go);
            if (hasAl)
                cp_async16(st + 1 * MAT_U32 * 4u + so, Al + (size_t)bm * KP + go);
            cp_async16(st + 2 * MAT_U32 * 4u + so, Bh + (size_t)bn * KP + go);
            cp_async16(st + 3 * MAT_U32 * 4u + so, Bl + (size_t)bn * KP + go);
        }
        asm volatile("cp.async.commit_group;\n");
    };

    issue(0, 0);
    if (ntiles > 1) issue(1, 1);

    for (int kt = 0; kt < ntiles; kt++) {
        const int s = kt & 1;
        if (kt + 2 < ntiles)
            asm volatile("cp.async.wait_group 1;\n" ::: "memory");
        else
            asm volatile("cp.async.wait_group 0;\n" ::: "memory");
        __syncthreads();

        const uint32_t* cs  = smem_u + s * STAGE_U32;
        const uint32_t* sAh = cs;
        const uint32_t* sAl = cs + 1 * MAT_U32;
        const uint32_t* sBh = cs + 2 * MAT_U32;
        const uint32_t* sBl = cs + 3 * MAT_U32;

        #pragma unroll
        for (int ch = 0; ch < 2; ch++) {
            const int c8 = (ch << 3) + t;

            uint32_t ah[2][4], alr[2][4];
            #pragma unroll
            for (int mi = 0; mi < 2; mi++) {
                const int r0 = warpM + (mi << 4);
                ah[mi][0] = sAh[(r0 + g) * PA + c8];
                ah[mi][1] = sAh[(r0 + 8 + g) * PA + c8];
                ah[mi][2] = sAh[(r0 + g) * PA + c8 + 4];
                ah[mi][3] = sAh[(r0 + 8 + g) * PA + c8 + 4];
                if (hasAl) {
                    alr[mi][0] = sAl[(r0 + g) * PA + c8];
                    alr[mi][1] = sAl[(r0 + 8 + g) * PA + c8];
                    alr[mi][2] = sAl[(r0 + g) * PA + c8 + 4];
                    alr[mi][3] = sAl[(r0 + 8 + g) * PA + c8 + 4];
                }
            }
            #pragma unroll
            for (int ni = 0; ni < 8; ni++) {
                const int c0 = warpN + (ni << 3) + g;
                uint32_t bh2[2], bl2[2];
                bh2[0] = sBh[c0 * PA + c8];
                bh2[1] = sBh[c0 * PA + c8 + 4];
                bl2[0] = sBl[c0 * PA + c8];
                bl2[1] = sBl[c0 * PA + c8 + 4];
                mma_bf16(acc[0][ni], ah[0], bh2);
                mma_bf16(acc[0][ni], ah[0], bl2);
                mma_bf16(acc[1][ni], ah[1], bh2);
                mma_bf16(acc[1][ni], ah[1], bl2);
                if (hasAl) {
                    mma_bf16(acc[0][ni], alr[0], bh2);
                    mma_bf16(acc[1][ni], alr[1], bh2);
                }
            }
        }

        __syncthreads();
        if (kt + 2 < ntiles) issue(kt + 2, s);
    }

    const int cq = t << 1;
    #pragma unroll
    for (int ni = 0; ni < 8; ni++) {
        const int col = bn + warpN + (ni << 3) + cq;
        const float b0 = bias[col], b1 = bias[col + 1];
        #pragma unroll
        for (int mi = 0; mi < 2; mi++) {
            const int row0 = bm + warpM + (mi << 4) + g;
            float2 v0, v1;
            v0.x = acc[mi][ni][0] + b0; v0.y = acc[mi][ni][1] + b1;
            v1.x = acc[mi][ni][2] + b0; v1.y = acc[mi][ni][3] + b1;
            if (Radd) {
                float2 r0 = *(const float2*)&Radd[(size_t)row0 * N + col];
                float2 r1 = *(const float2*)&Radd[(size_t)(row0 + 8) * N + col];
                v0.x += r0.x; v0.y += r0.y;
                v1.x += r1.x; v1.y += r1.y;
            }
            if (relu) {
                v0.x = fmaxf(v0.x, 0.f); v0.y = fmaxf(v0.y, 0.f);
                v1.x = fmaxf(v1.x, 0.f); v1.y = fmaxf(v1.y, 0.f);
            }
            if (C) {
                *(float2*)&C[(size_t)row0 * N + col] = v0;
                *(float2*)&C[(size_t)(row0 + 8) * N + col] = v1;
            }
            if (Ch) {
                const int NP = N >> 1;
                const int pc = col >> 1;
                uint32_t ph, pl;
                split2(v0.x, v0.y, ph, pl);
                Ch[(size_t)row0 * NP + pc] = ph;
                Cl[(size_t)row0 * NP + pc] = pl;
                split2(v1.x, v1.y, ph, pl);
                Ch[(size_t)(row0 + 8) * NP + pc] = ph;
                Cl[(size_t)(row0 + 8) * NP + pc] = pl;
            }
        }
    }
}

// ---------------- bf16x3 MMA flash attention (pre-split Q/K) ----------------
// Q fragments loaded directly from qkvh/qkvl; K tiles cp.async'd as pairs;
// V converted from fp32 qkv (pairs along key index).
__global__ void __launch_bounds__(128) flash_mma_kernel(
    const float* __restrict__ qkv,
    const uint32_t* __restrict__ qkvh, const uint32_t* __restrict__ qkvl,
    uint32_t* __restrict__ attnh, uint32_t* __restrict__ attnl)
{
    __shared__ uint32_t S[8960];
    uint32_t* KPh = S;            // [64][36]  key x d-pair (aliased as P)
    uint32_t* KPl = S + 2304;
    uint32_t* VPh = S + 4608;     // [32][68]  k-pair x d
    uint32_t* VPl = S + 6784;

    const int tid  = threadIdx.x;
    const int lane = tid & 31;
    const int w    = tid >> 5;
    const int g    = lane >> 2;
    const int t    = lane & 3;
    const int qb   = blockIdx.x;
    const int bh   = blockIdx.y;
    const int b    = bh >> 2, h = bh & 3;

    const uint32_t sbase = (uint32_t)__cvta_generic_to_shared(S);
    const float* vg = qkv + (size_t)b * 1024 * 768 + 512 + h * 64;
    const uint32_t* kph = qkvh + (size_t)b * 1024 * 384 + 128 + h * 32;
    const uint32_t* kpl = qkvl + (size_t)b * 1024 * 384 + 128 + h * 32;

    const int wr = w * 16;
    const float SCALE = 0.125f;
    const float L2E   = 1.4426950408889634f;

    // ---- Q fragments: direct global loads of pre-split pairs ----
    uint32_t qh[4][4], ql[4][4];
    {
        const size_t q0 = (size_t)(b * 1024 + qb * 64 + wr + g) * 384 + h * 32;
        const size_t q1 = q0 + (size_t)8 * 384;
        #pragma unroll
        for (int c = 0; c < 4; c++) {
            const int p = c * 8 + t;
            qh[c][0] = qkvh[q0 + p];     ql[c][0] = qkvl[q0 + p];
            qh[c][1] = qkvh[q1 + p];     ql[c][1] = qkvl[q1 + p];
            qh[c][2] = qkvh[q0 + p + 4]; ql[c][2] = qkvl[q0 + p + 4];
            qh[c][3] = qkvh[q1 + p + 4]; ql[c][3] = qkvl[q1 + p + 4];
        }
    }

    float oacc[8][4];
    #pragma unroll
    for (int nt = 0; nt < 8; nt++)
        #pragma unroll
        for (int r = 0; r < 4; r++) oacc[nt][r] = 0.f;
    float m0 = -1e30f, m1 = -1e30f, l0 = 0.f, l1 = 0.f;

    for (int kb = 0; kb < 16; kb++) {
        // ---- K tile: cp.async pre-split pairs (64 rows x 32 u32, pitch 36) ----
        #pragma unroll
        for (int i = 0; i < 4; i++) {
            const int idx = i * 128 + tid;
            const int row = idx >> 3, q4 = (idx & 7) << 2;
            const size_t go = (size_t)(kb * 64 + row) * 384 + q4;
            const uint32_t so = (uint32_t)(row * 36 + q4) * 4u;
            cp_async16(sbase + so, kph + go);
            cp_async16(sbase + 2304u * 4u + so, kpl + go);
        }
        asm volatile("cp.async.commit_group;\n");

        // ---- V tile: fp32 -> pairs along key index (overlaps cp.async) ----
        #pragma unroll
        for (int i = 0; i < 16; i++) {
            const int idx = i * 128 + tid;
            const int d = idx & 63, k2 = idx >> 6;
            const size_t go = (size_t)(kb * 64 + 2 * k2) * 768 + d;
            split2(vg[go], vg[go + 768], VPh[k2 * 68 + d], VPl[k2 * 68 + d]);
        }
        asm volatile("cp.async.wait_group 0;\n" ::: "memory");
        __syncthreads();

        // ---- QK^T (bf16x3) ----
        float sc[8][4];
        #pragma unroll
        for (int nt = 0; nt < 8; nt++)
            #pragma unroll
            for (int r = 0; r < 4; r++) sc[nt][r] = 0.f;

        #pragma unroll
        for (int c = 0; c < 4; c++) {
            const int c8 = c * 8 + t;
            #pragma unroll
            for (int nt = 0; nt < 8; nt++) {
                const uint32_t* kr = &KPh[(nt * 8 + g) * 36];
                const uint32_t* kl = &KPl[(nt * 8 + g) * 36];
                uint32_t bh2[2] = { kr[c8], kr[c8 + 4] };
                uint32_t bl2[2] = { kl[c8], kl[c8 + 4] };
                mma_bf16(sc[nt], qh[c], bh2);
                mma_bf16(sc[nt], qh[c], bl2);
                mma_bf16(sc[nt], ql[c], bh2);
            }
        }

        // ---- online softmax ----
        float mb0 = -1e30f, mb1 = -1e30f;
        #pragma unroll
        for (int nt = 0; nt < 8; nt++) {
            sc[nt][0] *= SCALE; sc[nt][1] *= SCALE;
            sc[nt][2] *= SCALE; sc[nt][3] *= SCALE;
            mb0 = fmaxf(mb0, fmaxf(sc[nt][0], sc[nt][1]));
            mb1 = fmaxf(mb1, fmaxf(sc[nt][2], sc[nt][3]));
        }
        #pragma unroll
        for (int off = 1; off <= 2; off <<= 1) {
            mb0 = fmaxf(mb0, __shfl_xor_sync(0xffffffffu, mb0, off));
            mb1 = fmaxf(mb1, __shfl_xor_sync(0xffffffffu, mb1, off));
        }
        const float mn0 = fmaxf(m0, mb0);
        const float mn1 = fmaxf(m1, mb1);
        const float c0 = exp2f((m0 - mn0) * L2E);
        const float c1 = exp2f((m1 - mn1) * L2E);
        l0 *= c0; l1 *= c1;
        #pragma unroll
        for (int nt = 0; nt < 8; nt++) {
            oacc[nt][0] *= c0; oacc[nt][1] *= c0;
            oacc[nt][2] *= c1; oacc[nt][3] *= c1;
        }
        #pragma unroll
        for (int nt = 0; nt < 8; nt++) {
            sc[nt][0] = exp2f((sc[nt][0] - mn0) * L2E);
            sc[nt][1] = exp2f((sc[nt][1] - mn0) * L2E);
            sc[nt][2] = exp2f((sc[nt][2] - mn1) * L2E);
            sc[nt][3] = exp2f((sc[nt][3] - mn1) * L2E);
            l0 += sc[nt][0] + sc[nt][1];
            l1 += sc[nt][2] + sc[nt][3];
        }
        m0 = mn0; m1 = mn1;

        // ---- pack P into pairs, aliasing K pair region ----
        __syncthreads();
        uint32_t* Ph = KPh;
        uint32_t* Pl = KPl;
        #pragma unroll
        for (int nt = 0; nt < 8; nt++) {
            const int pc = nt * 4 + t;
            split2(sc[nt][0], sc[nt][1], Ph[(wr + g) * 36 + pc], Pl[(wr + g) * 36 + pc]);
            split2(sc[nt][2], sc[nt][3], Ph[(wr + g + 8) * 36 + pc], Pl[(wr + g + 8) * 36 + pc]);
        }
        __syncwarp();

        // ---- P @ V (bf16x3) ----
        #pragma unroll
        for (int c = 0; c < 4; c++) {
            const int c8 = c * 8 + t;
            uint32_t ah2[4], al2[4];
            ah2[0] = Ph[(wr + g) * 36 + c8];
            ah2[1] = Ph[(wr + g + 8) * 36 + c8];
            ah2[2] = Ph[(wr + g) * 36 + c8 + 4];
            ah2[3] = Ph[(wr + g + 8) * 36 + c8 + 4];
            al2[0] = Pl[(wr + g) * 36 + c8];
            al2[1] = Pl[(wr + g + 8) * 36 + c8];
            al2[2] = Pl[(wr + g) * 36 + c8 + 4];
            al2[3] = Pl[(wr + g + 8) * 36 + c8 + 4];
            #pragma unroll
            for (int nt = 0; nt < 8; nt++) {
                const int vc = nt * 8 + g;
                uint32_t bh2[2] = { VPh[(c8) * 68 + vc], VPh[(c8 + 4) * 68 + vc] };
                uint32_t bl2[2] = { VPl[(c8) * 68 + vc], VPl[(c8 + 4) * 68 + vc] };
                mma_bf16(oacc[nt], ah2, bh2);
                mma_bf16(oacc[nt], ah2, bl2);
                mma_bf16(oacc[nt], al2, bh2);
            }
        }
        __syncthreads();
    }

    #pragma unroll
    for (int off = 1; off <= 2; off <<= 1) {
        l0 += __shfl_xor_sync(0xffffffffu, l0, off);
        l1 += __shfl_xor_sync(0xffffffffu, l1, off);
    }
    const float inv0 = 1.f / l0;
    const float inv1 = 1.f / l1;

    const int row0 = b * 1024 + qb * 64 + wr + g;
    #pragma unroll
    for (int nt = 0; nt < 8; nt++) {
        const int pc = h * 32 + (nt << 2) + t;
        uint32_t ph, pl;
        split2(oacc[nt][0] * inv0, oacc[nt][1] * inv0, ph, pl);
        attnh[(size_t)row0 * 128 + pc] = ph;
        attnl[(size_t)row0 * 128 + pc] = pl;
        split2(oacc[nt][2] * inv1, oacc[nt][3] * inv1, ph, pl);
        attnh[(size_t)(row0 + 8) * 128 + pc] = ph;
        attnl[(size_t)(row0 + 8) * 128 + pc] = pl;
    }
}

// ---------------- layernorm(xa[+xb])*g+b, fp32 out + optional bf16 pair out ----
__global__ void __launch_bounds__(256) ln_kernel(
    const float* __restrict__ xa, const float* __restrict__ xb,
    const float* __restrict__ g, const float* __restrict__ bt,
    float* __restrict__ out, uint32_t* __restrict__ oh, uint32_t* __restrict__ ol)
{
    const int warp = threadIdx.x >> 5, lane = threadIdx.x & 31;
    const size_t row = (size_t)blockIdx.x * 8 + warp;
    const float* pa = xa + row * 256;
    const float* pb = xb ? xb + row * 256 : nullptr;

    float v[8];
    float s = 0.f;
    #pragma unroll
    for (int i = 0; i < 8; i++) {
        v[i] = pa[lane + 32 * i];
        if (pb) v[i] += pb[lane + 32 * i];
        s += v[i];
    }
    #pragma unroll
    for (int off = 16; off > 0; off >>= 1) s += __shfl_xor_sync(0xffffffffu, s, off);
    float mean = s * (1.f / 256.f);

    float vs = 0.f;
    #pragma unroll
    for (int i = 0; i < 8; i++) { float d = v[i] - mean; vs += d * d; }
    #pragma unroll
    for (int off = 16; off > 0; off >>= 1) vs += __shfl_xor_sync(0xffffffffu, vs, off);
    float inv = 1.f / sqrtf(vs * (1.f / 256.f) + 1e-5f);

    #pragma unroll
    for (int i = 0; i < 8; i++) {
        int c = lane + 32 * i;
        float o = (v[i] - mean) * inv * g[c] + bt[c];
        out[row * 256 + c] = o;
        float on = __shfl_down_sync(0xffffffffu, o, 1);
        if (oh && !(lane & 1)) {
            uint32_t ph, pl;
            split2(o, on, ph, pl);
            oh[row * 128 + (c >> 1)] = ph;
            ol[row * 128 + (c >> 1)] = pl;
        }
    }
}

// -------------------------------- launch ---------------------------------------
extern "C" void kernel_launch(void* const* d_in, const int* in_sizes, int n_in,
                              void* d_out, int out_size)
{
    const float* x     = (const float*)d_in[0];
    const float* Win   = (const float*)d_in[1];
    const float* Wres  = (const float*)d_in[2];
    const float* Wread = (const float*)d_in[3];
    const float* bread = (const float*)d_in[4];
    const float* Wqkv  = (const float*)d_in[5];
    const float* bqkv  = (const float*)d_in[6];
    const float* Wo    = (const float*)d_in[7];
    const float* bo    = (const float*)d_in[8];
    const float* g1    = (const float*)d_in[9];
    const float* b1    = (const float*)d_in[10];
    const float* g2    = (const float*)d_in[11];
    const float* b2    = (const float*)d_in[12];
    const float* W1    = (const float*)d_in[13];
    const float* c1    = (const float*)d_in[14];
    const float* W2    = (const float*)d_in[15];
    const float* c2    = (const float*)d_in[16];
    float* out = (float*)d_out;

    float *qkv, *h, *tmp;
    uint32_t *zh, *qh, *ql_, *hh, *hl, *ath, *atl, *ffh, *ffl;
    uint32_t *wrh, *wrl, *wqh, *wql, *woh, *wol, *w1h, *w1l, *w2h, *w2l;
    cudaGetSymbolAddress((void**)&qkv, g_qkv);
    cudaGetSymbolAddress((void**)&h,   g_h);
    cudaGetSymbolAddress((void**)&tmp, g_tmp);
    cudaGetSymbolAddress((void**)&zh,  g_zh);
    cudaGetSymbolAddress((void**)&qh,  g_qkvh);
    cudaGetSymbolAddress((void**)&ql_, g_qkvl);
    cudaGetSymbolAddress((void**)&hh,  g_hh);
    cudaGetSymbolAddress((void**)&hl,  g_hl);
    cudaGetSymbolAddress((void**)&ath, g_attnh);
    cudaGetSymbolAddress((void**)&atl, g_attnl);
    cudaGetSymbolAddress((void**)&ffh, g_ffh);
    cudaGetSymbolAddress((void**)&ffl, g_ffl);
    cudaGetSymbolAddress((void**)&wrh, g_wrh);
    cudaGetSymbolAddress((void**)&wrl, g_wrl);
    cudaGetSymbolAddress((void**)&wqh, g_wqh);
    cudaGetSymbolAddress((void**)&wql, g_wql);
    cudaGetSymbolAddress((void**)&woh, g_woh);
    cudaGetSymbolAddress((void**)&wol, g_wol);
    cudaGetSymbolAddress((void**)&w1h, g_w1h);
    cudaGetSymbolAddress((void**)&w1l, g_w1l);
    cudaGetSymbolAddress((void**)&w2h, g_w2h);
    cudaGetSymbolAddress((void**)&w2l, g_w2l);

    cudaFuncSetAttribute(gemm_bf16x3,
                         cudaFuncAttributeMaxDynamicSharedMemorySize,
                         GEMM_SMEM_BYTES);

    const int M = 32768;
    const int SB = GEMM_SMEM_BYTES;

    wsplit_kernel<<<256,  256>>>(Wread, wrh, wrl, 256 * 256);
    wsplit_kernel<<<768,  256>>>(Wqkv,  wqh, wql, 2 * 768 * 128);
    wsplit_kernel<<<256,  256>>>(Wo,    woh, wol, 2 * 256 * 128);
    wsplit_kernel<<<1024, 256>>>(W1,    w1h, w1l, 2 * 1024 * 128);
    wsplit_kernel<<<1024, 256>>>(W2,    w2h, w2l, 2 * 256 * 512);

    colsum_kernel<<<1, 512>>>(Wres);
    lif_kernel<<<32, 512>>>(x, Win, Wres, zh);

    // h = z @ Wread^T + bread   (z exact in bf16 -> 2-term)
    gemm_bf16x3<<<dim3(2, 256), 256, SB>>>(zh, nullptr, wrh, wrl, bread, nullptr,
                                           h, hh, hl, M, 256, 512, 0);

    for (int l = 0; l < 2; l++) {
        // qkv = h @ Wqkv^T + bqkv  -> fp32 (V) + pairs (Q,K)
        gemm_bf16x3<<<dim3(6, 256), 256, SB>>>(hh, hl,
            wqh + (size_t)l * 768 * 128, wql + (size_t)l * 768 * 128,
            bqkv + l * 768, nullptr, qkv, qh, ql_, M, 768, 256, 0);
        // attention -> bf16 pair out
        flash_mma_kernel<<<dim3(16, 128), 128>>>(qkv, qh, ql_, ath, atl);
        // tmp = attn @ Wo^T + bo + h (residual fused)
        gemm_bf16x3<<<dim3(2, 256), 256, SB>>>(ath, atl,
            woh + (size_t)l * 256 * 128, wol + (size_t)l * 256 * 128,
            bo + l * 256, h, tmp, nullptr, nullptr, M, 256, 256, 0);
        // h = LN(tmp) (+ bf16 pairs)
        ln_kernel<<<4096, 256>>>(tmp, nullptr, g1 + l * 256, b1 + l * 256, h, hh, hl);
        // ff = relu(h @ W1^T + c1) -> pairs only
        gemm_bf16x3<<<dim3(8, 256), 256, SB>>>(hh, hl,
            w1h + (size_t)l * 1024 * 128, w1l + (size_t)l * 1024 * 128,
            c1 + l * 1024, nullptr, nullptr, ffh, ffl, M, 1024, 256, 1);
        // tmp = ff @ W2^T + c2 + h (residual fused)
        gemm_bf16x3<<<dim3(2, 256), 256, SB>>>(ffh, ffl,
            w2h + (size_t)l * 256 * 512, w2l + (size_t)l * 256 * 512,
            c2 + l * 256, h, tmp, nullptr, nullptr, M, 256, 1024, 0);
        // out/h = LN(tmp)
        ln_kernel<<<4096, 256>>>(tmp, nullptr, g2 + l * 256, b2 + l * 256,
                                 (l == 1) ? out : h,
                                 (l == 1) ? nullptr : hh,
                                 (l == 1) ? nullptr : hl);
    }
}

// round 9
// speedup vs baseline: 3.2789x; 1.0357x over previous
#include <cuda_runtime.h>
#include <cstdint>

// ---------------- scratch (device globals; no allocation APIs) ----------------
__device__ float    g_qkv [32768u*768u];     // fp32 qkv (V source), 96MB
__device__ float    g_h   [32768u*256u];     // fp32 hidden (residual), 32MB
__device__ float    g_tmp [32768u*256u];     // fp32 (residual-fused) GEMM out, 32MB
__device__ float    g_colsum[512];

// bf16x2 packed (hi,lo) operand arrays; u32 = {odd<<16 | even}
__device__ uint32_t g_zh   [32u*1024u*256u];
__device__ uint32_t g_qkvh [32768u*384u], g_qkvl [32768u*384u];   // pre-split qkv
__device__ uint32_t g_hh   [32768u*128u], g_hl   [32768u*128u];
__device__ uint32_t g_attnh[32768u*128u], g_attnl[32768u*128u];
__device__ uint32_t g_ffh  [32768u*512u], g_ffl  [32768u*512u];
__device__ uint32_t g_wrh  [256u*256u],   g_wrl  [256u*256u];
__device__ uint32_t g_wqh  [2u*768u*128u],g_wql  [2u*768u*128u];
__device__ uint32_t g_woh  [2u*256u*128u],g_wol  [2u*256u*128u];
__device__ uint32_t g_w1h  [2u*1024u*128u],g_w1l [2u*1024u*128u];
__device__ uint32_t g_w2h  [2u*256u*512u],g_w2l  [2u*256u*512u];

// ---------------- bf16 split helpers ----------------
__device__ __forceinline__ void split2(float e, float o, uint32_t& hi, uint32_t& lo) {
    asm("cvt.rn.bf16x2.f32 %0, %1, %2;" : "=r"(hi) : "f"(o), "f"(e));
    float he = __uint_as_float(hi << 16);
    float ho = __uint_as_float(hi & 0xffff0000u);
    asm("cvt.rn.bf16x2.f32 %0, %1, %2;" : "=r"(lo) : "f"(o - ho), "f"(e - he));
}

__global__ void wsplit_kernel(const float* __restrict__ src,
                              uint32_t* __restrict__ h, uint32_t* __restrict__ l,
                              int npairs) {
    int i = blockIdx.x * 256 + threadIdx.x;
    if (i < npairs) {
        float2 v = *(const float2*)(src + 2 * i);
        split2(v.x, v.y, h[i], l[i]);
    }
}

// ---------------- column sums of Wres ----------------
__global__ void colsum_kernel(const float* __restrict__ Wres) {
    int r = threadIdx.x;
    float s0 = 0.f, s1 = 0.f, s2 = 0.f, s3 = 0.f;
    #pragma unroll 4
    for (int rr = 0; rr < 512; rr += 4) {
        s0 += Wres[(rr + 0) * 512 + r];
        s1 += Wres[(rr + 1) * 512 + r];
        s2 += Wres[(rr + 2) * 512 + r];
        s3 += Wres[(rr + 3) * 512 + r];
    }
    g_colsum[r] = (s0 + s1) + (s2 + s3);
}

// ---------------- LIF reservoir: saturation fast path (1 barrier/step) ---------
__global__ void __launch_bounds__(512) lif_kernel(
    const float* __restrict__ x, const float* __restrict__ Win,
    const float* __restrict__ Wres, uint32_t* __restrict__ zh)
{
    const int b = blockIdx.x;
    const int r = threadIdx.x;
    const int warp = r >> 5, lane = r & 31;

    __shared__ float sWin[8][512];
    __shared__ int   s_act[512];
    __shared__ int   s_in[512];
    __shared__ int   s_wcnt[16];

    #pragma unroll
    for (int i = 0; i < 8; i++) sWin[i][r] = Win[i * 512 + r];

    const float colsum = g_colsum[r];
    const float* xb = x + (size_t)b * 1024 * 8;
    uint32_t* zb = zh + (size_t)b * 1024 * 256;

    float v = 0.f, isyn = 0.f;
    int zprev = 0;

    for (int t = 0; t < 1024; t++) {
        const int na = __syncthreads_count(zprev);

        float rec;
        if (na == 512) {
            rec = colsum;
        } else if (na == 0) {
            rec = 0.f;
        } else {
            unsigned bal = __ballot_sync(0xffffffffu, zprev);
            if (lane == 0) s_wcnt[warp] = __popc(bal);
            __syncthreads();
            int base_a = 0;
            #pragma unroll
            for (int w = 0; w < 16; w++) {
                int c = s_wcnt[w];
                if (w < warp) base_a += c;
            }
            int rank = __popc(bal & ((1u << lane) - 1u));
            if (zprev) s_act[base_a + rank] = r;
            else       s_in[warp * 32 - base_a + (lane - rank)] = r;
            __syncthreads();

            if (na <= 256) {
                rec = 0.f;
                for (int j = 0; j < na; j++) rec += Wres[s_act[j] * 512 + r];
            } else {
                const int ni = 512 - na;
                float a0 = 0.f, a1 = 0.f, a2 = 0.f, a3 = 0.f;
                int j = 0;
                for (; j + 4 <= ni; j += 4) {
                    a0 += Wres[s_in[j + 0] * 512 + r];
                    a1 += Wres[s_in[j + 1] * 512 + r];
                    a2 += Wres[s_in[j + 2] * 512 + r];
                    a3 += Wres[s_in[j + 3] * 512 + r];
                }
                for (; j < ni; j++) a0 += Wres[s_in[j] * 512 + r];
                rec = colsum - ((a0 + a1) + (a2 + a3));
            }
        }

        float cur = 0.f;
        #pragma unroll
        for (int i = 0; i < 8; i++) cur += xb[t * 8 + i] * sWin[i][r];

        float total = cur + rec;
        float vdec = v + 0.004f * (isyn - v);
        float idec = isyn * 0.8f;
        int z = (vdec - 0.1f) > 0.f ? 1 : 0;
        v = z ? 0.f : vdec;
        isyn = idec + total;

        int zn = __shfl_down_sync(0xffffffffu, z, 1);
        if (!(r & 1))
            zb[t * 256 + (r >> 1)] = (z ? 0x3f80u : 0u) | (zn ? 0x3f800000u : 0u);
        zprev = z;
    }
}

// ---------------- MMA helpers ----------------
__device__ __forceinline__ void mma_bf16(float* c, const uint32_t* a, const uint32_t* b) {
    asm volatile(
        "mma.sync.aligned.m16n8k16.row.col.f32.bf16.bf16.f32 "
        "{%0,%1,%2,%3},{%4,%5,%6,%7},{%8,%9},{%0,%1,%2,%3};\n"
        : "+f"(c[0]), "+f"(c[1]), "+f"(c[2]), "+f"(c[3])
        : "r"(a[0]), "r"(a[1]), "r"(a[2]), "r"(a[3]), "r"(b[0]), "r"(b[1]));
}

__device__ __forceinline__ void cp_async16(uint32_t saddr, const void* gptr) {
    asm volatile("cp.async.ca.shared.global [%0], [%1], 16;\n" :: "r"(saddr), "l"(gptr));
}

__device__ __forceinline__ void ldsm_x4(uint32_t& r0, uint32_t& r1,
                                        uint32_t& r2, uint32_t& r3, uint32_t saddr) {
    asm volatile("ldmatrix.sync.aligned.m8n8.x4.shared.b16 {%0,%1,%2,%3}, [%4];"
        : "=r"(r0), "=r"(r1), "=r"(r2), "=r"(r3) : "r"(saddr));
}

// ---------------- bf16x3 tensor-core GEMM (pre-split operands, ldmatrix) -------
// C[m][n] = sum_k A[m][k]*B[n][k] + bias[n] (+ Radd[m][n] residual, optional)
#define PA 20
#define MAT_U32 (128 * PA)
#define STAGE_U32 (4 * MAT_U32)
#define GEMM_SMEM_BYTES (2 * STAGE_U32 * 4)

__global__ void __launch_bounds__(256, 2) gemm_bf16x3(
    const uint32_t* __restrict__ Ah, const uint32_t* __restrict__ Al,
    const uint32_t* __restrict__ Bh, const uint32_t* __restrict__ Bl,
    const float* __restrict__ bias, const float* __restrict__ Radd,
    float* __restrict__ C, uint32_t* __restrict__ Ch, uint32_t* __restrict__ Cl,
    int M, int N, int K, int relu)
{
    extern __shared__ uint32_t smem_u[];
    const int KP   = K >> 1;
    const int tid  = threadIdx.x;
    const int lane = tid & 31;
    const int warp = tid >> 5;
    const int bm   = blockIdx.y << 7;
    const int bn   = blockIdx.x << 7;
    const int warpM = (warp >> 1) << 5;
    const int warpN = (warp & 1) << 6;
    const int g = lane >> 2;
    const int t = lane & 3;
    const bool hasAl = (Al != nullptr);

    const uint32_t sbase = (uint32_t)__cvta_generic_to_shared(smem_u);

    // ldmatrix per-lane addressing: matrix id m = lane>>3, row-in-matrix = lane&7
    const int lm = lane >> 3, lr = lane & 7;
    // A: m&1 -> +8 rows (a1/a3), m>>1 -> +4 u32 cols (a2/a3)
    const uint32_t aRow = (uint32_t)(warpM + ((lm & 1) << 3) + lr);
    const uint32_t aCol = (uint32_t)((lm >> 1) << 2);
    // B: m>>1 -> +8 rows (second ni of pair), m&1 -> +4 u32 cols (b1)
    const uint32_t bRow = (uint32_t)(warpN + ((lm >> 1) << 3) + lr);
    const uint32_t bCol = (uint32_t)((lm & 1) << 2);

    float acc[2][8][4];
    #pragma unroll
    for (int mi = 0; mi < 2; mi++)
        #pragma unroll
        for (int ni = 0; ni < 8; ni++)
            #pragma unroll
            for (int r = 0; r < 4; r++) acc[mi][ni][r] = 0.f;

    const int ntiles = K >> 5;

    auto issue = [&](int kt, int s) {
        uint32_t st = sbase + (uint32_t)(s * STAGE_U32) * 4u;
        #pragma unroll
        for (int i = 0; i < 2; i++) {
            int slot = tid + (i << 8);
            int row = slot >> 2, c4 = (slot & 3) << 2;
            size_t go = (size_t)row * KP + kt * 16 + c4;
            uint32_t so = (uint32_t)(row * PA + c4) * 4u;
            cp_async16(st + 0 * MAT_U32 * 4u + so, Ah + (size_t)bm * KP + go);
            if (hasAl)
                cp_async16(st + 1 * MAT_U32 * 4u + so, Al + (size_t)bm * KP + go);
            cp_async16(st + 2 * MAT_U32 * 4u + so, Bh + (size_t)bn * KP + go);
            cp_async16(st + 3 * MAT_U32 * 4u + so, Bl + (size_t)bn * KP + go);
        }
        asm volatile("cp.async.commit_group;\n");
    };

    issue(0, 0);
    if (ntiles > 1) issue(1, 1);

    for (int kt = 0; kt < ntiles; kt++) {
        const int s = kt & 1;
        if (kt + 2 < ntiles)
            asm volatile("cp.async.wait_group 1;\n" ::: "memory");
        else
            asm volatile("cp.async.wait_group 0;\n" ::: "memory");
        __syncthreads();

        const uint32_t stage = sbase + (uint32_t)(s * STAGE_U32) * 4u;
        const uint32_t aBaseH = stage + (aRow * PA + aCol) * 4u;               // Ah
        const uint32_t bBaseH = stage + 2u * MAT_U32 * 4u + (bRow * PA + bCol) * 4u; // Bh

        #pragma unroll
        for (int ch = 0; ch < 2; ch++) {
            const uint32_t cc = (uint32_t)(ch << 3) * 4u;

            uint32_t ah[2][4], alr[2][4];
            #pragma unroll
            for (int mi = 0; mi < 2; mi++) {
                const uint32_t aa = aBaseH + (uint32_t)(mi * 16 * PA) * 4u + cc;
                ldsm_x4(ah[mi][0], ah[mi][1], ah[mi][2], ah[mi][3], aa);
                if (hasAl)
                    ldsm_x4(alr[mi][0], alr[mi][1], alr[mi][2], alr[mi][3],
                            aa + (uint32_t)MAT_U32 * 4u);
            }

            #pragma unroll
            for (int p = 0; p < 4; p++) {
                const uint32_t ba = bBaseH + (uint32_t)(p * 16 * PA) * 4u + cc;
                uint32_t b0h[2], b1h[2], b0l[2], b1l[2];
                ldsm_x4(b0h[0], b0h[1], b1h[0], b1h[1], ba);
                ldsm_x4(b0l[0], b0l[1], b1l[0], b1l[1], ba + (uint32_t)MAT_U32 * 4u);

                const int n0 = 2 * p, n1 = 2 * p + 1;
                mma_bf16(acc[0][n0], ah[0], b0h);
                mma_bf16(acc[0][n0], ah[0], b0l);
                mma_bf16(acc[1][n0], ah[1], b0h);
                mma_bf16(acc[1][n0], ah[1], b0l);
                mma_bf16(acc[0][n1], ah[0], b1h);
                mma_bf16(acc[0][n1], ah[0], b1l);
                mma_bf16(acc[1][n1], ah[1], b1h);
                mma_bf16(acc[1][n1], ah[1], b1l);
                if (hasAl) {
                    mma_bf16(acc[0][n0], alr[0], b0h);
                    mma_bf16(acc[1][n0], alr[1], b0h);
                    mma_bf16(acc[0][n1], alr[0], b1h);
                    mma_bf16(acc[1][n1], alr[1], b1h);
                }
            }
        }

        __syncthreads();
        if (kt + 2 < ntiles) issue(kt + 2, s);
    }

    const int cq = t << 1;
    #pragma unroll
    for (int ni = 0; ni < 8; ni++) {
        const int col = bn + warpN + (ni << 3) + cq;
        const float b0 = bias[col], b1 = bias[col + 1];
        #pragma unroll
        for (int mi = 0; mi < 2; mi++) {
            const int row0 = bm + warpM + (mi << 4) + g;
            float2 v0, v1;
            v0.x = acc[mi][ni][0] + b0; v0.y = acc[mi][ni][1] + b1;
            v1.x = acc[mi][ni][2] + b0; v1.y = acc[mi][ni][3] + b1;
            if (Radd) {
                float2 r0 = *(const float2*)&Radd[(size_t)row0 * N + col];
                float2 r1 = *(const float2*)&Radd[(size_t)(row0 + 8) * N + col];
                v0.x += r0.x; v0.y += r0.y;
                v1.x += r1.x; v1.y += r1.y;
            }
            if (relu) {
                v0.x = fmaxf(v0.x, 0.f); v0.y = fmaxf(v0.y, 0.f);
                v1.x = fmaxf(v1.x, 0.f); v1.y = fmaxf(v1.y, 0.f);
            }
            if (C) {
                *(float2*)&C[(size_t)row0 * N + col] = v0;
                *(float2*)&C[(size_t)(row0 + 8) * N + col] = v1;
            }
            if (Ch) {
                const int NP = N >> 1;
                const int pc = col >> 1;
                uint32_t ph, pl;
                split2(v0.x, v0.y, ph, pl);
                Ch[(size_t)row0 * NP + pc] = ph;
                Cl[(size_t)row0 * NP + pc] = pl;
                split2(v1.x, v1.y, ph, pl);
                Ch[(size_t)(row0 + 8) * NP + pc] = ph;
                Cl[(size_t)(row0 + 8) * NP + pc] = pl;
            }
        }
    }
}

// ---------------- bf16x3 MMA flash attention (pre-split Q/K) ----------------
__global__ void __launch_bounds__(128) flash_mma_kernel(
    const float* __restrict__ qkv,
    const uint32_t* __restrict__ qkvh, const uint32_t* __restrict__ qkvl,
    uint32_t* __restrict__ attnh, uint32_t* __restrict__ attnl)
{
    __shared__ uint32_t S[8960];
    uint32_t* KPh = S;            // [64][36]  key x d-pair (aliased as P)
    uint32_t* KPl = S + 2304;
    uint32_t* VPh = S + 4608;     // [32][68]  k-pair x d
    uint32_t* VPl = S + 6784;

    const int tid  = threadIdx.x;
    const int lane = tid & 31;
    const int w    = tid >> 5;
    const int g    = lane >> 2;
    const int t    = lane & 3;
    const int qb   = blockIdx.x;
    const int bh   = blockIdx.y;
    const int b    = bh >> 2, h = bh & 3;

    const uint32_t sbase = (uint32_t)__cvta_generic_to_shared(S);
    const float* vg = qkv + (size_t)b * 1024 * 768 + 512 + h * 64;
    const uint32_t* kph = qkvh + (size_t)b * 1024 * 384 + 128 + h * 32;
    const uint32_t* kpl = qkvl + (size_t)b * 1024 * 384 + 128 + h * 32;

    const int wr = w * 16;
    const float SCALE = 0.125f;
    const float L2E   = 1.4426950408889634f;

    // ---- Q fragments: direct global loads of pre-split pairs ----
    uint32_t qh[4][4], ql[4][4];
    {
        const size_t q0 = (size_t)(b * 1024 + qb * 64 + wr + g) * 384 + h * 32;
        const size_t q1 = q0 + (size_t)8 * 384;
        #pragma unroll
        for (int c = 0; c < 4; c++) {
            const int p = c * 8 + t;
            qh[c][0] = qkvh[q0 + p];     ql[c][0] = qkvl[q0 + p];
            qh[c][1] = qkvh[q1 + p];     ql[c][1] = qkvl[q1 + p];
            qh[c][2] = qkvh[q0 + p + 4]; ql[c][2] = qkvl[q0 + p + 4];
            qh[c][3] = qkvh[q1 + p + 4]; ql[c][3] = qkvl[q1 + p + 4];
        }
    }

    float oacc[8][4];
    #pragma unroll
    for (int nt = 0; nt < 8; nt++)
        #pragma unroll
        for (int r = 0; r < 4; r++) oacc[nt][r] = 0.f;
    float m0 = -1e30f, m1 = -1e30f, l0 = 0.f, l1 = 0.f;

    for (int kb = 0; kb < 16; kb++) {
        // ---- K tile: cp.async pre-split pairs (64 rows x 32 u32, pitch 36) ----
        #pragma unroll
        for (int i = 0; i < 4; i++) {
            const int idx = i * 128 + tid;
            const int row = idx >> 3, q4 = (idx & 7) << 2;
            const size_t go = (size_t)(kb * 64 + row) * 384 + q4;
            const uint32_t so = (uint32_t)(row * 36 + q4) * 4u;
            cp_async16(sbase + so, kph + go);
            cp_async16(sbase + 2304u * 4u + so, kpl + go);
        }
        asm volatile("cp.async.commit_group;\n");

        // ---- V tile: fp32 -> pairs along key index (overlaps cp.async) ----
        #pragma unroll
        for (int i = 0; i < 16; i++) {
            const int idx = i * 128 + tid;
            const int d = idx & 63, k2 = idx >> 6;
            const size_t go = (size_t)(kb * 64 + 2 * k2) * 768 + d;
            split2(vg[go], vg[go + 768], VPh[k2 * 68 + d], VPl[k2 * 68 + d]);
        }
        asm volatile("cp.async.wait_group 0;\n" ::: "memory");
        __syncthreads();

        // ---- QK^T (bf16x3) ----
        float sc[8][4];
        #pragma unroll
        for (int nt = 0; nt < 8; nt++)
            #pragma unroll
            for (int r = 0; r < 4; r++) sc[nt][r] = 0.f;

        #pragma unroll
        for (int c = 0; c < 4; c++) {
            const int c8 = c * 8 + t;
            #pragma unroll
            for (int nt = 0; nt < 8; nt++) {
                const uint32_t* kr = &KPh[(nt * 8 + g) * 36];
                const uint32_t* kl = &KPl[(nt * 8 + g) * 36];
                uint32_t bh2[2] = { kr[c8], kr[c8 + 4] };
                uint32_t bl2[2] = { kl[c8], kl[c8 + 4] };
                mma_bf16(sc[nt], qh[c], bh2);
                mma_bf16(sc[nt], qh[c], bl2);
                mma_bf16(sc[nt], ql[c], bh2);
            }
        }

        // ---- online softmax ----
        float mb0 = -1e30f, mb1 = -1e30f;
        #pragma unroll
        for (int nt = 0; nt < 8; nt++) {
            sc[nt][0] *= SCALE; sc[nt][1] *= SCALE;
            sc[nt][2] *= SCALE; sc[nt][3] *= SCALE;
            mb0 = fmaxf(mb0, fmaxf(sc[nt][0], sc[nt][1]));
            mb1 = fmaxf(mb1, fmaxf(sc[nt][2], sc[nt][3]));
        }
        #pragma unroll
        for (int off = 1; off <= 2; off <<= 1) {
            mb0 = fmaxf(mb0, __shfl_xor_sync(0xffffffffu, mb0, off));
            mb1 = fmaxf(mb1, __shfl_xor_sync(0xffffffffu, mb1, off));
        }
        const float mn0 = fmaxf(m0, mb0);
        const float mn1 = fmaxf(m1, mb1);
        const float c0 = exp2f((m0 - mn0) * L2E);
        const float c1 = exp2f((m1 - mn1) * L2E);
        l0 *= c0; l1 *= c1;
        #pragma unroll
        for (int nt = 0; nt < 8; nt++) {
            oacc[nt][0] *= c0; oacc[nt][1] *= c0;
            oacc[nt][2] *= c1; oacc[nt][3] *= c1;
        }
        #pragma unroll
        for (int nt = 0; nt < 8; nt++) {
            sc[nt][0] = exp2f((sc[nt][0] - mn0) * L2E);
            sc[nt][1] = exp2f((sc[nt][1] - mn0) * L2E);
            sc[nt][2] = exp2f((sc[nt][2] - mn1) * L2E);
            sc[nt][3] = exp2f((sc[nt][3] - mn1) * L2E);
            l0 += sc[nt][0] + sc[nt][1];
            l1 += sc[nt][2] + sc[nt][3];
        }
        m0 = mn0; m1 = mn1;

        // ---- pack P into pairs, aliasing K pair region ----
        __syncthreads();
        uint32_t* Ph = KPh;
        uint32_t* Pl = KPl;
        #pragma unroll
        for (int nt = 0; nt < 8; nt++) {
            const int pc = nt * 4 + t;
            split2(sc[nt][0], sc[nt][1], Ph[(wr + g) * 36 + pc], Pl[(wr + g) * 36 + pc]);
            split2(sc[nt][2], sc[nt][3], Ph[(wr + g + 8) * 36 + pc], Pl[(wr + g + 8) * 36 + pc]);
        }
        __syncwarp();

        // ---- P @ V (bf16x3) ----
        #pragma unroll
        for (int c = 0; c < 4; c++) {
            const int c8 = c * 8 + t;
            uint32_t ah2[4], al2[4];
            ah2[0] = Ph[(wr + g) * 36 + c8];
            ah2[1] = Ph[(wr + g + 8) * 36 + c8];
            ah2[2] = Ph[(wr + g) * 36 + c8 + 4];
            ah2[3] = Ph[(wr + g + 8) * 36 + c8 + 4];
            al2[0] = Pl[(wr + g) * 36 + c8];
            al2[1] = Pl[(wr + g + 8) * 36 + c8];
            al2[2] = Pl[(wr + g) * 36 + c8 + 4];
            al2[3] = Pl[(wr + g + 8) * 36 + c8 + 4];
            #pragma unroll
            for (int nt = 0; nt < 8; nt++) {
                const int vc = nt * 8 + g;
                uint32_t bh2[2] = { VPh[(c8) * 68 + vc], VPh[(c8 + 4) * 68 + vc] };
                uint32_t bl2[2] = { VPl[(c8) * 68 + vc], VPl[(c8 + 4) * 68 + vc] };
                mma_bf16(oacc[nt], ah2, bh2);
                mma_bf16(oacc[nt], ah2, bl2);
                mma_bf16(oacc[nt], al2, bh2);
            }
        }
        __syncthreads();
    }

    #pragma unroll
    for (int off = 1; off <= 2; off <<= 1) {
        l0 += __shfl_xor_sync(0xffffffffu, l0, off);
        l1 += __shfl_xor_sync(0xffffffffu, l1, off);
    }
    const float inv0 = 1.f / l0;
    const float inv1 = 1.f / l1;

    const int row0 = b * 1024 + qb * 64 + wr + g;
    #pragma unroll
    for (int nt = 0; nt < 8; nt++) {
        const int pc = h * 32 + (nt << 2) + t;
        uint32_t ph, pl;
        split2(oacc[nt][0] * inv0, oacc[nt][1] * inv0, ph, pl);
        attnh[(size_t)row0 * 128 + pc] = ph;
        attnl[(size_t)row0 * 128 + pc] = pl;
        split2(oacc[nt][2] * inv1, oacc[nt][3] * inv1, ph, pl);
        attnh[(size_t)(row0 + 8) * 128 + pc] = ph;
        attnl[(size_t)(row0 + 8) * 128 + pc] = pl;
    }
}

// ---------------- layernorm(xa[+xb])*g+b, fp32 out + optional bf16 pair out ----
__global__ void __launch_bounds__(256) ln_kernel(
    const float* __restrict__ xa, const float* __restrict__ xb,
    const float* __restrict__ g, const float* __restrict__ bt,
    float* __restrict__ out, uint32_t* __restrict__ oh, uint32_t* __restrict__ ol)
{
    const int warp = threadIdx.x >> 5, lane = threadIdx.x & 31;
    const size_t row = (size_t)blockIdx.x * 8 + warp;
    const float* pa = xa + row * 256;
    const float* pb = xb ? xb + row * 256 : nullptr;

    float v[8];
    float s = 0.f;
    #pragma unroll
    for (int i = 0; i < 8; i++) {
        v[i] = pa[lane + 32 * i];
        if (pb) v[i] += pb[lane + 32 * i];
        s += v[i];
    }
    #pragma unroll
    for (int off = 16; off > 0; off >>= 1) s += __shfl_xor_sync(0xffffffffu, s, off);
    float mean = s * (1.f / 256.f);

    float vs = 0.f;
    #pragma unroll
    for (int i = 0; i < 8; i++) { float d = v[i] - mean; vs += d * d; }
    #pragma unroll
    for (int off = 16; off > 0; off >>= 1) vs += __shfl_xor_sync(0xffffffffu, vs, off);
    float inv = 1.f / sqrtf(vs * (1.f / 256.f) + 1e-5f);

    #pragma unroll
    for (int i = 0; i < 8; i++) {
        int c = lane + 32 * i;
        float o = (v[i] - mean) * inv * g[c] + bt[c];
        out[row * 256 + c] = o;
        float on = __shfl_down_sync(0xffffffffu, o, 1);
        if (oh && !(lane & 1)) {
            uint32_t ph, pl;
            split2(o, on, ph, pl);
            oh[row * 128 + (c >> 1)] = ph;
            ol[row * 128 + (c >> 1)] = pl;
        }
    }
}

// -------------------------------- launch ---------------------------------------
extern "C" void kernel_launch(void* const* d_in, const int* in_sizes, int n_in,
                              void* d_out, int out_size)
{
    const float* x     = (const float*)d_in[0];
    const float* Win   = (const float*)d_in[1];
    const float* Wres  = (const float*)d_in[2];
    const float* Wread = (const float*)d_in[3];
    const float* bread = (const float*)d_in[4];
    const float* Wqkv  = (const float*)d_in[5];
    const float* bqkv  = (const float*)d_in[6];
    const float* Wo    = (const float*)d_in[7];
    const float* bo    = (const float*)d_in[8];
    const float* g1    = (const float*)d_in[9];
    const float* b1    = (const float*)d_in[10];
    const float* g2    = (const float*)d_in[11];
    const float* b2    = (const float*)d_in[12];
    const float* W1    = (const float*)d_in[13];
    const float* c1    = (const float*)d_in[14];
    const float* W2    = (const float*)d_in[15];
    const float* c2    = (const float*)d_in[16];
    float* out = (float*)d_out;

    float *qkv, *h, *tmp;
    uint32_t *zh, *qh, *ql_, *hh, *hl, *ath, *atl, *ffh, *ffl;
    uint32_t *wrh, *wrl, *wqh, *wql, *woh, *wol, *w1h, *w1l, *w2h, *w2l;
    cudaGetSymbolAddress((void**)&qkv, g_qkv);
    cudaGetSymbolAddress((void**)&h,   g_h);
    cudaGetSymbolAddress((void**)&tmp, g_tmp);
    cudaGetSymbolAddress((void**)&zh,  g_zh);
    cudaGetSymbolAddress((void**)&qh,  g_qkvh);
    cudaGetSymbolAddress((void**)&ql_, g_qkvl);
    cudaGetSymbolAddress((void**)&hh,  g_hh);
    cudaGetSymbolAddress((void**)&hl,  g_hl);
    cudaGetSymbolAddress((void**)&ath, g_attnh);
    cudaGetSymbolAddress((void**)&atl, g_attnl);
    cudaGetSymbolAddress((void**)&ffh, g_ffh);
    cudaGetSymbolAddress((void**)&ffl, g_ffl);
    cudaGetSymbolAddress((void**)&wrh, g_wrh);
    cudaGetSymbolAddress((void**)&wrl, g_wrl);
    cudaGetSymbolAddress((void**)&wqh, g_wqh);
    cudaGetSymbolAddress((void**)&wql, g_wql);
    cudaGetSymbolAddress((void**)&woh, g_woh);
    cudaGetSymbolAddress((void**)&wol, g_wol);
    cudaGetSymbolAddress((void**)&w1h, g_w1h);
    cudaGetSymbolAddress((void**)&w1l, g_w1l);
    cudaGetSymbolAddress((void**)&w2h, g_w2h);
    cudaGetSymbolAddress((void**)&w2l, g_w2l);

    cudaFuncSetAttribute(gemm_bf16x3,
                         cudaFuncAttributeMaxDynamicSharedMemorySize,
                         GEMM_SMEM_BYTES);

    const int M = 32768;
    const int SB = GEMM_SMEM_BYTES;

    wsplit_kernel<<<256,  256>>>(Wread, wrh, wrl, 256 * 256);
    wsplit_kernel<<<768,  256>>>(Wqkv,  wqh, wql, 2 * 768 * 128);
    wsplit_kernel<<<256,  256>>>(Wo,    woh, wol, 2 * 256 * 128);
    wsplit_kernel<<<1024, 256>>>(W1,    w1h, w1l, 2 * 1024 * 128);
    wsplit_kernel<<<1024, 256>>>(W2,    w2h, w2l, 2 * 256 * 512);

    colsum_kernel<<<1, 512>>>(Wres);
    lif_kernel<<<32, 512>>>(x, Win, Wres, zh);

    // h = z @ Wread^T + bread   (z exact in bf16 -> 2-term)
    gemm_bf16x3<<<dim3(2, 256), 256, SB>>>(zh, nullptr, wrh, wrl, bread, nullptr,
                                           h, hh, hl, M, 256, 512, 0);

    for (int l = 0; l < 2; l++) {
        // qkv = h @ Wqkv^T + bqkv  -> fp32 (V) + pairs (Q,K)
        gemm_bf16x3<<<dim3(6, 256), 256, SB>>>(hh, hl,
            wqh + (size_t)l * 768 * 128, wql + (size_t)l * 768 * 128,
            bqkv + l * 768, nullptr, qkv, qh, ql_, M, 768, 256, 0);
        // attention -> bf16 pair out
        flash_mma_kernel<<<dim3(16, 128), 128>>>(qkv, qh, ql_, ath, atl);
        // tmp = attn @ Wo^T + bo + h (residual fused)
        gemm_bf16x3<<<dim3(2, 256), 256, SB>>>(ath, atl,
            woh + (size_t)l * 256 * 128, wol + (size_t)l * 256 * 128,
            bo + l * 256, h, tmp, nullptr, nullptr, M, 256, 256, 0);
        // h = LN(tmp) (+ bf16 pairs)
        ln_kernel<<<4096, 256>>>(tmp, nullptr, g1 + l * 256, b1 + l * 256, h, hh, hl);
        // ff = relu(h @ W1^T + c1) -> pairs only
        gemm_bf16x3<<<dim3(8, 256), 256, SB>>>(hh, hl,
            w1h + (size_t)l * 1024 * 128, w1l + (size_t)l * 1024 * 128,
            c1 + l * 1024, nullptr, nullptr, ffh, ffl, M, 1024, 256, 1);
        // tmp = ff @ W2^T + c2 + h (residual fused)
        gemm_bf16x3<<<dim3(2, 256), 256, SB>>>(ffh, ffl,
            w2h + (size_t)l * 256 * 512, w2l + (size_t)l * 256 * 512,
            c2 + l * 256, h, tmp, nullptr, nullptr, M, 256, 1024, 0);
        // out/h = LN(tmp)
        ln_kernel<<<4096, 256>>>(tmp, nullptr, g2 + l * 256, b2 + l * 256,
                                 (l == 1) ? out : h,
                                 (l == 1) ? nullptr : hh,
                                 (l == 1) ? nullptr : hl);
    }
}